// round 1
// baseline (speedup 1.0000x reference)
#include <cuda_runtime.h>
#include <cuda_bf16.h>

// ---------------------------------------------------------------------------
// EncoderLayer: x(4,2048,1024) -> QKV proj -> 16-head attn (clip ±10, softmax)
//               -> O proj -> add+LN -> FFN(4096,relu) -> add+LN
// Round 0: fp32 baseline (tiled SGEMM + fused flash-style attention + fused LN)
// ---------------------------------------------------------------------------

#define M_TOK   8192          // 4 * 2048 tokens
#define DMODEL  1024
#define DFF     4096
#define NHEAD   16
#define DHEAD   64
#define SEQ     2048

// Scratch (device globals: allocation-free)
__device__ float g_Q  [M_TOK * DMODEL];
__device__ float g_K  [M_TOK * DMODEL];
__device__ float g_V  [M_TOK * DMODEL];
__device__ float g_CTX[M_TOK * DMODEL];
__device__ float g_H1 [M_TOK * DFF];

// ---------------------------------------------------------------------------
// SGEMM: C[M,N] = A[M,K] @ B[K,N] + bias[N], optional relu.
// BM=BN=128, BK=16, 256 threads, 8x8 per thread.
// ---------------------------------------------------------------------------
__global__ __launch_bounds__(256) void sgemm_bias(
    const float* __restrict__ A, const float* __restrict__ B,
    const float* __restrict__ bias, float* __restrict__ C,
    int M, int N, int K, int relu)
{
    __shared__ float As[16][128];
    __shared__ float Bs[16][128];

    const int tid = threadIdx.x;
    const int bx = blockIdx.x, by = blockIdx.y;
    const int tr = tid >> 4, tc = tid & 15;

    const int aRow = tid >> 2;          // 0..63
    const int aCol = (tid & 3) << 2;    // 0,4,8,12
    const int bRow = tid >> 5;          // 0..7
    const int bCol = (tid & 31) << 2;   // 0..124

    const float* Ap = A + (long)(by * 128) * K;
    const float* Bp = B + bx * 128;

    float acc[8][8];
#pragma unroll
    for (int i = 0; i < 8; i++)
#pragma unroll
        for (int j = 0; j < 8; j++) acc[i][j] = 0.f;

    for (int k0 = 0; k0 < K; k0 += 16) {
        float4 a0 = *(const float4*)(Ap + (long)aRow * K + k0 + aCol);
        float4 a1 = *(const float4*)(Ap + (long)(aRow + 64) * K + k0 + aCol);
        float4 b0 = *(const float4*)(Bp + (long)(k0 + bRow) * N + bCol);
        float4 b1 = *(const float4*)(Bp + (long)(k0 + bRow + 8) * N + bCol);

        __syncthreads();
        As[aCol + 0][aRow] = a0.x;
        As[aCol + 1][aRow] = a0.y;
        As[aCol + 2][aRow] = a0.z;
        As[aCol + 3][aRow] = a0.w;
        As[aCol + 0][aRow + 64] = a1.x;
        As[aCol + 1][aRow + 64] = a1.y;
        As[aCol + 2][aRow + 64] = a1.z;
        As[aCol + 3][aRow + 64] = a1.w;
        *(float4*)&Bs[bRow][bCol]     = b0;
        *(float4*)&Bs[bRow + 8][bCol] = b1;
        __syncthreads();

#pragma unroll
        for (int kk = 0; kk < 16; kk++) {
            float ar[8], br[8];
            float4 t;
            t = *(const float4*)&As[kk][tr * 8];     ar[0]=t.x; ar[1]=t.y; ar[2]=t.z; ar[3]=t.w;
            t = *(const float4*)&As[kk][tr * 8 + 4]; ar[4]=t.x; ar[5]=t.y; ar[6]=t.z; ar[7]=t.w;
            t = *(const float4*)&Bs[kk][tc * 8];     br[0]=t.x; br[1]=t.y; br[2]=t.z; br[3]=t.w;
            t = *(const float4*)&Bs[kk][tc * 8 + 4]; br[4]=t.x; br[5]=t.y; br[6]=t.z; br[7]=t.w;
#pragma unroll
            for (int i = 0; i < 8; i++)
#pragma unroll
                for (int j = 0; j < 8; j++)
                    acc[i][j] = fmaf(ar[i], br[j], acc[i][j]);
        }
    }

    const float* bp = bias + bx * 128 + tc * 8;
#pragma unroll
    for (int i = 0; i < 8; i++) {
        float* cp = C + (long)(by * 128 + tr * 8 + i) * N + bx * 128 + tc * 8;
#pragma unroll
        for (int j = 0; j < 8; j++) {
            float v = acc[i][j] + bp[j];
            if (relu) v = fmaxf(v, 0.f);
            cp[j] = v;
        }
    }
}

// ---------------------------------------------------------------------------
// Attention: per (b,h) and 128-query tile, stream 64-key K/V tiles.
// clip(l, ±10) -> p = exp(l - 10) (shift-invariant; max bounded by clip)
// numerator += P @ V ; denominator += rowsum(P) ; out = num/den.
// ---------------------------------------------------------------------------
#define QT_STRIDE 132   // 128 + 4 pad (float4-aligned)
#define KV_STRIDE 68    // 64 + 4 pad

__global__ __launch_bounds__(256) void attn_kernel(
    const float* __restrict__ Q, const float* __restrict__ K,
    const float* __restrict__ V, float* __restrict__ O)
{
    extern __shared__ float sm[];
    float* Qt  = sm;                          // [64][132] transposed Q tile
    float* Kt  = Qt + 64 * QT_STRIDE;         // [64][68]  transposed K tile
    float* Vs  = Kt + 64 * KV_STRIDE;         // [64][68]  natural V tile
    float* Pt  = Vs + 64 * KV_STRIDE;         // [64][132] transposed P tile
    float* den = Pt + 64 * QT_STRIDE;         // [128]

    const int tid = threadIdx.x;
    const int bh = blockIdx.y;
    const int b = bh >> 4, h = bh & 15;
    const int q0 = blockIdx.x * 128;
    const long base   = (long)(b * SEQ + q0) * DMODEL + h * DHEAD;
    const long kvbase = (long)(b * SEQ) * DMODEL + h * DHEAD;

    // Load Q tile transposed: Qt[d][i]
    for (int e = tid; e < 128 * 64; e += 256) {
        int i = e >> 6, d = e & 63;
        Qt[d * QT_STRIDE + i] = Q[base + (long)i * DMODEL + d];
    }
    if (tid < 128) den[tid] = 0.f;

    const int tr = tid >> 4, tc = tid & 15;
    const int i0 = tr * 8, c0 = tc * 4;

    float acc[8][4];
#pragma unroll
    for (int u = 0; u < 8; u++)
#pragma unroll
        for (int v = 0; v < 4; v++) acc[u][v] = 0.f;

    for (int kt = 0; kt < SEQ / 64; kt++) {
        __syncthreads();   // prior GEMM2 / den done reading Kt,Vs,Pt
        for (int e = tid; e < 64 * 64; e += 256) {
            int j = e >> 6, d = e & 63;
            long g = kvbase + (long)(kt * 64 + j) * DMODEL + d;
            Kt[d * KV_STRIDE + j] = K[g];
            Vs[j * KV_STRIDE + d] = V[g];
        }
        __syncthreads();

        // S micro-tile: rows i0..i0+7, key cols c0..c0+3
        float s[8][4];
#pragma unroll
        for (int u = 0; u < 8; u++)
#pragma unroll
            for (int v = 0; v < 4; v++) s[u][v] = 0.f;

        for (int d = 0; d < 64; d++) {
            float4 qa = *(const float4*)&Qt[d * QT_STRIDE + i0];
            float4 qb = *(const float4*)&Qt[d * QT_STRIDE + i0 + 4];
            float4 kv = *(const float4*)&Kt[d * KV_STRIDE + c0];
            float qv[8] = {qa.x,qa.y,qa.z,qa.w,qb.x,qb.y,qb.z,qb.w};
            float kr[4] = {kv.x,kv.y,kv.z,kv.w};
#pragma unroll
            for (int u = 0; u < 8; u++)
#pragma unroll
                for (int v = 0; v < 4; v++)
                    s[u][v] = fmaf(qv[u], kr[v], s[u][v]);
        }

        // p = exp(clip(s/8) - 10), store transposed Pt[j][i]
#pragma unroll
        for (int u = 0; u < 8; u++)
#pragma unroll
            for (int v = 0; v < 4; v++) {
                float l = s[u][v] * 0.125f;
                l = fminf(fmaxf(l, -10.f), 10.f);
                Pt[(c0 + v) * QT_STRIDE + i0 + u] = __expf(l - 10.f);
            }
        __syncthreads();

        // denominator: rowsum over all 64 keys
        if (tid < 128) {
            float ds = 0.f;
#pragma unroll 8
            for (int j = 0; j < 64; j++) ds += Pt[j * QT_STRIDE + tid];
            den[tid] += ds;
        }

        // numerator: acc += P @ V
        for (int j = 0; j < 64; j++) {
            float4 pa = *(const float4*)&Pt[j * QT_STRIDE + i0];
            float4 pb = *(const float4*)&Pt[j * QT_STRIDE + i0 + 4];
            float4 vv = *(const float4*)&Vs[j * KV_STRIDE + c0];
            float pv[8] = {pa.x,pa.y,pa.z,pa.w,pb.x,pb.y,pb.z,pb.w};
            float vr[4] = {vv.x,vv.y,vv.z,vv.w};
#pragma unroll
            for (int u = 0; u < 8; u++)
#pragma unroll
                for (int v = 0; v < 4; v++)
                    acc[u][v] = fmaf(pv[u], vr[v], acc[u][v]);
        }
    }
    __syncthreads();

#pragma unroll
    for (int u = 0; u < 8; u++) {
        float inv = 1.f / den[i0 + u];
#pragma unroll
        for (int v = 0; v < 4; v++)
            O[base + (long)(i0 + u) * DMODEL + c0 + v] = acc[u][v] * inv;
    }
}

// ---------------------------------------------------------------------------
// out = LayerNorm(A + B) * gamma + beta   (one block per row, d=1024)
// ---------------------------------------------------------------------------
__global__ __launch_bounds__(256) void add_ln_kernel(
    const float* __restrict__ A, const float* __restrict__ B,
    const float* __restrict__ gamma, const float* __restrict__ beta,
    float* __restrict__ out)
{
    __shared__ float red[34];
    const int row = blockIdx.x;
    const int tid = threadIdx.x;

    float4 a = ((const float4*)(A + (long)row * DMODEL))[tid];
    float4 b = ((const float4*)(B + (long)row * DMODEL))[tid];
    float4 v = {a.x + b.x, a.y + b.y, a.z + b.z, a.w + b.w};

    float s  = v.x + v.y + v.z + v.w;
    float sq = v.x * v.x + v.y * v.y + v.z * v.z + v.w * v.w;
#pragma unroll
    for (int o = 16; o; o >>= 1) {
        s  += __shfl_xor_sync(~0u, s,  o);
        sq += __shfl_xor_sync(~0u, sq, o);
    }
    const int w = tid >> 5, l = tid & 31;
    __shared__ float ws[8], wq[8];
    if (l == 0) { ws[w] = s; wq[w] = sq; }
    __syncthreads();
    if (tid < 32) {
        float s2 = (tid < 8) ? ws[tid] : 0.f;
        float q2 = (tid < 8) ? wq[tid] : 0.f;
#pragma unroll
        for (int o = 4; o; o >>= 1) {
            s2 += __shfl_xor_sync(~0u, s2, o);
            q2 += __shfl_xor_sync(~0u, q2, o);
        }
        if (tid == 0) { red[32] = s2; red[33] = q2; }
    }
    __syncthreads();
    float mean = red[32] * (1.f / DMODEL);
    float var  = red[33] * (1.f / DMODEL) - mean * mean;
    float rs   = rsqrtf(var + 1e-8f);

    float4 g  = ((const float4*)gamma)[tid];
    float4 be = ((const float4*)beta)[tid];
    float4 o4;
    o4.x = (v.x - mean) * rs * g.x + be.x;
    o4.y = (v.y - mean) * rs * g.y + be.y;
    o4.z = (v.z - mean) * rs * g.z + be.z;
    o4.w = (v.w - mean) * rs * g.w + be.w;
    ((float4*)(out + (long)row * DMODEL))[tid] = o4;
}

// ---------------------------------------------------------------------------
extern "C" void kernel_launch(void* const* d_in, const int* in_sizes, int n_in,
                              void* d_out, int out_size)
{
    const float* x  = (const float*)d_in[0];
    const float* wq = (const float*)d_in[1];
    const float* bq = (const float*)d_in[2];
    const float* wk = (const float*)d_in[3];
    const float* bk = (const float*)d_in[4];
    const float* wv = (const float*)d_in[5];
    const float* bv = (const float*)d_in[6];
    const float* wo = (const float*)d_in[7];
    const float* bo = (const float*)d_in[8];
    const float* w1 = (const float*)d_in[9];
    const float* b1 = (const float*)d_in[10];
    const float* w2 = (const float*)d_in[11];
    const float* b2 = (const float*)d_in[12];
    const float* ga = (const float*)d_in[13];
    const float* be = (const float*)d_in[14];
    float* out = (float*)d_out;

    float *Qb, *Kb, *Vb, *Cb, *H1b;
    cudaGetSymbolAddress((void**)&Qb,  g_Q);
    cudaGetSymbolAddress((void**)&Kb,  g_K);
    cudaGetSymbolAddress((void**)&Vb,  g_V);
    cudaGetSymbolAddress((void**)&Cb,  g_CTX);
    cudaGetSymbolAddress((void**)&H1b, g_H1);

    const int ATTN_SMEM = (64 * QT_STRIDE * 2 + 64 * KV_STRIDE * 2 + 128) * (int)sizeof(float);
    cudaFuncSetAttribute(attn_kernel, cudaFuncAttributeMaxDynamicSharedMemorySize, ATTN_SMEM);

    dim3 blk(256);
    dim3 gProj(DMODEL / 128, M_TOK / 128);   // (8, 64)
    dim3 gF1(DFF / 128, M_TOK / 128);        // (32, 64)

    // QKV projections
    sgemm_bias<<<gProj, blk>>>(x, wq, bq, Qb, M_TOK, DMODEL, DMODEL, 0);
    sgemm_bias<<<gProj, blk>>>(x, wk, bk, Kb, M_TOK, DMODEL, DMODEL, 0);
    sgemm_bias<<<gProj, blk>>>(x, wv, bv, Vb, M_TOK, DMODEL, DMODEL, 0);

    // Attention
    dim3 gAttn(SEQ / 128, 4 * NHEAD);        // (16, 64)
    attn_kernel<<<gAttn, blk, ATTN_SMEM>>>(Qb, Kb, Vb, Cb);

    // O projection (ctx @ wo + bo) -> reuse Qb
    sgemm_bias<<<gProj, blk>>>(Cb, wo, bo, Qb, M_TOK, DMODEL, DMODEL, 0);

    // out1 = LN(x + attn_out) -> Kb
    add_ln_kernel<<<M_TOK, blk>>>(x, Qb, ga, be, Kb);

    // FFN
    sgemm_bias<<<gF1, blk>>>(Kb, w1, b1, H1b, M_TOK, DFF, DMODEL, 1);
    sgemm_bias<<<gProj, blk>>>(H1b, w2, b2, Vb, M_TOK, DMODEL, DFF, 0);

    // out = LN(out1 + ffn)
    add_ln_kernel<<<M_TOK, blk>>>(Kb, Vb, ga, be, out);
}

// round 3
// speedup vs baseline: 1.5311x; 1.5311x over previous
#include <cuda_runtime.h>
#include <cuda_bf16.h>
#include <cstdint>

// ---------------------------------------------------------------------------
// EncoderLayer R2: warp-MMA (HMMA bf16 split) GEMMs + fp32 flash attention
// tcgen05 is unusable: harness compiles PTX at compute_103 (no 'a' features).
// ---------------------------------------------------------------------------

#define M_TOK   8192
#define DMODEL  1024
#define DFF     4096
#define NHEAD   16
#define DHEAD   64
#define SEQ     2048

// fp32 scratch
__device__ float g_Q  [M_TOK * DMODEL];
__device__ float g_K  [M_TOK * DMODEL];
__device__ float g_V  [M_TOK * DMODEL];
__device__ float g_CTX[M_TOK * DMODEL];
__device__ float g_H1 [M_TOK * DFF];
// bf16 split scratch (A operand, max 8192x4096)
__device__ __nv_bfloat16 g_Ahi[M_TOK * DFF];
__device__ __nv_bfloat16 g_Alo[M_TOK * DFF];
// transposed split weights (max 4096x1024)
__device__ __nv_bfloat16 g_Wthi[DFF * DMODEL];
__device__ __nv_bfloat16 g_Wtlo[DFF * DMODEL];

__device__ __forceinline__ uint32_t smem_u32(const void* p) {
    uint32_t a;
    asm("{ .reg .u64 t; cvta.to.shared.u64 t, %1; cvt.u32.u64 %0, t; }" : "=r"(a) : "l"(p));
    return a;
}
__device__ __forceinline__ void ldmat_x4(uint32_t* r, uint32_t addr) {
    asm volatile("ldmatrix.sync.aligned.m8n8.x4.shared.b16 {%0,%1,%2,%3}, [%4];"
                 : "=r"(r[0]), "=r"(r[1]), "=r"(r[2]), "=r"(r[3]) : "r"(addr));
}
__device__ __forceinline__ void mma_bf16(float* d, const uint32_t* a, const uint32_t* b) {
    asm volatile("mma.sync.aligned.m16n8k16.row.col.f32.bf16.bf16.f32 "
                 "{%0,%1,%2,%3}, {%4,%5,%6,%7}, {%8,%9}, {%0,%1,%2,%3};"
                 : "+f"(d[0]), "+f"(d[1]), "+f"(d[2]), "+f"(d[3])
                 : "r"(a[0]), "r"(a[1]), "r"(a[2]), "r"(a[3]), "r"(b[0]), "r"(b[1]));
}

// ---------------------------------------------------------------------------
// Split-bf16 HMMA GEMM: C[M,N] = A[M,K] @ W[K,N] + bias  (W given as Wt[N,K])
// BM=BN=128, BK=32. 256 threads = 2x4 warps, 64x32 per warp.
// ---------------------------------------------------------------------------
#define SM_STRIDE 40   // 32 + 8 pad (bf16 elems); conflict-free for ldmatrix

__global__ void __launch_bounds__(256, 2) gemm_mma(
    const __nv_bfloat16* __restrict__ Ahi, const __nv_bfloat16* __restrict__ Alo,
    const __nv_bfloat16* __restrict__ Bhi, const __nv_bfloat16* __restrict__ Blo,
    const float* __restrict__ bias, float* __restrict__ C,
    int N, int K, int relu)
{
    __shared__ __nv_bfloat16 sA[2][128][SM_STRIDE];
    __shared__ __nv_bfloat16 sB[2][128][SM_STRIDE];

    const int tid = threadIdx.x;
    const int wid = tid >> 5, lid = tid & 31;
    const int m0 = blockIdx.y * 128, n0 = blockIdx.x * 128;
    const int wm = (wid >> 2) * 64;     // warp M offset in tile
    const int wn = (wid & 3) * 32;      // warp N offset in tile

    const int r  = tid >> 2;            // 0..63
    const int cg = (tid & 3) * 8;       // 0,8,16,24

    float acc[4][4][4];
#pragma unroll
    for (int mt = 0; mt < 4; mt++)
#pragma unroll
        for (int nt = 0; nt < 4; nt++)
#pragma unroll
            for (int f = 0; f < 4; f++) acc[mt][nt][f] = 0.f;

    // ldmatrix lane addressing (element offsets within a [128][SM_STRIDE] tile)
    const int lrow = lid & 15;          // row within 16-row block
    const int lcol = (lid >> 4) * 8;    // 0 or 8 (k offset)

    const uint32_t aBase[2] = { smem_u32(&sA[0][0][0]), smem_u32(&sA[1][0][0]) };
    const uint32_t bBase[2] = { smem_u32(&sB[0][0][0]), smem_u32(&sB[1][0][0]) };

    const int NC = K >> 5;
    for (int i = 0; i < NC; i++) {
        const int k0 = i << 5;
        // prefetch to regs
        uint4 av0, av1, al0, al1, bv0, bv1, bl0, bl1;
        {
            const long ra = (long)(m0 + r) * K + k0 + cg;
            const long rb = (long)(n0 + r) * K + k0 + cg;
            av0 = *(const uint4*)(Ahi + ra);
            av1 = *(const uint4*)(Ahi + ra + 64 * (long)K);
            al0 = *(const uint4*)(Alo + ra);
            al1 = *(const uint4*)(Alo + ra + 64 * (long)K);
            bv0 = *(const uint4*)(Bhi + rb);
            bv1 = *(const uint4*)(Bhi + rb + 64 * (long)K);
            bl0 = *(const uint4*)(Blo + rb);
            bl1 = *(const uint4*)(Blo + rb + 64 * (long)K);
        }
        __syncthreads();
        *(uint4*)&sA[0][r][cg]      = av0;
        *(uint4*)&sA[0][r + 64][cg] = av1;
        *(uint4*)&sA[1][r][cg]      = al0;
        *(uint4*)&sA[1][r + 64][cg] = al1;
        *(uint4*)&sB[0][r][cg]      = bv0;
        *(uint4*)&sB[0][r + 64][cg] = bv1;
        *(uint4*)&sB[1][r][cg]      = bl0;
        *(uint4*)&sB[1][r + 64][cg] = bl1;
        __syncthreads();

        // 3 passes: (Ahi,Bhi), (Ahi,Blo), (Alo,Bhi)
#pragma unroll
        for (int p = 0; p < 3; p++) {
            const uint32_t aB = aBase[p == 2 ? 1 : 0];
            const uint32_t bB = bBase[p == 1 ? 1 : 0];
#pragma unroll
            for (int k16 = 0; k16 < 2; k16++) {
                uint32_t af[4][4];
#pragma unroll
                for (int mt = 0; mt < 4; mt++) {
                    uint32_t addr = aB + ((wm + mt * 16 + lrow) * SM_STRIDE + k16 * 16 + lcol) * 2;
                    ldmat_x4(af[mt], addr);
                }
                uint32_t bf[2][4];
#pragma unroll
                for (int np = 0; np < 2; np++) {
                    uint32_t addr = bB + ((wn + np * 16 + lrow) * SM_STRIDE + k16 * 16 + lcol) * 2;
                    ldmat_x4(bf[np], addr);
                }
                // bf[np] regs: {mat0,mat1,mat2,mat3} = {n0k0, n1k0, n0k8, n1k8}
#pragma unroll
                for (int mt = 0; mt < 4; mt++) {
#pragma unroll
                    for (int nt = 0; nt < 4; nt++) {
                        uint32_t bfr[2] = { bf[nt >> 1][nt & 1], bf[nt >> 1][(nt & 1) + 2] };
                        mma_bf16(acc[mt][nt], af[mt], bfr);
                    }
                }
            }
        }
    }

    // epilogue: bias (+relu) -> C
    const int g  = lid >> 2;       // 0..7
    const int tg = (lid & 3) * 2;  // 0,2,4,6
#pragma unroll
    for (int mt = 0; mt < 4; mt++) {
        const int row = m0 + wm + mt * 16 + g;
#pragma unroll
        for (int nt = 0; nt < 4; nt++) {
            const int col = n0 + wn + nt * 8 + tg;
            const float b0 = bias[col], b1 = bias[col + 1];
            float v0 = acc[mt][nt][0] + b0;
            float v1 = acc[mt][nt][1] + b1;
            float v2 = acc[mt][nt][2] + b0;
            float v3 = acc[mt][nt][3] + b1;
            if (relu) {
                v0 = fmaxf(v0, 0.f); v1 = fmaxf(v1, 0.f);
                v2 = fmaxf(v2, 0.f); v3 = fmaxf(v3, 0.f);
            }
            C[(long)row * N + col]           = v0;
            C[(long)row * N + col + 1]       = v1;
            C[(long)(row + 8) * N + col]     = v2;
            C[(long)(row + 8) * N + col + 1] = v3;
        }
    }
}

// ---------------------------------------------------------------------------
// fp32 -> (hi, lo) bf16 split
// ---------------------------------------------------------------------------
__global__ void __launch_bounds__(256) split_kernel(
    const float* __restrict__ A, __nv_bfloat16* __restrict__ hi,
    __nv_bfloat16* __restrict__ lo, long n4)
{
    long i = (long)blockIdx.x * blockDim.x + threadIdx.x;
    long stride = (long)gridDim.x * blockDim.x;
    for (; i < n4; i += stride) {
        float4 v = ((const float4*)A)[i];
        __nv_bfloat16 h0 = __float2bfloat16(v.x), h1 = __float2bfloat16(v.y);
        __nv_bfloat16 h2 = __float2bfloat16(v.z), h3 = __float2bfloat16(v.w);
        __nv_bfloat16 l0 = __float2bfloat16(v.x - __bfloat162float(h0));
        __nv_bfloat16 l1 = __float2bfloat16(v.y - __bfloat162float(h1));
        __nv_bfloat16 l2 = __float2bfloat16(v.z - __bfloat162float(h2));
        __nv_bfloat16 l3 = __float2bfloat16(v.w - __bfloat162float(h3));
        __nv_bfloat162 hp0(h0, h1), hp1(h2, h3), lp0(l0, l1), lp1(l2, l3);
        ((__nv_bfloat162*)hi)[i * 2]     = hp0;
        ((__nv_bfloat162*)hi)[i * 2 + 1] = hp1;
        ((__nv_bfloat162*)lo)[i * 2]     = lp0;
        ((__nv_bfloat162*)lo)[i * 2 + 1] = lp1;
    }
}

// ---------------------------------------------------------------------------
// W[K,N] fp32 -> Wt hi/lo [N,K] bf16 (transpose + split)
// ---------------------------------------------------------------------------
__global__ void __launch_bounds__(256) tsplit_kernel(
    const float* __restrict__ W, __nv_bfloat16* __restrict__ hi,
    __nv_bfloat16* __restrict__ lo, int K, int N)
{
    __shared__ float t[32][33];
    const int bn = blockIdx.x * 32, bk = blockIdx.y * 32;
    const int x = threadIdx.x & 31, y = threadIdx.x >> 5;
#pragma unroll
    for (int r = 0; r < 32; r += 8)
        t[y + r][x] = W[(long)(bk + y + r) * N + bn + x];
    __syncthreads();
#pragma unroll
    for (int r = 0; r < 32; r += 8) {
        float v = t[x][y + r];
        __nv_bfloat16 h = __float2bfloat16(v);
        float rem = v - __bfloat162float(h);
        long o = (long)(bn + y + r) * K + bk + x;
        hi[o] = h;
        lo[o] = __float2bfloat16(rem);
    }
}

// ---------------------------------------------------------------------------
// Attention (fp32 flash-style, from R0)
// ---------------------------------------------------------------------------
#define QT_STRIDE 132
#define KV_STRIDE 68

__global__ __launch_bounds__(256) void attn_kernel(
    const float* __restrict__ Q, const float* __restrict__ K,
    const float* __restrict__ V, float* __restrict__ O)
{
    extern __shared__ float sm[];
    float* Qt  = sm;
    float* Kt  = Qt + 64 * QT_STRIDE;
    float* Vs  = Kt + 64 * KV_STRIDE;
    float* Pt  = Vs + 64 * KV_STRIDE;
    float* den = Pt + 64 * QT_STRIDE;

    const int tid = threadIdx.x;
    const int bh = blockIdx.y;
    const int b = bh >> 4, h = bh & 15;
    const int q0 = blockIdx.x * 128;
    const long base   = (long)(b * SEQ + q0) * DMODEL + h * DHEAD;
    const long kvbase = (long)(b * SEQ) * DMODEL + h * DHEAD;

    for (int e = tid; e < 128 * 64; e += 256) {
        int i = e >> 6, d = e & 63;
        Qt[d * QT_STRIDE + i] = Q[base + (long)i * DMODEL + d];
    }
    if (tid < 128) den[tid] = 0.f;

    const int tr = tid >> 4, tc = tid & 15;
    const int i0 = tr * 8, c0 = tc * 4;

    float acc[8][4];
#pragma unroll
    for (int u = 0; u < 8; u++)
#pragma unroll
        for (int v = 0; v < 4; v++) acc[u][v] = 0.f;

    for (int kt = 0; kt < SEQ / 64; kt++) {
        __syncthreads();
        for (int e = tid; e < 64 * 64; e += 256) {
            int j = e >> 6, d = e & 63;
            long g = kvbase + (long)(kt * 64 + j) * DMODEL + d;
            Kt[d * KV_STRIDE + j] = K[g];
            Vs[j * KV_STRIDE + d] = V[g];
        }
        __syncthreads();

        float s[8][4];
#pragma unroll
        for (int u = 0; u < 8; u++)
#pragma unroll
            for (int v = 0; v < 4; v++) s[u][v] = 0.f;

        for (int d = 0; d < 64; d++) {
            float4 qa = *(const float4*)&Qt[d * QT_STRIDE + i0];
            float4 qb = *(const float4*)&Qt[d * QT_STRIDE + i0 + 4];
            float4 kv = *(const float4*)&Kt[d * KV_STRIDE + c0];
            float qv[8] = {qa.x,qa.y,qa.z,qa.w,qb.x,qb.y,qb.z,qb.w};
            float kr[4] = {kv.x,kv.y,kv.z,kv.w};
#pragma unroll
            for (int u = 0; u < 8; u++)
#pragma unroll
                for (int v = 0; v < 4; v++)
                    s[u][v] = fmaf(qv[u], kr[v], s[u][v]);
        }

#pragma unroll
        for (int u = 0; u < 8; u++)
#pragma unroll
            for (int v = 0; v < 4; v++) {
                float l = s[u][v] * 0.125f;
                l = fminf(fmaxf(l, -10.f), 10.f);
                Pt[(c0 + v) * QT_STRIDE + i0 + u] = __expf(l - 10.f);
            }
        __syncthreads();

        if (tid < 128) {
            float ds = 0.f;
#pragma unroll 8
            for (int j = 0; j < 64; j++) ds += Pt[j * QT_STRIDE + tid];
            den[tid] += ds;
        }

        for (int j = 0; j < 64; j++) {
            float4 pa = *(const float4*)&Pt[j * QT_STRIDE + i0];
            float4 pb = *(const float4*)&Pt[j * QT_STRIDE + i0 + 4];
            float4 vv = *(const float4*)&Vs[j * KV_STRIDE + c0];
            float pv[8] = {pa.x,pa.y,pa.z,pa.w,pb.x,pb.y,pb.z,pb.w};
            float vr[4] = {vv.x,vv.y,vv.z,vv.w};
#pragma unroll
            for (int u = 0; u < 8; u++)
#pragma unroll
                for (int v = 0; v < 4; v++)
                    acc[u][v] = fmaf(pv[u], vr[v], acc[u][v]);
        }
    }
    __syncthreads();

#pragma unroll
    for (int u = 0; u < 8; u++) {
        float inv = 1.f / den[i0 + u];
#pragma unroll
        for (int v = 0; v < 4; v++)
            O[base + (long)(i0 + u) * DMODEL + c0 + v] = acc[u][v] * inv;
    }
}

// ---------------------------------------------------------------------------
// out = LayerNorm(A + B) * gamma + beta
// ---------------------------------------------------------------------------
__global__ __launch_bounds__(256) void add_ln_kernel(
    const float* __restrict__ A, const float* __restrict__ B,
    const float* __restrict__ gamma, const float* __restrict__ beta,
    float* __restrict__ out)
{
    __shared__ float red[2];
    const int row = blockIdx.x;
    const int tid = threadIdx.x;

    float4 a = ((const float4*)(A + (long)row * DMODEL))[tid];
    float4 b = ((const float4*)(B + (long)row * DMODEL))[tid];
    float4 v = {a.x + b.x, a.y + b.y, a.z + b.z, a.w + b.w};

    float s  = v.x + v.y + v.z + v.w;
    float sq = v.x * v.x + v.y * v.y + v.z * v.z + v.w * v.w;
#pragma unroll
    for (int o = 16; o; o >>= 1) {
        s  += __shfl_xor_sync(~0u, s,  o);
        sq += __shfl_xor_sync(~0u, sq, o);
    }
    const int w = tid >> 5, l = tid & 31;
    __shared__ float ws[8], wq[8];
    if (l == 0) { ws[w] = s; wq[w] = sq; }
    __syncthreads();
    if (tid < 32) {
        float s2 = (tid < 8) ? ws[tid] : 0.f;
        float q2 = (tid < 8) ? wq[tid] : 0.f;
#pragma unroll
        for (int o = 4; o; o >>= 1) {
            s2 += __shfl_xor_sync(~0u, s2, o);
            q2 += __shfl_xor_sync(~0u, q2, o);
        }
        if (tid == 0) { red[0] = s2; red[1] = q2; }
    }
    __syncthreads();
    float mean = red[0] * (1.f / DMODEL);
    float var  = red[1] * (1.f / DMODEL) - mean * mean;
    float rs   = rsqrtf(var + 1e-8f);

    float4 g  = ((const float4*)gamma)[tid];
    float4 be = ((const float4*)beta)[tid];
    float4 o4;
    o4.x = (v.x - mean) * rs * g.x + be.x;
    o4.y = (v.y - mean) * rs * g.y + be.y;
    o4.z = (v.z - mean) * rs * g.z + be.z;
    o4.w = (v.w - mean) * rs * g.w + be.w;
    ((float4*)(out + (long)row * DMODEL))[tid] = o4;
}

// ---------------------------------------------------------------------------
extern "C" void kernel_launch(void* const* d_in, const int* in_sizes, int n_in,
                              void* d_out, int out_size)
{
    const float* x  = (const float*)d_in[0];
    const float* wq = (const float*)d_in[1];
    const float* bq = (const float*)d_in[2];
    const float* wk = (const float*)d_in[3];
    const float* bk = (const float*)d_in[4];
    const float* wv = (const float*)d_in[5];
    const float* bv = (const float*)d_in[6];
    const float* wo = (const float*)d_in[7];
    const float* bo = (const float*)d_in[8];
    const float* w1 = (const float*)d_in[9];
    const float* b1 = (const float*)d_in[10];
    const float* w2 = (const float*)d_in[11];
    const float* b2 = (const float*)d_in[12];
    const float* ga = (const float*)d_in[13];
    const float* be = (const float*)d_in[14];
    float* out = (float*)d_out;

    float *Qb, *Kb, *Vb, *Cb, *H1b;
    __nv_bfloat16 *Ahi, *Alo, *Whi, *Wlo;
    cudaGetSymbolAddress((void**)&Qb,  g_Q);
    cudaGetSymbolAddress((void**)&Kb,  g_K);
    cudaGetSymbolAddress((void**)&Vb,  g_V);
    cudaGetSymbolAddress((void**)&Cb,  g_CTX);
    cudaGetSymbolAddress((void**)&H1b, g_H1);
    cudaGetSymbolAddress((void**)&Ahi, g_Ahi);
    cudaGetSymbolAddress((void**)&Alo, g_Alo);
    cudaGetSymbolAddress((void**)&Whi, g_Wthi);
    cudaGetSymbolAddress((void**)&Wlo, g_Wtlo);

    const int ATTN_SMEM = (64 * QT_STRIDE * 2 + 64 * KV_STRIDE * 2 + 128) * (int)sizeof(float);
    cudaFuncSetAttribute(attn_kernel, cudaFuncAttributeMaxDynamicSharedMemorySize, ATTN_SMEM);

    dim3 blk(256);
    dim3 gProj(DMODEL / 128, M_TOK / 128);     // (8, 64)
    dim3 gF1(DFF / 128, M_TOK / 128);          // (32, 64)
    dim3 gT_d(DMODEL / 32, DMODEL / 32);
    dim3 gT_1(DFF / 32, DMODEL / 32);
    dim3 gT_2(DMODEL / 32, DFF / 32);

    // x -> split
    split_kernel<<<512, blk>>>(x, Ahi, Alo, (long)M_TOK * DMODEL / 4);

    // QKV projections
    tsplit_kernel<<<gT_d, blk>>>(wq, Whi, Wlo, DMODEL, DMODEL);
    gemm_mma<<<gProj, blk>>>(Ahi, Alo, Whi, Wlo, bq, Qb, DMODEL, DMODEL, 0);
    tsplit_kernel<<<gT_d, blk>>>(wk, Whi, Wlo, DMODEL, DMODEL);
    gemm_mma<<<gProj, blk>>>(Ahi, Alo, Whi, Wlo, bk, Kb, DMODEL, DMODEL, 0);
    tsplit_kernel<<<gT_d, blk>>>(wv, Whi, Wlo, DMODEL, DMODEL);
    gemm_mma<<<gProj, blk>>>(Ahi, Alo, Whi, Wlo, bv, Vb, DMODEL, DMODEL, 0);

    // Attention (fp32)
    dim3 gAttn(SEQ / 128, 4 * NHEAD);
    attn_kernel<<<gAttn, blk, ATTN_SMEM>>>(Qb, Kb, Vb, Cb);

    // O projection
    split_kernel<<<512, blk>>>(Cb, Ahi, Alo, (long)M_TOK * DMODEL / 4);
    tsplit_kernel<<<gT_d, blk>>>(wo, Whi, Wlo, DMODEL, DMODEL);
    gemm_mma<<<gProj, blk>>>(Ahi, Alo, Whi, Wlo, bo, Qb, DMODEL, DMODEL, 0);

    // out1 = LN(x + attn_out) -> Kb
    add_ln_kernel<<<M_TOK, blk>>>(x, Qb, ga, be, Kb);

    // FFN1
    split_kernel<<<512, blk>>>(Kb, Ahi, Alo, (long)M_TOK * DMODEL / 4);
    tsplit_kernel<<<gT_1, blk>>>(w1, Whi, Wlo, DMODEL, DFF);
    gemm_mma<<<gF1, blk>>>(Ahi, Alo, Whi, Wlo, b1, H1b, DFF, DMODEL, 1);

    // FFN2
    split_kernel<<<512, blk>>>(H1b, Ahi, Alo, (long)M_TOK * DFF / 4);
    tsplit_kernel<<<gT_2, blk>>>(w2, Whi, Wlo, DFF, DMODEL);
    gemm_mma<<<gProj, blk>>>(Ahi, Alo, Whi, Wlo, b2, Vb, DMODEL, DFF, 0);

    // out = LN(out1 + ffn)
    add_ln_kernel<<<M_TOK, blk>>>(Kb, Vb, ga, be, out);
}

// round 4
// speedup vs baseline: 2.2036x; 1.4392x over previous
#include <cuda_runtime.h>
#include <cuda_bf16.h>
#include <cstdint>

// ---------------------------------------------------------------------------
// EncoderLayer R3: HMMA split-bf16 GEMMs + HMMA attention + fused split epilogues
// ---------------------------------------------------------------------------

#define M_TOK   8192
#define DMODEL  1024
#define DFF     4096
#define NHEAD   16
#define DHEAD   64
#define SEQ     2048

// fp32 scratch
__device__ float g_S1 [M_TOK * DMODEL];
__device__ float g_S2 [M_TOK * DMODEL];
// bf16 split operands
__device__ __nv_bfloat16 g_Xhi[M_TOK * DMODEL];
__device__ __nv_bfloat16 g_Xlo[M_TOK * DMODEL];
__device__ __nv_bfloat16 g_Qhi[M_TOK * DMODEL];
__device__ __nv_bfloat16 g_Qlo[M_TOK * DMODEL];
__device__ __nv_bfloat16 g_Khi[M_TOK * DMODEL];
__device__ __nv_bfloat16 g_Klo[M_TOK * DMODEL];
__device__ __nv_bfloat16 g_Vhi[M_TOK * DMODEL];
__device__ __nv_bfloat16 g_Vlo[M_TOK * DMODEL];
__device__ __nv_bfloat16 g_Chi[M_TOK * DMODEL];   // ctx split
__device__ __nv_bfloat16 g_Clo[M_TOK * DMODEL];
__device__ __nv_bfloat16 g_O1hi[M_TOK * DMODEL];  // out1 split
__device__ __nv_bfloat16 g_O1lo[M_TOK * DMODEL];
__device__ __nv_bfloat16 g_H1hi[M_TOK * DFF];
__device__ __nv_bfloat16 g_H1lo[M_TOK * DFF];
// transposed split weights
__device__ __nv_bfloat16 g_Wthi[DFF * DMODEL];
__device__ __nv_bfloat16 g_Wtlo[DFF * DMODEL];

__device__ __forceinline__ uint32_t smem_u32(const void* p) {
    uint32_t a;
    asm("{ .reg .u64 t; cvta.to.shared.u64 t, %1; cvt.u32.u64 %0, t; }" : "=r"(a) : "l"(p));
    return a;
}
__device__ __forceinline__ void ldmat_x4(uint32_t* r, uint32_t addr) {
    asm volatile("ldmatrix.sync.aligned.m8n8.x4.shared.b16 {%0,%1,%2,%3}, [%4];"
                 : "=r"(r[0]), "=r"(r[1]), "=r"(r[2]), "=r"(r[3]) : "r"(addr));
}
__device__ __forceinline__ void ldmat_x4t(uint32_t* r, uint32_t addr) {
    asm volatile("ldmatrix.sync.aligned.m8n8.x4.trans.shared.b16 {%0,%1,%2,%3}, [%4];"
                 : "=r"(r[0]), "=r"(r[1]), "=r"(r[2]), "=r"(r[3]) : "r"(addr));
}
__device__ __forceinline__ void mma_bf16(float* d, const uint32_t* a, const uint32_t* b) {
    asm volatile("mma.sync.aligned.m16n8k16.row.col.f32.bf16.bf16.f32 "
                 "{%0,%1,%2,%3}, {%4,%5,%6,%7}, {%8,%9}, {%0,%1,%2,%3};"
                 : "+f"(d[0]), "+f"(d[1]), "+f"(d[2]), "+f"(d[3])
                 : "r"(a[0]), "r"(a[1]), "r"(a[2]), "r"(a[3]), "r"(b[0]), "r"(b[1]));
}
__device__ __forceinline__ uint32_t pack_bf2(float lo, float hi) {
    __nv_bfloat162 t = __floats2bfloat162_rn(lo, hi);
    return *reinterpret_cast<uint32_t*>(&t);
}

// ---------------------------------------------------------------------------
// Split-bf16 HMMA GEMM. mode 0: fp32 C. mode 1: bf16 hi/lo split outputs.
// BM=BN=128, BK=32. 256 threads = 2x4 warps, 64x32 per warp.
// ---------------------------------------------------------------------------
#define SM_STRIDE 40

__global__ void __launch_bounds__(256, 2) gemm_mma(
    const __nv_bfloat16* __restrict__ Ahi, const __nv_bfloat16* __restrict__ Alo,
    const __nv_bfloat16* __restrict__ Bhi, const __nv_bfloat16* __restrict__ Blo,
    const float* __restrict__ bias, float* __restrict__ C,
    __nv_bfloat16* __restrict__ Chi, __nv_bfloat16* __restrict__ Clo,
    int N, int K, int relu, int mode)
{
    __shared__ __nv_bfloat16 sA[2][128][SM_STRIDE];
    __shared__ __nv_bfloat16 sB[2][128][SM_STRIDE];

    const int tid = threadIdx.x;
    const int wid = tid >> 5, lid = tid & 31;
    const int m0 = blockIdx.y * 128, n0 = blockIdx.x * 128;
    const int wm = (wid >> 2) * 64;
    const int wn = (wid & 3) * 32;

    const int r  = tid >> 2;
    const int cg = (tid & 3) * 8;

    float acc[4][4][4];
#pragma unroll
    for (int mt = 0; mt < 4; mt++)
#pragma unroll
        for (int nt = 0; nt < 4; nt++)
#pragma unroll
            for (int f = 0; f < 4; f++) acc[mt][nt][f] = 0.f;

    const int lrow = lid & 15;
    const int lcol = (lid >> 4) * 8;

    const uint32_t aBase[2] = { smem_u32(&sA[0][0][0]), smem_u32(&sA[1][0][0]) };
    const uint32_t bBase[2] = { smem_u32(&sB[0][0][0]), smem_u32(&sB[1][0][0]) };

    const int NC = K >> 5;
    for (int i = 0; i < NC; i++) {
        const int k0 = i << 5;
        uint4 av0, av1, al0, al1, bv0, bv1, bl0, bl1;
        {
            const long ra = (long)(m0 + r) * K + k0 + cg;
            const long rb = (long)(n0 + r) * K + k0 + cg;
            av0 = *(const uint4*)(Ahi + ra);
            av1 = *(const uint4*)(Ahi + ra + 64 * (long)K);
            al0 = *(const uint4*)(Alo + ra);
            al1 = *(const uint4*)(Alo + ra + 64 * (long)K);
            bv0 = *(const uint4*)(Bhi + rb);
            bv1 = *(const uint4*)(Bhi + rb + 64 * (long)K);
            bl0 = *(const uint4*)(Blo + rb);
            bl1 = *(const uint4*)(Blo + rb + 64 * (long)K);
        }
        __syncthreads();
        *(uint4*)&sA[0][r][cg]      = av0;
        *(uint4*)&sA[0][r + 64][cg] = av1;
        *(uint4*)&sA[1][r][cg]      = al0;
        *(uint4*)&sA[1][r + 64][cg] = al1;
        *(uint4*)&sB[0][r][cg]      = bv0;
        *(uint4*)&sB[0][r + 64][cg] = bv1;
        *(uint4*)&sB[1][r][cg]      = bl0;
        *(uint4*)&sB[1][r + 64][cg] = bl1;
        __syncthreads();

#pragma unroll
        for (int p = 0; p < 3; p++) {
            const uint32_t aB = aBase[p == 2 ? 1 : 0];
            const uint32_t bB = bBase[p == 1 ? 1 : 0];
#pragma unroll
            for (int k16 = 0; k16 < 2; k16++) {
                uint32_t af[4][4];
#pragma unroll
                for (int mt = 0; mt < 4; mt++) {
                    uint32_t addr = aB + ((wm + mt * 16 + lrow) * SM_STRIDE + k16 * 16 + lcol) * 2;
                    ldmat_x4(af[mt], addr);
                }
                uint32_t bf[2][4];
#pragma unroll
                for (int np = 0; np < 2; np++) {
                    uint32_t addr = bB + ((wn + np * 16 + lrow) * SM_STRIDE + k16 * 16 + lcol) * 2;
                    ldmat_x4(bf[np], addr);
                }
#pragma unroll
                for (int mt = 0; mt < 4; mt++) {
#pragma unroll
                    for (int nt = 0; nt < 4; nt++) {
                        uint32_t bfr[2] = { bf[nt >> 1][nt & 1], bf[nt >> 1][(nt & 1) + 2] };
                        mma_bf16(acc[mt][nt], af[mt], bfr);
                    }
                }
            }
        }
    }

    const int g  = lid >> 2;
    const int tg = (lid & 3) * 2;
#pragma unroll
    for (int mt = 0; mt < 4; mt++) {
        const int row = m0 + wm + mt * 16 + g;
#pragma unroll
        for (int nt = 0; nt < 4; nt++) {
            const int col = n0 + wn + nt * 8 + tg;
            const float b0 = bias[col], b1 = bias[col + 1];
            float v0 = acc[mt][nt][0] + b0;
            float v1 = acc[mt][nt][1] + b1;
            float v2 = acc[mt][nt][2] + b0;
            float v3 = acc[mt][nt][3] + b1;
            if (relu) {
                v0 = fmaxf(v0, 0.f); v1 = fmaxf(v1, 0.f);
                v2 = fmaxf(v2, 0.f); v3 = fmaxf(v3, 0.f);
            }
            if (mode == 0) {
                C[(long)row * N + col]           = v0;
                C[(long)row * N + col + 1]       = v1;
                C[(long)(row + 8) * N + col]     = v2;
                C[(long)(row + 8) * N + col + 1] = v3;
            } else {
                float h0 = __bfloat162float(__float2bfloat16(v0));
                float h1 = __bfloat162float(__float2bfloat16(v1));
                float h2 = __bfloat162float(__float2bfloat16(v2));
                float h3 = __bfloat162float(__float2bfloat16(v3));
                *(uint32_t*)(Chi + (long)row * N + col)       = pack_bf2(h0, h1);
                *(uint32_t*)(Chi + (long)(row + 8) * N + col) = pack_bf2(h2, h3);
                *(uint32_t*)(Clo + (long)row * N + col)       = pack_bf2(v0 - h0, v1 - h1);
                *(uint32_t*)(Clo + (long)(row + 8) * N + col) = pack_bf2(v2 - h2, v3 - h3);
            }
        }
    }
}

// ---------------------------------------------------------------------------
// HMMA attention. Per block: one (b,h), 128 queries. 8 warps x 16 rows.
// S = QK^T (3-term split), p = exp(clip(S/8)-10), ctx = (P@V)/rowsum(P).
// Writes ctx as split bf16 (feeds O-proj directly).
// ---------------------------------------------------------------------------
#define AT_STRIDE 72    // 64 + 8 pad (bf16)

__global__ void __launch_bounds__(256, 2) attn_mma(
    const __nv_bfloat16* __restrict__ Qhi, const __nv_bfloat16* __restrict__ Qlo,
    const __nv_bfloat16* __restrict__ Khi, const __nv_bfloat16* __restrict__ Klo,
    const __nv_bfloat16* __restrict__ Vhi, const __nv_bfloat16* __restrict__ Vlo,
    __nv_bfloat16* __restrict__ Chi, __nv_bfloat16* __restrict__ Clo)
{
    extern __shared__ __nv_bfloat16 smA[];
    __nv_bfloat16* sQh = smA;                    // [128][72]
    __nv_bfloat16* sQl = sQh + 128 * AT_STRIDE;
    __nv_bfloat16* sKh = sQl + 128 * AT_STRIDE;  // [64][72]
    __nv_bfloat16* sKl = sKh + 64 * AT_STRIDE;
    __nv_bfloat16* sVh = sKl + 64 * AT_STRIDE;
    __nv_bfloat16* sVl = sVh + 64 * AT_STRIDE;

    const int tid = threadIdx.x;
    const int wid = tid >> 5, lid = tid & 31;
    const int bh = blockIdx.y;
    const int b = bh >> 4, h = bh & 15;
    const int q0 = blockIdx.x * 128;
    const long qbase  = (long)(b * SEQ + q0) * DMODEL + h * DHEAD;
    const long kvbase = (long)(b * SEQ) * DMODEL + h * DHEAD;

    const uint32_t qhB = smem_u32(sQh), qlB = smem_u32(sQl);
    const uint32_t khB = smem_u32(sKh), klB = smem_u32(sKl);
    const uint32_t vhB = smem_u32(sVh), vlB = smem_u32(sVl);

    // load Q tile (128 x 64) hi/lo
    for (int e = tid; e < 128 * 8; e += 256) {
        int row = e >> 3, cgp = (e & 7) * 8;
        const long gp = qbase + (long)row * DMODEL + cgp;
        *(uint4*)(sQh + row * AT_STRIDE + cgp) = *(const uint4*)(Qhi + gp);
        *(uint4*)(sQl + row * AT_STRIDE + cgp) = *(const uint4*)(Qlo + gp);
    }

    const int mrow = wid * 16;
    const int lrow = lid & 15;
    const int lcol = (lid >> 4) * 8;

    float acc[8][4];
#pragma unroll
    for (int nt = 0; nt < 8; nt++)
#pragma unroll
        for (int f = 0; f < 4; f++) acc[nt][f] = 0.f;
    float den0 = 0.f, den1 = 0.f;

    for (int kt = 0; kt < SEQ / 64; kt++) {
        __syncthreads();
        // load K/V chunk (64 x 64) hi/lo
        for (int e = tid; e < 64 * 8; e += 256) {
            int row = e >> 3, cgp = (e & 7) * 8;
            const long gp = kvbase + (long)(kt * 64 + row) * DMODEL + cgp;
            *(uint4*)(sKh + row * AT_STRIDE + cgp) = *(const uint4*)(Khi + gp);
            *(uint4*)(sKl + row * AT_STRIDE + cgp) = *(const uint4*)(Klo + gp);
            *(uint4*)(sVh + row * AT_STRIDE + cgp) = *(const uint4*)(Vhi + gp);
            *(uint4*)(sVl + row * AT_STRIDE + cgp) = *(const uint4*)(Vlo + gp);
        }
        __syncthreads();

        // S = Q K^T  (3-term split), 16 rows x 64 keys per warp
        float S[8][4];
#pragma unroll
        for (int nt = 0; nt < 8; nt++)
#pragma unroll
            for (int f = 0; f < 4; f++) S[nt][f] = 0.f;

#pragma unroll
        for (int k16 = 0; k16 < 4; k16++) {
            uint32_t aH[4], aL[4];
            ldmat_x4(aH, qhB + ((mrow + lrow) * AT_STRIDE + k16 * 16 + lcol) * 2);
            ldmat_x4(aL, qlB + ((mrow + lrow) * AT_STRIDE + k16 * 16 + lcol) * 2);
#pragma unroll
            for (int np = 0; np < 4; np++) {
                uint32_t bH[4], bL[4];
                ldmat_x4(bH, khB + ((np * 16 + lrow) * AT_STRIDE + k16 * 16 + lcol) * 2);
                ldmat_x4(bL, klB + ((np * 16 + lrow) * AT_STRIDE + k16 * 16 + lcol) * 2);
                uint32_t f0H[2] = { bH[0], bH[2] }, f1H[2] = { bH[1], bH[3] };
                uint32_t f0L[2] = { bL[0], bL[2] }, f1L[2] = { bL[1], bL[3] };
                mma_bf16(S[2 * np],     aH, f0H);
                mma_bf16(S[2 * np],     aH, f0L);
                mma_bf16(S[2 * np],     aL, f0H);
                mma_bf16(S[2 * np + 1], aH, f1H);
                mma_bf16(S[2 * np + 1], aH, f1L);
                mma_bf16(S[2 * np + 1], aL, f1H);
            }
        }

        // p = exp(clip(S/8) - 10); pack to bf16 A-fragments; accumulate den
        uint32_t P[4][4];
#pragma unroll
        for (int nt = 0; nt < 8; nt++) {
            float e0 = __expf(fminf(fmaxf(S[nt][0] * 0.125f, -10.f), 10.f) - 10.f);
            float e1 = __expf(fminf(fmaxf(S[nt][1] * 0.125f, -10.f), 10.f) - 10.f);
            float e2 = __expf(fminf(fmaxf(S[nt][2] * 0.125f, -10.f), 10.f) - 10.f);
            float e3 = __expf(fminf(fmaxf(S[nt][3] * 0.125f, -10.f), 10.f) - 10.f);
            den0 += e0 + e1;
            den1 += e2 + e3;
            const int j = nt >> 1;
            if ((nt & 1) == 0) { P[j][0] = pack_bf2(e0, e1); P[j][1] = pack_bf2(e2, e3); }
            else               { P[j][2] = pack_bf2(e0, e1); P[j][3] = pack_bf2(e2, e3); }
        }

        // acc += P @ V (V split, ldmatrix.trans)
#pragma unroll
        for (int j = 0; j < 4; j++) {
#pragma unroll
            for (int np = 0; np < 4; np++) {
                uint32_t vH[4], vL[4];
                ldmat_x4t(vH, vhB + ((j * 16 + lrow) * AT_STRIDE + np * 16 + lcol) * 2);
                ldmat_x4t(vL, vlB + ((j * 16 + lrow) * AT_STRIDE + np * 16 + lcol) * 2);
                uint32_t fH0[2] = { vH[0], vH[1] }, fH1[2] = { vH[2], vH[3] };
                uint32_t fL0[2] = { vL[0], vL[1] }, fL1[2] = { vL[2], vL[3] };
                mma_bf16(acc[2 * np],     P[j], fH0);
                mma_bf16(acc[2 * np],     P[j], fL0);
                mma_bf16(acc[2 * np + 1], P[j], fH1);
                mma_bf16(acc[2 * np + 1], P[j], fL1);
            }
        }
    }

    // reduce denominators across the 4 lanes of each row group
    den0 += __shfl_xor_sync(~0u, den0, 1);
    den0 += __shfl_xor_sync(~0u, den0, 2);
    den1 += __shfl_xor_sync(~0u, den1, 1);
    den1 += __shfl_xor_sync(~0u, den1, 2);
    const float i0 = 1.f / den0, i1 = 1.f / den1;

    // write ctx as split bf16
    const int g  = lid >> 2;
    const int tg = (lid & 3) * 2;
    const long row0 = (long)(b * SEQ + q0 + mrow + g) * DMODEL + h * DHEAD;
    const long row1 = row0 + 8 * DMODEL;
#pragma unroll
    for (int nt = 0; nt < 8; nt++) {
        const int col = nt * 8 + tg;
        float v0 = acc[nt][0] * i0, v1 = acc[nt][1] * i0;
        float v2 = acc[nt][2] * i1, v3 = acc[nt][3] * i1;
        float h0 = __bfloat162float(__float2bfloat16(v0));
        float h1 = __bfloat162float(__float2bfloat16(v1));
        float h2 = __bfloat162float(__float2bfloat16(v2));
        float h3 = __bfloat162float(__float2bfloat16(v3));
        *(uint32_t*)(Chi + row0 + col) = pack_bf2(h0, h1);
        *(uint32_t*)(Chi + row1 + col) = pack_bf2(h2, h3);
        *(uint32_t*)(Clo + row0 + col) = pack_bf2(v0 - h0, v1 - h1);
        *(uint32_t*)(Clo + row1 + col) = pack_bf2(v2 - h2, v3 - h3);
    }
}

// ---------------------------------------------------------------------------
// fp32 -> (hi, lo) bf16 split (input x only)
// ---------------------------------------------------------------------------
__global__ void __launch_bounds__(256) split_kernel(
    const float* __restrict__ A, __nv_bfloat16* __restrict__ hi,
    __nv_bfloat16* __restrict__ lo, long n4)
{
    long i = (long)blockIdx.x * blockDim.x + threadIdx.x;
    long stride = (long)gridDim.x * blockDim.x;
    for (; i < n4; i += stride) {
        float4 v = ((const float4*)A)[i];
        __nv_bfloat16 h0 = __float2bfloat16(v.x), h1 = __float2bfloat16(v.y);
        __nv_bfloat16 h2 = __float2bfloat16(v.z), h3 = __float2bfloat16(v.w);
        __nv_bfloat16 l0 = __float2bfloat16(v.x - __bfloat162float(h0));
        __nv_bfloat16 l1 = __float2bfloat16(v.y - __bfloat162float(h1));
        __nv_bfloat16 l2 = __float2bfloat16(v.z - __bfloat162float(h2));
        __nv_bfloat16 l3 = __float2bfloat16(v.w - __bfloat162float(h3));
        __nv_bfloat162 hp0(h0, h1), hp1(h2, h3), lp0(l0, l1), lp1(l2, l3);
        ((__nv_bfloat162*)hi)[i * 2]     = hp0;
        ((__nv_bfloat162*)hi)[i * 2 + 1] = hp1;
        ((__nv_bfloat162*)lo)[i * 2]     = lp0;
        ((__nv_bfloat162*)lo)[i * 2 + 1] = lp1;
    }
}

// ---------------------------------------------------------------------------
// W[K,N] fp32 -> Wt hi/lo [N,K] bf16 (transpose + split)
// ---------------------------------------------------------------------------
__global__ void __launch_bounds__(256) tsplit_kernel(
    const float* __restrict__ W, __nv_bfloat16* __restrict__ hi,
    __nv_bfloat16* __restrict__ lo, int K, int N)
{
    __shared__ float t[32][33];
    const int bn = blockIdx.x * 32, bk = blockIdx.y * 32;
    const int x = threadIdx.x & 31, y = threadIdx.x >> 5;
#pragma unroll
    for (int r = 0; r < 32; r += 8)
        t[y + r][x] = W[(long)(bk + y + r) * N + bn + x];
    __syncthreads();
#pragma unroll
    for (int r = 0; r < 32; r += 8) {
        float v = t[x][y + r];
        __nv_bfloat16 hh = __float2bfloat16(v);
        float rem = v - __bfloat162float(hh);
        long o = (long)(bn + y + r) * K + bk + x;
        hi[o] = hh;
        lo[o] = __float2bfloat16(rem);
    }
}

// ---------------------------------------------------------------------------
// out = LayerNorm(A + B) * gamma + beta ; optional split bf16 output
// ---------------------------------------------------------------------------
__global__ __launch_bounds__(256) void add_ln_kernel(
    const float* __restrict__ A, const float* __restrict__ B,
    const float* __restrict__ gamma, const float* __restrict__ beta,
    float* __restrict__ out,
    __nv_bfloat16* __restrict__ ohi, __nv_bfloat16* __restrict__ olo,
    int do_split)
{
    __shared__ float red[2];
    const int row = blockIdx.x;
    const int tid = threadIdx.x;

    float4 a = ((const float4*)(A + (long)row * DMODEL))[tid];
    float4 b = ((const float4*)(B + (long)row * DMODEL))[tid];
    float4 v = {a.x + b.x, a.y + b.y, a.z + b.z, a.w + b.w};

    float s  = v.x + v.y + v.z + v.w;
    float sq = v.x * v.x + v.y * v.y + v.z * v.z + v.w * v.w;
#pragma unroll
    for (int o = 16; o; o >>= 1) {
        s  += __shfl_xor_sync(~0u, s,  o);
        sq += __shfl_xor_sync(~0u, sq, o);
    }
    const int w = tid >> 5, l = tid & 31;
    __shared__ float ws[8], wq[8];
    if (l == 0) { ws[w] = s; wq[w] = sq; }
    __syncthreads();
    if (tid < 32) {
        float s2 = (tid < 8) ? ws[tid] : 0.f;
        float q2 = (tid < 8) ? wq[tid] : 0.f;
#pragma unroll
        for (int o = 4; o; o >>= 1) {
            s2 += __shfl_xor_sync(~0u, s2, o);
            q2 += __shfl_xor_sync(~0u, q2, o);
        }
        if (tid == 0) { red[0] = s2; red[1] = q2; }
    }
    __syncthreads();
    float mean = red[0] * (1.f / DMODEL);
    float var  = red[1] * (1.f / DMODEL) - mean * mean;
    float rs   = rsqrtf(var + 1e-8f);

    float4 g  = ((const float4*)gamma)[tid];
    float4 be = ((const float4*)beta)[tid];
    float4 o4;
    o4.x = (v.x - mean) * rs * g.x + be.x;
    o4.y = (v.y - mean) * rs * g.y + be.y;
    o4.z = (v.z - mean) * rs * g.z + be.z;
    o4.w = (v.w - mean) * rs * g.w + be.w;
    ((float4*)(out + (long)row * DMODEL))[tid] = o4;

    if (do_split) {
        float h0 = __bfloat162float(__float2bfloat16(o4.x));
        float h1 = __bfloat162float(__float2bfloat16(o4.y));
        float h2 = __bfloat162float(__float2bfloat16(o4.z));
        float h3 = __bfloat162float(__float2bfloat16(o4.w));
        uint2 hv = { pack_bf2(h0, h1), pack_bf2(h2, h3) };
        uint2 lv = { pack_bf2(o4.x - h0, o4.y - h1), pack_bf2(o4.z - h2, o4.w - h3) };
        ((uint2*)(ohi + (long)row * DMODEL))[tid] = hv;
        ((uint2*)(olo + (long)row * DMODEL))[tid] = lv;
    }
}

// ---------------------------------------------------------------------------
extern "C" void kernel_launch(void* const* d_in, const int* in_sizes, int n_in,
                              void* d_out, int out_size)
{
    const float* x  = (const float*)d_in[0];
    const float* wq = (const float*)d_in[1];
    const float* bq = (const float*)d_in[2];
    const float* wk = (const float*)d_in[3];
    const float* bk = (const float*)d_in[4];
    const float* wv = (const float*)d_in[5];
    const float* bv = (const float*)d_in[6];
    const float* wo = (const float*)d_in[7];
    const float* bo = (const float*)d_in[8];
    const float* w1 = (const float*)d_in[9];
    const float* b1 = (const float*)d_in[10];
    const float* w2 = (const float*)d_in[11];
    const float* b2 = (const float*)d_in[12];
    const float* ga = (const float*)d_in[13];
    const float* be = (const float*)d_in[14];
    float* out = (float*)d_out;

    float *S1, *S2;
    __nv_bfloat16 *Xhi, *Xlo, *Qhi, *Qlo, *Khi, *Klo, *Vhi, *Vlo;
    __nv_bfloat16 *Chi, *Clo, *O1hi, *O1lo, *H1hi, *H1lo, *Whi, *Wlo;
    cudaGetSymbolAddress((void**)&S1,   g_S1);
    cudaGetSymbolAddress((void**)&S2,   g_S2);
    cudaGetSymbolAddress((void**)&Xhi,  g_Xhi);
    cudaGetSymbolAddress((void**)&Xlo,  g_Xlo);
    cudaGetSymbolAddress((void**)&Qhi,  g_Qhi);
    cudaGetSymbolAddress((void**)&Qlo,  g_Qlo);
    cudaGetSymbolAddress((void**)&Khi,  g_Khi);
    cudaGetSymbolAddress((void**)&Klo,  g_Klo);
    cudaGetSymbolAddress((void**)&Vhi,  g_Vhi);
    cudaGetSymbolAddress((void**)&Vlo,  g_Vlo);
    cudaGetSymbolAddress((void**)&Chi,  g_Chi);
    cudaGetSymbolAddress((void**)&Clo,  g_Clo);
    cudaGetSymbolAddress((void**)&O1hi, g_O1hi);
    cudaGetSymbolAddress((void**)&O1lo, g_O1lo);
    cudaGetSymbolAddress((void**)&H1hi, g_H1hi);
    cudaGetSymbolAddress((void**)&H1lo, g_H1lo);
    cudaGetSymbolAddress((void**)&Whi,  g_Wthi);
    cudaGetSymbolAddress((void**)&Wlo,  g_Wtlo);

    const int ATTN_SMEM = (2 * 128 + 4 * 64) * AT_STRIDE * 2;   // 73728 B
    cudaFuncSetAttribute(attn_mma, cudaFuncAttributeMaxDynamicSharedMemorySize, ATTN_SMEM);

    dim3 blk(256);
    dim3 gProj(DMODEL / 128, M_TOK / 128);
    dim3 gF1(DFF / 128, M_TOK / 128);
    dim3 gT_d(DMODEL / 32, DMODEL / 32);
    dim3 gT_1(DFF / 32, DMODEL / 32);
    dim3 gT_2(DMODEL / 32, DFF / 32);

    // split input
    split_kernel<<<512, blk>>>(x, Xhi, Xlo, (long)M_TOK * DMODEL / 4);

    // QKV projections -> split bf16 outputs
    tsplit_kernel<<<gT_d, blk>>>(wq, Whi, Wlo, DMODEL, DMODEL);
    gemm_mma<<<gProj, blk>>>(Xhi, Xlo, Whi, Wlo, bq, nullptr, Qhi, Qlo, DMODEL, DMODEL, 0, 1);
    tsplit_kernel<<<gT_d, blk>>>(wk, Whi, Wlo, DMODEL, DMODEL);
    gemm_mma<<<gProj, blk>>>(Xhi, Xlo, Whi, Wlo, bk, nullptr, Khi, Klo, DMODEL, DMODEL, 0, 1);
    tsplit_kernel<<<gT_d, blk>>>(wv, Whi, Wlo, DMODEL, DMODEL);
    gemm_mma<<<gProj, blk>>>(Xhi, Xlo, Whi, Wlo, bv, nullptr, Vhi, Vlo, DMODEL, DMODEL, 0, 1);

    // attention -> ctx split
    dim3 gAttn(SEQ / 128, 4 * NHEAD);
    attn_mma<<<gAttn, blk, ATTN_SMEM>>>(Qhi, Qlo, Khi, Klo, Vhi, Vlo, Chi, Clo);

    // O projection -> fp32
    tsplit_kernel<<<gT_d, blk>>>(wo, Whi, Wlo, DMODEL, DMODEL);
    gemm_mma<<<gProj, blk>>>(Chi, Clo, Whi, Wlo, bo, S1, nullptr, nullptr, DMODEL, DMODEL, 0, 0);

    // out1 = LN(x + attn_out) -> S2 fp32 + split
    add_ln_kernel<<<M_TOK, blk>>>(x, S1, ga, be, S2, O1hi, O1lo, 1);

    // FFN1 -> relu -> split
    tsplit_kernel<<<gT_1, blk>>>(w1, Whi, Wlo, DMODEL, DFF);
    gemm_mma<<<gF1, blk>>>(O1hi, O1lo, Whi, Wlo, b1, nullptr, H1hi, H1lo, DFF, DMODEL, 1, 1);

    // FFN2 -> fp32
    tsplit_kernel<<<gT_2, blk>>>(w2, Whi, Wlo, DFF, DMODEL);
    gemm_mma<<<gProj, blk>>>(H1hi, H1lo, Whi, Wlo, b2, S1, nullptr, nullptr, DMODEL, DFF, 0, 0);

    // out = LN(out1 + ffn)
    add_ln_kernel<<<M_TOK, blk>>>(S2, S1, ga, be, out, nullptr, nullptr, 0);
}

// round 5
// speedup vs baseline: 2.4912x; 1.1305x over previous
#include <cuda_runtime.h>
#include <cuda_bf16.h>
#include <cstdint>

// ---------------------------------------------------------------------------
// EncoderLayer R4: cp.async-pipelined HMMA split-bf16 GEMMs (merged QKV),
// pipelined HMMA attention, fused split epilogues.
// ---------------------------------------------------------------------------

#define M_TOK   8192
#define DMODEL  1024
#define DFF     4096
#define NHEAD   16
#define DHEAD   64
#define SEQ     2048
#define QKVS    3072      // fused QKV row stride

// fp32 scratch
__device__ float g_S1 [M_TOK * DMODEL];
__device__ float g_S2 [M_TOK * DMODEL];
__device__ float g_b3 [QKVS];
// bf16 split operands
__device__ __nv_bfloat16 g_Xhi [M_TOK * DMODEL];
__device__ __nv_bfloat16 g_Xlo [M_TOK * DMODEL];
__device__ __nv_bfloat16 g_QKVhi[M_TOK * QKVS];
__device__ __nv_bfloat16 g_QKVlo[M_TOK * QKVS];
__device__ __nv_bfloat16 g_Chi [M_TOK * DMODEL];
__device__ __nv_bfloat16 g_Clo [M_TOK * DMODEL];
__device__ __nv_bfloat16 g_O1hi[M_TOK * DMODEL];
__device__ __nv_bfloat16 g_O1lo[M_TOK * DMODEL];
__device__ __nv_bfloat16 g_H1hi[M_TOK * DFF];
__device__ __nv_bfloat16 g_H1lo[M_TOK * DFF];
__device__ __nv_bfloat16 g_Wthi[DFF * DMODEL];
__device__ __nv_bfloat16 g_Wtlo[DFF * DMODEL];

__device__ __forceinline__ uint32_t smem_u32(const void* p) {
    uint32_t a;
    asm("{ .reg .u64 t; cvta.to.shared.u64 t, %1; cvt.u32.u64 %0, t; }" : "=r"(a) : "l"(p));
    return a;
}
__device__ __forceinline__ void ldmat_x4(uint32_t* r, uint32_t addr) {
    asm volatile("ldmatrix.sync.aligned.m8n8.x4.shared.b16 {%0,%1,%2,%3}, [%4];"
                 : "=r"(r[0]), "=r"(r[1]), "=r"(r[2]), "=r"(r[3]) : "r"(addr));
}
__device__ __forceinline__ void ldmat_x4t(uint32_t* r, uint32_t addr) {
    asm volatile("ldmatrix.sync.aligned.m8n8.x4.trans.shared.b16 {%0,%1,%2,%3}, [%4];"
                 : "=r"(r[0]), "=r"(r[1]), "=r"(r[2]), "=r"(r[3]) : "r"(addr));
}
__device__ __forceinline__ void mma_bf16(float* d, const uint32_t* a, const uint32_t* b) {
    asm volatile("mma.sync.aligned.m16n8k16.row.col.f32.bf16.bf16.f32 "
                 "{%0,%1,%2,%3}, {%4,%5,%6,%7}, {%8,%9}, {%0,%1,%2,%3};"
                 : "+f"(d[0]), "+f"(d[1]), "+f"(d[2]), "+f"(d[3])
                 : "r"(a[0]), "r"(a[1]), "r"(a[2]), "r"(a[3]), "r"(b[0]), "r"(b[1]));
}
__device__ __forceinline__ uint32_t pack_bf2(float lo, float hi) {
    __nv_bfloat162 t = __floats2bfloat162_rn(lo, hi);
    return *reinterpret_cast<uint32_t*>(&t);
}
#define CP16(dst, src) asm volatile("cp.async.cg.shared.global [%0], [%1], 16;" :: "r"(dst), "l"(src))
#define CP_COMMIT()    asm volatile("cp.async.commit_group;" ::: "memory")
#define CP_WAIT1()     asm volatile("cp.async.wait_group 1;" ::: "memory")
#define CP_WAIT0()     asm volatile("cp.async.wait_group 0;" ::: "memory")

// ---------------------------------------------------------------------------
// Split-bf16 HMMA GEMM, cp.async double-buffered.
// BM=BN=128, BK=32. 256 threads = 2x4 warps, 64x32 per warp.
// smem stage (bytes): AHI 10240 | ALO 10240 | BHI 10240 | BLO 10240 = 40960
// ---------------------------------------------------------------------------
#define SMS 40           // padded stride, elements (80 bytes/row)
#define GST 40960        // stage size bytes
#define OF_AHI 0
#define OF_ALO 10240
#define OF_BHI 20480
#define OF_BLO 30720
#define GEMM_SMEM (2 * GST)

__global__ void __launch_bounds__(256, 2) gemm_mma(
    const __nv_bfloat16* __restrict__ Ahi, const __nv_bfloat16* __restrict__ Alo,
    const __nv_bfloat16* __restrict__ Bhi, const __nv_bfloat16* __restrict__ Blo,
    const float* __restrict__ bias, float* __restrict__ C,
    __nv_bfloat16* __restrict__ Chi, __nv_bfloat16* __restrict__ Clo,
    int N, int K, int relu, int mode)
{
    extern __shared__ char smraw[];
    const uint32_t sb = smem_u32(smraw);

    const int tid = threadIdx.x;
    const int wid = tid >> 5, lid = tid & 31;
    const int m0 = blockIdx.y * 128, n0 = blockIdx.x * 128;
    const int wm = (wid >> 2) * 64;
    const int wn = (wid & 3) * 32;

    const int r   = tid >> 2;          // 0..63
    const int cg  = (tid & 3) * 8;     // element col
    const uint32_t soff = (uint32_t)(r * 80 + cg * 2);   // byte offset in tile

    float acc[4][4][4];
#pragma unroll
    for (int mt = 0; mt < 4; mt++)
#pragma unroll
        for (int nt = 0; nt < 4; nt++)
#pragma unroll
            for (int f = 0; f < 4; f++) acc[mt][nt][f] = 0.f;

    const int lrow = lid & 15;
    const int lcol = (lid >> 4) * 8;
    const int NC = K >> 5;

    // ---- async load of chunk i into stage i&1 ----
    auto issue = [&](int i) {
        const int s = i & 1;
        const uint32_t base = sb + s * GST;
        const long k0 = (long)(i << 5);
        const long ra = (long)(m0 + r) * K + k0 + cg;
        const long rb = (long)(n0 + r) * K + k0 + cg;
        CP16(base + OF_AHI + soff,            Ahi + ra);
        CP16(base + OF_AHI + soff + 64 * 80,  Ahi + ra + 64 * (long)K);
        CP16(base + OF_ALO + soff,            Alo + ra);
        CP16(base + OF_ALO + soff + 64 * 80,  Alo + ra + 64 * (long)K);
        CP16(base + OF_BHI + soff,            Bhi + rb);
        CP16(base + OF_BHI + soff + 64 * 80,  Bhi + rb + 64 * (long)K);
        CP16(base + OF_BLO + soff,            Blo + rb);
        CP16(base + OF_BLO + soff + 64 * 80,  Blo + rb + 64 * (long)K);
    };

    issue(0);
    CP_COMMIT();

    for (int i = 0; i < NC; i++) {
        if (i + 1 < NC) { issue(i + 1); CP_COMMIT(); CP_WAIT1(); }
        else            { CP_WAIT0(); }
        __syncthreads();

        const uint32_t base = sb + (i & 1) * GST;
        const uint32_t aH = base + OF_AHI, aL = base + OF_ALO;
        const uint32_t bH = base + OF_BHI, bL = base + OF_BLO;

#pragma unroll
        for (int k16 = 0; k16 < 2; k16++) {
            const uint32_t ao = ((wm + lrow) * SMS + k16 * 16 + lcol) * 2;
            const uint32_t bo = ((wn + lrow) * SMS + k16 * 16 + lcol) * 2;
            uint32_t afH[4][4], afL[4][4];
#pragma unroll
            for (int mt = 0; mt < 4; mt++) {
                ldmat_x4(afH[mt], aH + ao + mt * 16 * SMS * 2);
                ldmat_x4(afL[mt], aL + ao + mt * 16 * SMS * 2);
            }
            uint32_t bfH[2][4], bfL[2][4];
#pragma unroll
            for (int np = 0; np < 2; np++) {
                ldmat_x4(bfH[np], bH + bo + np * 16 * SMS * 2);
                ldmat_x4(bfL[np], bL + bo + np * 16 * SMS * 2);
            }
#pragma unroll
            for (int mt = 0; mt < 4; mt++) {
#pragma unroll
                for (int nt = 0; nt < 4; nt++) {
                    uint32_t bH2[2] = { bfH[nt >> 1][nt & 1], bfH[nt >> 1][(nt & 1) + 2] };
                    uint32_t bL2[2] = { bfL[nt >> 1][nt & 1], bfL[nt >> 1][(nt & 1) + 2] };
                    mma_bf16(acc[mt][nt], afH[mt], bH2);   // hi*hi
                    mma_bf16(acc[mt][nt], afH[mt], bL2);   // hi*lo
                    mma_bf16(acc[mt][nt], afL[mt], bH2);   // lo*hi
                }
            }
        }
        __syncthreads();
    }

    const int g  = lid >> 2;
    const int tg = (lid & 3) * 2;
#pragma unroll
    for (int mt = 0; mt < 4; mt++) {
        const int row = m0 + wm + mt * 16 + g;
#pragma unroll
        for (int nt = 0; nt < 4; nt++) {
            const int col = n0 + wn + nt * 8 + tg;
            const float b0 = bias[col], b1 = bias[col + 1];
            float v0 = acc[mt][nt][0] + b0;
            float v1 = acc[mt][nt][1] + b1;
            float v2 = acc[mt][nt][2] + b0;
            float v3 = acc[mt][nt][3] + b1;
            if (relu) {
                v0 = fmaxf(v0, 0.f); v1 = fmaxf(v1, 0.f);
                v2 = fmaxf(v2, 0.f); v3 = fmaxf(v3, 0.f);
            }
            if (mode == 0) {
                C[(long)row * N + col]           = v0;
                C[(long)row * N + col + 1]       = v1;
                C[(long)(row + 8) * N + col]     = v2;
                C[(long)(row + 8) * N + col + 1] = v3;
            } else {
                float h0 = __bfloat162float(__float2bfloat16(v0));
                float h1 = __bfloat162float(__float2bfloat16(v1));
                float h2 = __bfloat162float(__float2bfloat16(v2));
                float h3 = __bfloat162float(__float2bfloat16(v3));
                *(uint32_t*)(Chi + (long)row * N + col)       = pack_bf2(h0, h1);
                *(uint32_t*)(Chi + (long)(row + 8) * N + col) = pack_bf2(h2, h3);
                *(uint32_t*)(Clo + (long)row * N + col)       = pack_bf2(v0 - h0, v1 - h1);
                *(uint32_t*)(Clo + (long)(row + 8) * N + col) = pack_bf2(v2 - h2, v3 - h3);
            }
        }
    }
}

// ---------------------------------------------------------------------------
// HMMA attention, cp.async double-buffered K/V. Reads fused QKV (stride 3072).
// smem: QH 18432 | QL 18432 | stage{KH,KL,VH,VL} 36864 x2  = 110592 bytes
// ---------------------------------------------------------------------------
#define ATS 72           // padded stride (144 bytes/row)
#define AQ_H  0
#define AQ_L  18432
#define AKV0  36864
#define AKVST 36864
#define A_KH  0
#define A_KL  9216
#define A_VH  18432
#define A_VL  27648
#define ATTN_SMEM 110592

__global__ void __launch_bounds__(256, 2) attn_mma(
    const __nv_bfloat16* __restrict__ QKVhi, const __nv_bfloat16* __restrict__ QKVlo,
    __nv_bfloat16* __restrict__ Chi, __nv_bfloat16* __restrict__ Clo)
{
    extern __shared__ char smraw[];
    const uint32_t sb = smem_u32(smraw);

    const int tid = threadIdx.x;
    const int wid = tid >> 5, lid = tid & 31;
    const int bh = blockIdx.y;
    const int b = bh >> 4, h = bh & 15;
    const int q0 = blockIdx.x * 128;
    const long qbase = (long)(b * SEQ + q0) * QKVS + h * DHEAD;
    const long kbase = (long)(b * SEQ) * QKVS + DMODEL + h * DHEAD;
    const long vbase = kbase + DMODEL;

    // load Q tile (plain stores; covered by first barrier)
    for (int e = tid; e < 128 * 8; e += 256) {
        int row = e >> 3, cgp = (e & 7) * 8;
        const long gp = qbase + (long)row * QKVS + cgp;
        const uint32_t so = (uint32_t)(row * 144 + cgp * 2);
        *(uint4*)(smraw + AQ_H + so) = *(const uint4*)(QKVhi + gp);
        *(uint4*)(smraw + AQ_L + so) = *(const uint4*)(QKVlo + gp);
    }

    auto issueKV = [&](int kt, int s) {
        const uint32_t base = sb + AKV0 + s * AKVST;
#pragma unroll
        for (int e0 = 0; e0 < 2; e0++) {
            const int e = tid + e0 * 256;
            const int row = e >> 3, cgp = (e & 7) * 8;
            const long kR = kbase + (long)(kt * 64 + row) * QKVS + cgp;
            const long vR = vbase + (long)(kt * 64 + row) * QKVS + cgp;
            const uint32_t so = (uint32_t)(row * 144 + cgp * 2);
            CP16(base + A_KH + so, QKVhi + kR);
            CP16(base + A_KL + so, QKVlo + kR);
            CP16(base + A_VH + so, QKVhi + vR);
            CP16(base + A_VL + so, QKVlo + vR);
        }
    };

    const int mrow = wid * 16;
    const int lrow = lid & 15;
    const int lcol = (lid >> 4) * 8;
    const uint32_t qhB = sb + AQ_H, qlB = sb + AQ_L;

    float acc[8][4];
#pragma unroll
    for (int nt = 0; nt < 8; nt++)
#pragma unroll
        for (int f = 0; f < 4; f++) acc[nt][f] = 0.f;
    float den0 = 0.f, den1 = 0.f;

    issueKV(0, 0);
    CP_COMMIT();

    for (int kt = 0; kt < SEQ / 64; kt++) {
        if (kt + 1 < SEQ / 64) { issueKV(kt + 1, (kt + 1) & 1); CP_COMMIT(); CP_WAIT1(); }
        else                   { CP_WAIT0(); }
        __syncthreads();

        const uint32_t kvb = sb + AKV0 + (kt & 1) * AKVST;
        const uint32_t khB = kvb + A_KH, klB = kvb + A_KL;
        const uint32_t vhB = kvb + A_VH, vlB = kvb + A_VL;

        // S = Q K^T (3-term split)
        float S[8][4];
#pragma unroll
        for (int nt = 0; nt < 8; nt++)
#pragma unroll
            for (int f = 0; f < 4; f++) S[nt][f] = 0.f;

#pragma unroll
        for (int k16 = 0; k16 < 4; k16++) {
            uint32_t aH[4], aL[4];
            ldmat_x4(aH, qhB + ((mrow + lrow) * ATS + k16 * 16 + lcol) * 2);
            ldmat_x4(aL, qlB + ((mrow + lrow) * ATS + k16 * 16 + lcol) * 2);
#pragma unroll
            for (int np = 0; np < 4; np++) {
                uint32_t bH[4], bL[4];
                ldmat_x4(bH, khB + ((np * 16 + lrow) * ATS + k16 * 16 + lcol) * 2);
                ldmat_x4(bL, klB + ((np * 16 + lrow) * ATS + k16 * 16 + lcol) * 2);
                uint32_t f0H[2] = { bH[0], bH[2] }, f1H[2] = { bH[1], bH[3] };
                uint32_t f0L[2] = { bL[0], bL[2] }, f1L[2] = { bL[1], bL[3] };
                mma_bf16(S[2 * np],     aH, f0H);
                mma_bf16(S[2 * np],     aH, f0L);
                mma_bf16(S[2 * np],     aL, f0H);
                mma_bf16(S[2 * np + 1], aH, f1H);
                mma_bf16(S[2 * np + 1], aH, f1L);
                mma_bf16(S[2 * np + 1], aL, f1H);
            }
        }

        // p = exp(clip(S/8) - 10)
        uint32_t P[4][4];
#pragma unroll
        for (int nt = 0; nt < 8; nt++) {
            float e0 = __expf(fminf(fmaxf(S[nt][0] * 0.125f, -10.f), 10.f) - 10.f);
            float e1 = __expf(fminf(fmaxf(S[nt][1] * 0.125f, -10.f), 10.f) - 10.f);
            float e2 = __expf(fminf(fmaxf(S[nt][2] * 0.125f, -10.f), 10.f) - 10.f);
            float e3 = __expf(fminf(fmaxf(S[nt][3] * 0.125f, -10.f), 10.f) - 10.f);
            den0 += e0 + e1;
            den1 += e2 + e3;
            const int j = nt >> 1;
            if ((nt & 1) == 0) { P[j][0] = pack_bf2(e0, e1); P[j][1] = pack_bf2(e2, e3); }
            else               { P[j][2] = pack_bf2(e0, e1); P[j][3] = pack_bf2(e2, e3); }
        }

        // acc += P @ V (V split)
#pragma unroll
        for (int j = 0; j < 4; j++) {
#pragma unroll
            for (int np = 0; np < 4; np++) {
                uint32_t vH[4], vL[4];
                ldmat_x4t(vH, vhB + ((j * 16 + lrow) * ATS + np * 16 + lcol) * 2);
                ldmat_x4t(vL, vlB + ((j * 16 + lrow) * ATS + np * 16 + lcol) * 2);
                uint32_t fH0[2] = { vH[0], vH[1] }, fH1[2] = { vH[2], vH[3] };
                uint32_t fL0[2] = { vL[0], vL[1] }, fL1[2] = { vL[2], vL[3] };
                mma_bf16(acc[2 * np],     P[j], fH0);
                mma_bf16(acc[2 * np],     P[j], fL0);
                mma_bf16(acc[2 * np + 1], P[j], fH1);
                mma_bf16(acc[2 * np + 1], P[j], fL1);
            }
        }
        __syncthreads();
    }

    den0 += __shfl_xor_sync(~0u, den0, 1);
    den0 += __shfl_xor_sync(~0u, den0, 2);
    den1 += __shfl_xor_sync(~0u, den1, 1);
    den1 += __shfl_xor_sync(~0u, den1, 2);
    const float i0 = 1.f / den0, i1 = 1.f / den1;

    const int g  = lid >> 2;
    const int tg = (lid & 3) * 2;
    const long row0 = (long)(b * SEQ + q0 + mrow + g) * DMODEL + h * DHEAD;
    const long row1 = row0 + 8 * DMODEL;
#pragma unroll
    for (int nt = 0; nt < 8; nt++) {
        const int col = nt * 8 + tg;
        float v0 = acc[nt][0] * i0, v1 = acc[nt][1] * i0;
        float v2 = acc[nt][2] * i1, v3 = acc[nt][3] * i1;
        float h0 = __bfloat162float(__float2bfloat16(v0));
        float h1 = __bfloat162float(__float2bfloat16(v1));
        float h2 = __bfloat162float(__float2bfloat16(v2));
        float h3 = __bfloat162float(__float2bfloat16(v3));
        *(uint32_t*)(Chi + row0 + col) = pack_bf2(h0, h1);
        *(uint32_t*)(Chi + row1 + col) = pack_bf2(h2, h3);
        *(uint32_t*)(Clo + row0 + col) = pack_bf2(v0 - h0, v1 - h1);
        *(uint32_t*)(Clo + row1 + col) = pack_bf2(v2 - h2, v3 - h3);
    }
}

// ---------------------------------------------------------------------------
__global__ void __launch_bounds__(256) split_kernel(
    const float* __restrict__ A, __nv_bfloat16* __restrict__ hi,
    __nv_bfloat16* __restrict__ lo, long n4)
{
    long i = (long)blockIdx.x * blockDim.x + threadIdx.x;
    long stride = (long)gridDim.x * blockDim.x;
    for (; i < n4; i += stride) {
        float4 v = ((const float4*)A)[i];
        __nv_bfloat16 h0 = __float2bfloat16(v.x), h1 = __float2bfloat16(v.y);
        __nv_bfloat16 h2 = __float2bfloat16(v.z), h3 = __float2bfloat16(v.w);
        __nv_bfloat16 l0 = __float2bfloat16(v.x - __bfloat162float(h0));
        __nv_bfloat16 l1 = __float2bfloat16(v.y - __bfloat162float(h1));
        __nv_bfloat16 l2 = __float2bfloat16(v.z - __bfloat162float(h2));
        __nv_bfloat16 l3 = __float2bfloat16(v.w - __bfloat162float(h3));
        __nv_bfloat162 hp0(h0, h1), hp1(h2, h3), lp0(l0, l1), lp1(l2, l3);
        ((__nv_bfloat162*)hi)[i * 2]     = hp0;
        ((__nv_bfloat162*)hi)[i * 2 + 1] = hp1;
        ((__nv_bfloat162*)lo)[i * 2]     = lp0;
        ((__nv_bfloat162*)lo)[i * 2 + 1] = lp1;
    }
}

__global__ void __launch_bounds__(256) tsplit_kernel(
    const float* __restrict__ W, __nv_bfloat16* __restrict__ hi,
    __nv_bfloat16* __restrict__ lo, int K, int N)
{
    __shared__ float t[32][33];
    const int bn = blockIdx.x * 32, bk = blockIdx.y * 32;
    const int x = threadIdx.x & 31, y = threadIdx.x >> 5;
#pragma unroll
    for (int r = 0; r < 32; r += 8)
        t[y + r][x] = W[(long)(bk + y + r) * N + bn + x];
    __syncthreads();
#pragma unroll
    for (int r = 0; r < 32; r += 8) {
        float v = t[x][y + r];
        __nv_bfloat16 hh = __float2bfloat16(v);
        float rem = v - __bfloat162float(hh);
        long o = (long)(bn + y + r) * K + bk + x;
        hi[o] = hh;
        lo[o] = __float2bfloat16(rem);
    }
}

__global__ void __launch_bounds__(256) concat_bias_kernel(
    const float* __restrict__ bq, const float* __restrict__ bk,
    const float* __restrict__ bv, float* __restrict__ o)
{
    int i = blockIdx.x * 256 + threadIdx.x;
    if (i < DMODEL)           o[i] = bq[i];
    else if (i < 2 * DMODEL)  o[i] = bk[i - DMODEL];
    else if (i < 3 * DMODEL)  o[i] = bv[i - 2 * DMODEL];
}

// ---------------------------------------------------------------------------
__global__ __launch_bounds__(256) void add_ln_kernel(
    const float* __restrict__ A, const float* __restrict__ B,
    const float* __restrict__ gamma, const float* __restrict__ beta,
    float* __restrict__ out,
    __nv_bfloat16* __restrict__ ohi, __nv_bfloat16* __restrict__ olo,
    int do_split)
{
    __shared__ float red[2];
    const int row = blockIdx.x;
    const int tid = threadIdx.x;

    float4 a = ((const float4*)(A + (long)row * DMODEL))[tid];
    float4 b = ((const float4*)(B + (long)row * DMODEL))[tid];
    float4 v = {a.x + b.x, a.y + b.y, a.z + b.z, a.w + b.w};

    float s  = v.x + v.y + v.z + v.w;
    float sq = v.x * v.x + v.y * v.y + v.z * v.z + v.w * v.w;
#pragma unroll
    for (int o = 16; o; o >>= 1) {
        s  += __shfl_xor_sync(~0u, s,  o);
        sq += __shfl_xor_sync(~0u, sq, o);
    }
    const int w = tid >> 5, l = tid & 31;
    __shared__ float ws[8], wq[8];
    if (l == 0) { ws[w] = s; wq[w] = sq; }
    __syncthreads();
    if (tid < 32) {
        float s2 = (tid < 8) ? ws[tid] : 0.f;
        float q2 = (tid < 8) ? wq[tid] : 0.f;
#pragma unroll
        for (int o = 4; o; o >>= 1) {
            s2 += __shfl_xor_sync(~0u, s2, o);
            q2 += __shfl_xor_sync(~0u, q2, o);
        }
        if (tid == 0) { red[0] = s2; red[1] = q2; }
    }
    __syncthreads();
    float mean = red[0] * (1.f / DMODEL);
    float var  = red[1] * (1.f / DMODEL) - mean * mean;
    float rs   = rsqrtf(var + 1e-8f);

    float4 g  = ((const float4*)gamma)[tid];
    float4 be = ((const float4*)beta)[tid];
    float4 o4;
    o4.x = (v.x - mean) * rs * g.x + be.x;
    o4.y = (v.y - mean) * rs * g.y + be.y;
    o4.z = (v.z - mean) * rs * g.z + be.z;
    o4.w = (v.w - mean) * rs * g.w + be.w;
    ((float4*)(out + (long)row * DMODEL))[tid] = o4;

    if (do_split) {
        float h0 = __bfloat162float(__float2bfloat16(o4.x));
        float h1 = __bfloat162float(__float2bfloat16(o4.y));
        float h2 = __bfloat162float(__float2bfloat16(o4.z));
        float h3 = __bfloat162float(__float2bfloat16(o4.w));
        uint2 hv = { pack_bf2(h0, h1), pack_bf2(h2, h3) };
        uint2 lv = { pack_bf2(o4.x - h0, o4.y - h1), pack_bf2(o4.z - h2, o4.w - h3) };
        ((uint2*)(ohi + (long)row * DMODEL))[tid] = hv;
        ((uint2*)(olo + (long)row * DMODEL))[tid] = lv;
    }
}

// ---------------------------------------------------------------------------
extern "C" void kernel_launch(void* const* d_in, const int* in_sizes, int n_in,
                              void* d_out, int out_size)
{
    const float* x  = (const float*)d_in[0];
    const float* wq = (const float*)d_in[1];
    const float* bq = (const float*)d_in[2];
    const float* wk = (const float*)d_in[3];
    const float* bk = (const float*)d_in[4];
    const float* wv = (const float*)d_in[5];
    const float* bv = (const float*)d_in[6];
    const float* wo = (const float*)d_in[7];
    const float* bo = (const float*)d_in[8];
    const float* w1 = (const float*)d_in[9];
    const float* b1 = (const float*)d_in[10];
    const float* w2 = (const float*)d_in[11];
    const float* b2 = (const float*)d_in[12];
    const float* ga = (const float*)d_in[13];
    const float* be = (const float*)d_in[14];
    float* out = (float*)d_out;

    float *S1, *S2, *b3;
    __nv_bfloat16 *Xhi, *Xlo, *QKVhi, *QKVlo;
    __nv_bfloat16 *Chi, *Clo, *O1hi, *O1lo, *H1hi, *H1lo, *Whi, *Wlo;
    cudaGetSymbolAddress((void**)&S1,    g_S1);
    cudaGetSymbolAddress((void**)&S2,    g_S2);
    cudaGetSymbolAddress((void**)&b3,    g_b3);
    cudaGetSymbolAddress((void**)&Xhi,   g_Xhi);
    cudaGetSymbolAddress((void**)&Xlo,   g_Xlo);
    cudaGetSymbolAddress((void**)&QKVhi, g_QKVhi);
    cudaGetSymbolAddress((void**)&QKVlo, g_QKVlo);
    cudaGetSymbolAddress((void**)&Chi,   g_Chi);
    cudaGetSymbolAddress((void**)&Clo,   g_Clo);
    cudaGetSymbolAddress((void**)&O1hi,  g_O1hi);
    cudaGetSymbolAddress((void**)&O1lo,  g_O1lo);
    cudaGetSymbolAddress((void**)&H1hi,  g_H1hi);
    cudaGetSymbolAddress((void**)&H1lo,  g_H1lo);
    cudaGetSymbolAddress((void**)&Whi,   g_Wthi);
    cudaGetSymbolAddress((void**)&Wlo,   g_Wtlo);

    cudaFuncSetAttribute(gemm_mma, cudaFuncAttributeMaxDynamicSharedMemorySize, GEMM_SMEM);
    cudaFuncSetAttribute(attn_mma, cudaFuncAttributeMaxDynamicSharedMemorySize, ATTN_SMEM);

    dim3 blk(256);
    dim3 gQKV(QKVS / 128, M_TOK / 128);        // (24, 64)
    dim3 gProj(DMODEL / 128, M_TOK / 128);     // (8, 64)
    dim3 gF1(DFF / 128, M_TOK / 128);          // (32, 64)
    dim3 gT_d(DMODEL / 32, DMODEL / 32);
    dim3 gT_1(DFF / 32, DMODEL / 32);
    dim3 gT_2(DMODEL / 32, DFF / 32);

    // input split + weight prep
    split_kernel<<<512, blk>>>(x, Xhi, Xlo, (long)M_TOK * DMODEL / 4);
    tsplit_kernel<<<gT_d, blk>>>(wq, Whi,                    Wlo,                    DMODEL, DMODEL);
    tsplit_kernel<<<gT_d, blk>>>(wk, Whi + DMODEL * DMODEL,  Wlo + DMODEL * DMODEL,  DMODEL, DMODEL);
    tsplit_kernel<<<gT_d, blk>>>(wv, Whi + 2 * DMODEL * DMODEL, Wlo + 2 * DMODEL * DMODEL, DMODEL, DMODEL);
    concat_bias_kernel<<<(QKVS + 255) / 256, blk>>>(bq, bk, bv, b3);

    // fused QKV projection
    gemm_mma<<<gQKV, blk, GEMM_SMEM>>>(Xhi, Xlo, Whi, Wlo, b3, nullptr, QKVhi, QKVlo, QKVS, DMODEL, 0, 1);

    // attention
    dim3 gAttn(SEQ / 128, 4 * NHEAD);
    attn_mma<<<gAttn, blk, ATTN_SMEM>>>(QKVhi, QKVlo, Chi, Clo);

    // O projection
    tsplit_kernel<<<gT_d, blk>>>(wo, Whi, Wlo, DMODEL, DMODEL);
    gemm_mma<<<gProj, blk, GEMM_SMEM>>>(Chi, Clo, Whi, Wlo, bo, S1, nullptr, nullptr, DMODEL, DMODEL, 0, 0);

    // out1 = LN(x + attn_out)
    add_ln_kernel<<<M_TOK, blk>>>(x, S1, ga, be, S2, O1hi, O1lo, 1);

    // FFN1
    tsplit_kernel<<<gT_1, blk>>>(w1, Whi, Wlo, DMODEL, DFF);
    gemm_mma<<<gF1, blk, GEMM_SMEM>>>(O1hi, O1lo, Whi, Wlo, b1, nullptr, H1hi, H1lo, DFF, DMODEL, 1, 1);

    // FFN2
    tsplit_kernel<<<gT_2, blk>>>(w2, Whi, Wlo, DFF, DMODEL);
    gemm_mma<<<gProj, blk, GEMM_SMEM>>>(H1hi, H1lo, Whi, Wlo, b2, S1, nullptr, nullptr, DMODEL, DFF, 0, 0);

    // out = LN(out1 + ffn)
    add_ln_kernel<<<M_TOK, blk>>>(S2, S1, ga, be, out, nullptr, nullptr, 0);
}

// round 6
// speedup vs baseline: 2.5971x; 1.0425x over previous
#include <cuda_runtime.h>
#include <cuda_bf16.h>
#include <cstdint>

// ---------------------------------------------------------------------------
// EncoderLayer R5: R4 + split-K (blockIdx.z) for O-proj/FFN2 with partial sums
// folded into 3-input add+LN kernels.
// ---------------------------------------------------------------------------

#define M_TOK   8192
#define DMODEL  1024
#define DFF     4096
#define NHEAD   16
#define DHEAD   64
#define SEQ     2048
#define QKVS    3072      // fused QKV row stride

// fp32 scratch
__device__ float g_S1 [M_TOK * DMODEL];   // partial 0
__device__ float g_S2 [M_TOK * DMODEL];   // out1
__device__ float g_S3 [M_TOK * DMODEL];   // partial 1
__device__ float g_b3 [QKVS];
// bf16 split operands
__device__ __nv_bfloat16 g_Xhi [M_TOK * DMODEL];
__device__ __nv_bfloat16 g_Xlo [M_TOK * DMODEL];
__device__ __nv_bfloat16 g_QKVhi[M_TOK * QKVS];
__device__ __nv_bfloat16 g_QKVlo[M_TOK * QKVS];
__device__ __nv_bfloat16 g_Chi [M_TOK * DMODEL];
__device__ __nv_bfloat16 g_Clo [M_TOK * DMODEL];
__device__ __nv_bfloat16 g_O1hi[M_TOK * DMODEL];
__device__ __nv_bfloat16 g_O1lo[M_TOK * DMODEL];
__device__ __nv_bfloat16 g_H1hi[M_TOK * DFF];
__device__ __nv_bfloat16 g_H1lo[M_TOK * DFF];
__device__ __nv_bfloat16 g_Wthi[DFF * DMODEL];
__device__ __nv_bfloat16 g_Wtlo[DFF * DMODEL];

__device__ __forceinline__ uint32_t smem_u32(const void* p) {
    uint32_t a;
    asm("{ .reg .u64 t; cvta.to.shared.u64 t, %1; cvt.u32.u64 %0, t; }" : "=r"(a) : "l"(p));
    return a;
}
__device__ __forceinline__ void ldmat_x4(uint32_t* r, uint32_t addr) {
    asm volatile("ldmatrix.sync.aligned.m8n8.x4.shared.b16 {%0,%1,%2,%3}, [%4];"
                 : "=r"(r[0]), "=r"(r[1]), "=r"(r[2]), "=r"(r[3]) : "r"(addr));
}
__device__ __forceinline__ void ldmat_x4t(uint32_t* r, uint32_t addr) {
    asm volatile("ldmatrix.sync.aligned.m8n8.x4.trans.shared.b16 {%0,%1,%2,%3}, [%4];"
                 : "=r"(r[0]), "=r"(r[1]), "=r"(r[2]), "=r"(r[3]) : "r"(addr));
}
__device__ __forceinline__ void mma_bf16(float* d, const uint32_t* a, const uint32_t* b) {
    asm volatile("mma.sync.aligned.m16n8k16.row.col.f32.bf16.bf16.f32 "
                 "{%0,%1,%2,%3}, {%4,%5,%6,%7}, {%8,%9}, {%0,%1,%2,%3};"
                 : "+f"(d[0]), "+f"(d[1]), "+f"(d[2]), "+f"(d[3])
                 : "r"(a[0]), "r"(a[1]), "r"(a[2]), "r"(a[3]), "r"(b[0]), "r"(b[1]));
}
__device__ __forceinline__ uint32_t pack_bf2(float lo, float hi) {
    __nv_bfloat162 t = __floats2bfloat162_rn(lo, hi);
    return *reinterpret_cast<uint32_t*>(&t);
}
#define CP16(dst, src) asm volatile("cp.async.cg.shared.global [%0], [%1], 16;" :: "r"(dst), "l"(src))
#define CP_COMMIT()    asm volatile("cp.async.commit_group;" ::: "memory")
#define CP_WAIT1()     asm volatile("cp.async.wait_group 1;" ::: "memory")
#define CP_WAIT0()     asm volatile("cp.async.wait_group 0;" ::: "memory")

// ---------------------------------------------------------------------------
// Split-bf16 HMMA GEMM, cp.async double-buffered, optional split-K (gridDim.z).
// BM=BN=128, BK=32. 256 threads = 2x4 warps, 64x32 per warp.
// ---------------------------------------------------------------------------
#define SMS 40           // padded stride, elements (80 bytes/row)
#define GST 40960        // stage size bytes
#define OF_AHI 0
#define OF_ALO 10240
#define OF_BHI 20480
#define OF_BLO 30720
#define GEMM_SMEM (2 * GST)

__global__ void __launch_bounds__(256, 2) gemm_mma(
    const __nv_bfloat16* __restrict__ Ahi, const __nv_bfloat16* __restrict__ Alo,
    const __nv_bfloat16* __restrict__ Bhi, const __nv_bfloat16* __restrict__ Blo,
    const float* __restrict__ bias, float* __restrict__ C0, float* __restrict__ C1,
    __nv_bfloat16* __restrict__ Chi, __nv_bfloat16* __restrict__ Clo,
    int N, int K, int Ksl, int relu, int mode)
{
    extern __shared__ char smraw[];
    const uint32_t sb = smem_u32(smraw);

    const int tid = threadIdx.x;
    const int wid = tid >> 5, lid = tid & 31;
    const int m0 = blockIdx.y * 128, n0 = blockIdx.x * 128;
    const int z  = blockIdx.z;
    const long kzb = (long)z * Ksl;
    float* __restrict__ C = z ? C1 : C0;
    const int wm = (wid >> 2) * 64;
    const int wn = (wid & 3) * 32;

    const int r   = tid >> 2;
    const int cg  = (tid & 3) * 8;
    const uint32_t soff = (uint32_t)(r * 80 + cg * 2);

    float acc[4][4][4];
#pragma unroll
    for (int mt = 0; mt < 4; mt++)
#pragma unroll
        for (int nt = 0; nt < 4; nt++)
#pragma unroll
            for (int f = 0; f < 4; f++) acc[mt][nt][f] = 0.f;

    const int lrow = lid & 15;
    const int lcol = (lid >> 4) * 8;
    const int NC = Ksl >> 5;

    auto issue = [&](int i) {
        const int s = i & 1;
        const uint32_t base = sb + s * GST;
        const long k0 = kzb + (long)(i << 5);
        const long ra = (long)(m0 + r) * K + k0 + cg;
        const long rb = (long)(n0 + r) * K + k0 + cg;
        CP16(base + OF_AHI + soff,            Ahi + ra);
        CP16(base + OF_AHI + soff + 64 * 80,  Ahi + ra + 64 * (long)K);
        CP16(base + OF_ALO + soff,            Alo + ra);
        CP16(base + OF_ALO + soff + 64 * 80,  Alo + ra + 64 * (long)K);
        CP16(base + OF_BHI + soff,            Bhi + rb);
        CP16(base + OF_BHI + soff + 64 * 80,  Bhi + rb + 64 * (long)K);
        CP16(base + OF_BLO + soff,            Blo + rb);
        CP16(base + OF_BLO + soff + 64 * 80,  Blo + rb + 64 * (long)K);
    };

    issue(0);
    CP_COMMIT();

    for (int i = 0; i < NC; i++) {
        if (i + 1 < NC) { issue(i + 1); CP_COMMIT(); CP_WAIT1(); }
        else            { CP_WAIT0(); }
        __syncthreads();

        const uint32_t base = sb + (i & 1) * GST;
        const uint32_t aH = base + OF_AHI, aL = base + OF_ALO;
        const uint32_t bH = base + OF_BHI, bL = base + OF_BLO;

#pragma unroll
        for (int k16 = 0; k16 < 2; k16++) {
            const uint32_t ao = ((wm + lrow) * SMS + k16 * 16 + lcol) * 2;
            const uint32_t bo = ((wn + lrow) * SMS + k16 * 16 + lcol) * 2;
            uint32_t afH[4][4], afL[4][4];
#pragma unroll
            for (int mt = 0; mt < 4; mt++) {
                ldmat_x4(afH[mt], aH + ao + mt * 16 * SMS * 2);
                ldmat_x4(afL[mt], aL + ao + mt * 16 * SMS * 2);
            }
            uint32_t bfH[2][4], bfL[2][4];
#pragma unroll
            for (int np = 0; np < 2; np++) {
                ldmat_x4(bfH[np], bH + bo + np * 16 * SMS * 2);
                ldmat_x4(bfL[np], bL + bo + np * 16 * SMS * 2);
            }
#pragma unroll
            for (int mt = 0; mt < 4; mt++) {
#pragma unroll
                for (int nt = 0; nt < 4; nt++) {
                    uint32_t bH2[2] = { bfH[nt >> 1][nt & 1], bfH[nt >> 1][(nt & 1) + 2] };
                    uint32_t bL2[2] = { bfL[nt >> 1][nt & 1], bfL[nt >> 1][(nt & 1) + 2] };
                    mma_bf16(acc[mt][nt], afH[mt], bH2);
                    mma_bf16(acc[mt][nt], afH[mt], bL2);
                    mma_bf16(acc[mt][nt], afL[mt], bH2);
                }
            }
        }
        __syncthreads();
    }

    const int g  = lid >> 2;
    const int tg = (lid & 3) * 2;
#pragma unroll
    for (int mt = 0; mt < 4; mt++) {
        const int row = m0 + wm + mt * 16 + g;
#pragma unroll
        for (int nt = 0; nt < 4; nt++) {
            const int col = n0 + wn + nt * 8 + tg;
            const float b0 = z ? 0.f : bias[col];
            const float b1 = z ? 0.f : bias[col + 1];
            float v0 = acc[mt][nt][0] + b0;
            float v1 = acc[mt][nt][1] + b1;
            float v2 = acc[mt][nt][2] + b0;
            float v3 = acc[mt][nt][3] + b1;
            if (relu) {
                v0 = fmaxf(v0, 0.f); v1 = fmaxf(v1, 0.f);
                v2 = fmaxf(v2, 0.f); v3 = fmaxf(v3, 0.f);
            }
            if (mode == 0) {
                C[(long)row * N + col]           = v0;
                C[(long)row * N + col + 1]       = v1;
                C[(long)(row + 8) * N + col]     = v2;
                C[(long)(row + 8) * N + col + 1] = v3;
            } else {
                float h0 = __bfloat162float(__float2bfloat16(v0));
                float h1 = __bfloat162float(__float2bfloat16(v1));
                float h2 = __bfloat162float(__float2bfloat16(v2));
                float h3 = __bfloat162float(__float2bfloat16(v3));
                *(uint32_t*)(Chi + (long)row * N + col)       = pack_bf2(h0, h1);
                *(uint32_t*)(Chi + (long)(row + 8) * N + col) = pack_bf2(h2, h3);
                *(uint32_t*)(Clo + (long)row * N + col)       = pack_bf2(v0 - h0, v1 - h1);
                *(uint32_t*)(Clo + (long)(row + 8) * N + col) = pack_bf2(v2 - h2, v3 - h3);
            }
        }
    }
}

// ---------------------------------------------------------------------------
// HMMA attention, cp.async double-buffered K/V. Reads fused QKV (stride 3072).
// ---------------------------------------------------------------------------
#define ATS 72
#define AQ_H  0
#define AQ_L  18432
#define AKV0  36864
#define AKVST 36864
#define A_KH  0
#define A_KL  9216
#define A_VH  18432
#define A_VL  27648
#define ATTN_SMEM 110592

__global__ void __launch_bounds__(256, 2) attn_mma(
    const __nv_bfloat16* __restrict__ QKVhi, const __nv_bfloat16* __restrict__ QKVlo,
    __nv_bfloat16* __restrict__ Chi, __nv_bfloat16* __restrict__ Clo)
{
    extern __shared__ char smraw[];
    const uint32_t sb = smem_u32(smraw);

    const int tid = threadIdx.x;
    const int wid = tid >> 5, lid = tid & 31;
    const int bh = blockIdx.y;
    const int b = bh >> 4, h = bh & 15;
    const int q0 = blockIdx.x * 128;
    const long qbase = (long)(b * SEQ + q0) * QKVS + h * DHEAD;
    const long kbase = (long)(b * SEQ) * QKVS + DMODEL + h * DHEAD;
    const long vbase = kbase + DMODEL;

    for (int e = tid; e < 128 * 8; e += 256) {
        int row = e >> 3, cgp = (e & 7) * 8;
        const long gp = qbase + (long)row * QKVS + cgp;
        const uint32_t so = (uint32_t)(row * 144 + cgp * 2);
        *(uint4*)(smraw + AQ_H + so) = *(const uint4*)(QKVhi + gp);
        *(uint4*)(smraw + AQ_L + so) = *(const uint4*)(QKVlo + gp);
    }

    auto issueKV = [&](int kt, int s) {
        const uint32_t base = sb + AKV0 + s * AKVST;
#pragma unroll
        for (int e0 = 0; e0 < 2; e0++) {
            const int e = tid + e0 * 256;
            const int row = e >> 3, cgp = (e & 7) * 8;
            const long kR = kbase + (long)(kt * 64 + row) * QKVS + cgp;
            const long vR = vbase + (long)(kt * 64 + row) * QKVS + cgp;
            const uint32_t so = (uint32_t)(row * 144 + cgp * 2);
            CP16(base + A_KH + so, QKVhi + kR);
            CP16(base + A_KL + so, QKVlo + kR);
            CP16(base + A_VH + so, QKVhi + vR);
            CP16(base + A_VL + so, QKVlo + vR);
        }
    };

    const int mrow = wid * 16;
    const int lrow = lid & 15;
    const int lcol = (lid >> 4) * 8;
    const uint32_t qhB = sb + AQ_H, qlB = sb + AQ_L;

    float acc[8][4];
#pragma unroll
    for (int nt = 0; nt < 8; nt++)
#pragma unroll
        for (int f = 0; f < 4; f++) acc[nt][f] = 0.f;
    float den0 = 0.f, den1 = 0.f;

    issueKV(0, 0);
    CP_COMMIT();

    for (int kt = 0; kt < SEQ / 64; kt++) {
        if (kt + 1 < SEQ / 64) { issueKV(kt + 1, (kt + 1) & 1); CP_COMMIT(); CP_WAIT1(); }
        else                   { CP_WAIT0(); }
        __syncthreads();

        const uint32_t kvb = sb + AKV0 + (kt & 1) * AKVST;
        const uint32_t khB = kvb + A_KH, klB = kvb + A_KL;
        const uint32_t vhB = kvb + A_VH, vlB = kvb + A_VL;

        float S[8][4];
#pragma unroll
        for (int nt = 0; nt < 8; nt++)
#pragma unroll
            for (int f = 0; f < 4; f++) S[nt][f] = 0.f;

#pragma unroll
        for (int k16 = 0; k16 < 4; k16++) {
            uint32_t aH[4], aL[4];
            ldmat_x4(aH, qhB + ((mrow + lrow) * ATS + k16 * 16 + lcol) * 2);
            ldmat_x4(aL, qlB + ((mrow + lrow) * ATS + k16 * 16 + lcol) * 2);
#pragma unroll
            for (int np = 0; np < 4; np++) {
                uint32_t bH[4], bL[4];
                ldmat_x4(bH, khB + ((np * 16 + lrow) * ATS + k16 * 16 + lcol) * 2);
                ldmat_x4(bL, klB + ((np * 16 + lrow) * ATS + k16 * 16 + lcol) * 2);
                uint32_t f0H[2] = { bH[0], bH[2] }, f1H[2] = { bH[1], bH[3] };
                uint32_t f0L[2] = { bL[0], bL[2] }, f1L[2] = { bL[1], bL[3] };
                mma_bf16(S[2 * np],     aH, f0H);
                mma_bf16(S[2 * np],     aH, f0L);
                mma_bf16(S[2 * np],     aL, f0H);
                mma_bf16(S[2 * np + 1], aH, f1H);
                mma_bf16(S[2 * np + 1], aH, f1L);
                mma_bf16(S[2 * np + 1], aL, f1H);
            }
        }

        uint32_t P[4][4];
#pragma unroll
        for (int nt = 0; nt < 8; nt++) {
            float e0 = __expf(fminf(fmaxf(S[nt][0] * 0.125f, -10.f), 10.f) - 10.f);
            float e1 = __expf(fminf(fmaxf(S[nt][1] * 0.125f, -10.f), 10.f) - 10.f);
            float e2 = __expf(fminf(fmaxf(S[nt][2] * 0.125f, -10.f), 10.f) - 10.f);
            float e3 = __expf(fminf(fmaxf(S[nt][3] * 0.125f, -10.f), 10.f) - 10.f);
            den0 += e0 + e1;
            den1 += e2 + e3;
            const int j = nt >> 1;
            if ((nt & 1) == 0) { P[j][0] = pack_bf2(e0, e1); P[j][1] = pack_bf2(e2, e3); }
            else               { P[j][2] = pack_bf2(e0, e1); P[j][3] = pack_bf2(e2, e3); }
        }

#pragma unroll
        for (int j = 0; j < 4; j++) {
#pragma unroll
            for (int np = 0; np < 4; np++) {
                uint32_t vH[4], vL[4];
                ldmat_x4t(vH, vhB + ((j * 16 + lrow) * ATS + np * 16 + lcol) * 2);
                ldmat_x4t(vL, vlB + ((j * 16 + lrow) * ATS + np * 16 + lcol) * 2);
                uint32_t fH0[2] = { vH[0], vH[1] }, fH1[2] = { vH[2], vH[3] };
                uint32_t fL0[2] = { vL[0], vL[1] }, fL1[2] = { vL[2], vL[3] };
                mma_bf16(acc[2 * np],     P[j], fH0);
                mma_bf16(acc[2 * np],     P[j], fL0);
                mma_bf16(acc[2 * np + 1], P[j], fH1);
                mma_bf16(acc[2 * np + 1], P[j], fL1);
            }
        }
        __syncthreads();
    }

    den0 += __shfl_xor_sync(~0u, den0, 1);
    den0 += __shfl_xor_sync(~0u, den0, 2);
    den1 += __shfl_xor_sync(~0u, den1, 1);
    den1 += __shfl_xor_sync(~0u, den1, 2);
    const float i0 = 1.f / den0, i1 = 1.f / den1;

    const int g  = lid >> 2;
    const int tg = (lid & 3) * 2;
    const long row0 = (long)(b * SEQ + q0 + mrow + g) * DMODEL + h * DHEAD;
    const long row1 = row0 + 8 * DMODEL;
#pragma unroll
    for (int nt = 0; nt < 8; nt++) {
        const int col = nt * 8 + tg;
        float v0 = acc[nt][0] * i0, v1 = acc[nt][1] * i0;
        float v2 = acc[nt][2] * i1, v3 = acc[nt][3] * i1;
        float h0 = __bfloat162float(__float2bfloat16(v0));
        float h1 = __bfloat162float(__float2bfloat16(v1));
        float h2 = __bfloat162float(__float2bfloat16(v2));
        float h3 = __bfloat162float(__float2bfloat16(v3));
        *(uint32_t*)(Chi + row0 + col) = pack_bf2(h0, h1);
        *(uint32_t*)(Chi + row1 + col) = pack_bf2(h2, h3);
        *(uint32_t*)(Clo + row0 + col) = pack_bf2(v0 - h0, v1 - h1);
        *(uint32_t*)(Clo + row1 + col) = pack_bf2(v2 - h2, v3 - h3);
    }
}

// ---------------------------------------------------------------------------
__global__ void __launch_bounds__(256) split_kernel(
    const float* __restrict__ A, __nv_bfloat16* __restrict__ hi,
    __nv_bfloat16* __restrict__ lo, long n4)
{
    long i = (long)blockIdx.x * blockDim.x + threadIdx.x;
    long stride = (long)gridDim.x * blockDim.x;
    for (; i < n4; i += stride) {
        float4 v = ((const float4*)A)[i];
        __nv_bfloat16 h0 = __float2bfloat16(v.x), h1 = __float2bfloat16(v.y);
        __nv_bfloat16 h2 = __float2bfloat16(v.z), h3 = __float2bfloat16(v.w);
        __nv_bfloat16 l0 = __float2bfloat16(v.x - __bfloat162float(h0));
        __nv_bfloat16 l1 = __float2bfloat16(v.y - __bfloat162float(h1));
        __nv_bfloat16 l2 = __float2bfloat16(v.z - __bfloat162float(h2));
        __nv_bfloat16 l3 = __float2bfloat16(v.w - __bfloat162float(h3));
        __nv_bfloat162 hp0(h0, h1), hp1(h2, h3), lp0(l0, l1), lp1(l2, l3);
        ((__nv_bfloat162*)hi)[i * 2]     = hp0;
        ((__nv_bfloat162*)hi)[i * 2 + 1] = hp1;
        ((__nv_bfloat162*)lo)[i * 2]     = lp0;
        ((__nv_bfloat162*)lo)[i * 2 + 1] = lp1;
    }
}

__global__ void __launch_bounds__(256) tsplit_kernel(
    const float* __restrict__ W, __nv_bfloat16* __restrict__ hi,
    __nv_bfloat16* __restrict__ lo, int K, int N)
{
    __shared__ float t[32][33];
    const int bn = blockIdx.x * 32, bk = blockIdx.y * 32;
    const int x = threadIdx.x & 31, y = threadIdx.x >> 5;
#pragma unroll
    for (int r = 0; r < 32; r += 8)
        t[y + r][x] = W[(long)(bk + y + r) * N + bn + x];
    __syncthreads();
#pragma unroll
    for (int r = 0; r < 32; r += 8) {
        float v = t[x][y + r];
        __nv_bfloat16 hh = __float2bfloat16(v);
        float rem = v - __bfloat162float(hh);
        long o = (long)(bn + y + r) * K + bk + x;
        hi[o] = hh;
        lo[o] = __float2bfloat16(rem);
    }
}

__global__ void __launch_bounds__(256) concat_bias_kernel(
    const float* __restrict__ bq, const float* __restrict__ bk,
    const float* __restrict__ bv, float* __restrict__ o)
{
    int i = blockIdx.x * 256 + threadIdx.x;
    if (i < DMODEL)           o[i] = bq[i];
    else if (i < 2 * DMODEL)  o[i] = bk[i - DMODEL];
    else if (i < 3 * DMODEL)  o[i] = bv[i - 2 * DMODEL];
}

// ---------------------------------------------------------------------------
// out = LayerNorm(A + B [+ B2]) * gamma + beta ; optional split bf16 output
// ---------------------------------------------------------------------------
__global__ __launch_bounds__(256) void add_ln_kernel(
    const float* __restrict__ A, const float* __restrict__ B,
    const float* __restrict__ B2,
    const float* __restrict__ gamma, const float* __restrict__ beta,
    float* __restrict__ out,
    __nv_bfloat16* __restrict__ ohi, __nv_bfloat16* __restrict__ olo,
    int do_split)
{
    __shared__ float red[2];
    const int row = blockIdx.x;
    const int tid = threadIdx.x;

    float4 a = ((const float4*)(A + (long)row * DMODEL))[tid];
    float4 b = ((const float4*)(B + (long)row * DMODEL))[tid];
    float4 v = {a.x + b.x, a.y + b.y, a.z + b.z, a.w + b.w};
    if (B2) {
        float4 c = ((const float4*)(B2 + (long)row * DMODEL))[tid];
        v.x += c.x; v.y += c.y; v.z += c.z; v.w += c.w;
    }

    float s  = v.x + v.y + v.z + v.w;
    float sq = v.x * v.x + v.y * v.y + v.z * v.z + v.w * v.w;
#pragma unroll
    for (int o = 16; o; o >>= 1) {
        s  += __shfl_xor_sync(~0u, s,  o);
        sq += __shfl_xor_sync(~0u, sq, o);
    }
    const int w = tid >> 5, l = tid & 31;
    __shared__ float ws[8], wq[8];
    if (l == 0) { ws[w] = s; wq[w] = sq; }
    __syncthreads();
    if (tid < 32) {
        float s2 = (tid < 8) ? ws[tid] : 0.f;
        float q2 = (tid < 8) ? wq[tid] : 0.f;
#pragma unroll
        for (int o = 4; o; o >>= 1) {
            s2 += __shfl_xor_sync(~0u, s2, o);
            q2 += __shfl_xor_sync(~0u, q2, o);
        }
        if (tid == 0) { red[0] = s2; red[1] = q2; }
    }
    __syncthreads();
    float mean = red[0] * (1.f / DMODEL);
    float var  = red[1] * (1.f / DMODEL) - mean * mean;
    float rs   = rsqrtf(var + 1e-8f);

    float4 g  = ((const float4*)gamma)[tid];
    float4 be = ((const float4*)beta)[tid];
    float4 o4;
    o4.x = (v.x - mean) * rs * g.x + be.x;
    o4.y = (v.y - mean) * rs * g.y + be.y;
    o4.z = (v.z - mean) * rs * g.z + be.z;
    o4.w = (v.w - mean) * rs * g.w + be.w;
    ((float4*)(out + (long)row * DMODEL))[tid] = o4;

    if (do_split) {
        float h0 = __bfloat162float(__float2bfloat16(o4.x));
        float h1 = __bfloat162float(__float2bfloat16(o4.y));
        float h2 = __bfloat162float(__float2bfloat16(o4.z));
        float h3 = __bfloat162float(__float2bfloat16(o4.w));
        uint2 hv = { pack_bf2(h0, h1), pack_bf2(h2, h3) };
        uint2 lv = { pack_bf2(o4.x - h0, o4.y - h1), pack_bf2(o4.z - h2, o4.w - h3) };
        ((uint2*)(ohi + (long)row * DMODEL))[tid] = hv;
        ((uint2*)(olo + (long)row * DMODEL))[tid] = lv;
    }
}

// ---------------------------------------------------------------------------
extern "C" void kernel_launch(void* const* d_in, const int* in_sizes, int n_in,
                              void* d_out, int out_size)
{
    const float* x  = (const float*)d_in[0];
    const float* wq = (const float*)d_in[1];
    const float* bq = (const float*)d_in[2];
    const float* wk = (const float*)d_in[3];
    const float* bk = (const float*)d_in[4];
    const float* wv = (const float*)d_in[5];
    const float* bv = (const float*)d_in[6];
    const float* wo = (const float*)d_in[7];
    const float* bo = (const float*)d_in[8];
    const float* w1 = (const float*)d_in[9];
    const float* b1 = (const float*)d_in[10];
    const float* w2 = (const float*)d_in[11];
    const float* b2 = (const float*)d_in[12];
    const float* ga = (const float*)d_in[13];
    const float* be = (const float*)d_in[14];
    float* out = (float*)d_out;

    float *S1, *S2, *S3, *b3;
    __nv_bfloat16 *Xhi, *Xlo, *QKVhi, *QKVlo;
    __nv_bfloat16 *Chi, *Clo, *O1hi, *O1lo, *H1hi, *H1lo, *Whi, *Wlo;
    cudaGetSymbolAddress((void**)&S1,    g_S1);
    cudaGetSymbolAddress((void**)&S2,    g_S2);
    cudaGetSymbolAddress((void**)&S3,    g_S3);
    cudaGetSymbolAddress((void**)&b3,    g_b3);
    cudaGetSymbolAddress((void**)&Xhi,   g_Xhi);
    cudaGetSymbolAddress((void**)&Xlo,   g_Xlo);
    cudaGetSymbolAddress((void**)&QKVhi, g_QKVhi);
    cudaGetSymbolAddress((void**)&QKVlo, g_QKVlo);
    cudaGetSymbolAddress((void**)&Chi,   g_Chi);
    cudaGetSymbolAddress((void**)&Clo,   g_Clo);
    cudaGetSymbolAddress((void**)&O1hi,  g_O1hi);
    cudaGetSymbolAddress((void**)&O1lo,  g_O1lo);
    cudaGetSymbolAddress((void**)&H1hi,  g_H1hi);
    cudaGetSymbolAddress((void**)&H1lo,  g_H1lo);
    cudaGetSymbolAddress((void**)&Whi,   g_Wthi);
    cudaGetSymbolAddress((void**)&Wlo,   g_Wtlo);

    cudaFuncSetAttribute(gemm_mma, cudaFuncAttributeMaxDynamicSharedMemorySize, GEMM_SMEM);
    cudaFuncSetAttribute(attn_mma, cudaFuncAttributeMaxDynamicSharedMemorySize, ATTN_SMEM);

    dim3 blk(256);
    dim3 gQKV(QKVS / 128, M_TOK / 128, 1);     // (24, 64)
    dim3 gProjZ(DMODEL / 128, M_TOK / 128, 2); // (8, 64, 2) split-K
    dim3 gF1(DFF / 128, M_TOK / 128, 1);       // (32, 64)
    dim3 gT_d(DMODEL / 32, DMODEL / 32);
    dim3 gT_1(DFF / 32, DMODEL / 32);
    dim3 gT_2(DMODEL / 32, DFF / 32);

    // input split + weight prep
    split_kernel<<<512, blk>>>(x, Xhi, Xlo, (long)M_TOK * DMODEL / 4);
    tsplit_kernel<<<gT_d, blk>>>(wq, Whi,                       Wlo,                       DMODEL, DMODEL);
    tsplit_kernel<<<gT_d, blk>>>(wk, Whi + DMODEL * DMODEL,     Wlo + DMODEL * DMODEL,     DMODEL, DMODEL);
    tsplit_kernel<<<gT_d, blk>>>(wv, Whi + 2 * DMODEL * DMODEL, Wlo + 2 * DMODEL * DMODEL, DMODEL, DMODEL);
    concat_bias_kernel<<<(QKVS + 255) / 256, blk>>>(bq, bk, bv, b3);

    // fused QKV projection
    gemm_mma<<<gQKV, blk, GEMM_SMEM>>>(Xhi, Xlo, Whi, Wlo, b3, nullptr, nullptr,
                                       QKVhi, QKVlo, QKVS, DMODEL, DMODEL, 0, 1);

    // attention
    dim3 gAttn(SEQ / 128, 4 * NHEAD);
    attn_mma<<<gAttn, blk, ATTN_SMEM>>>(QKVhi, QKVlo, Chi, Clo);

    // O projection, split-K=2 -> partials S1, S3
    tsplit_kernel<<<gT_d, blk>>>(wo, Whi, Wlo, DMODEL, DMODEL);
    gemm_mma<<<gProjZ, blk, GEMM_SMEM>>>(Chi, Clo, Whi, Wlo, bo, S1, S3,
                                         nullptr, nullptr, DMODEL, DMODEL, DMODEL / 2, 0, 0);

    // out1 = LN(x + p0 + p1)
    add_ln_kernel<<<M_TOK, blk>>>(x, S1, S3, ga, be, S2, O1hi, O1lo, 1);

    // FFN1
    tsplit_kernel<<<gT_1, blk>>>(w1, Whi, Wlo, DMODEL, DFF);
    gemm_mma<<<gF1, blk, GEMM_SMEM>>>(O1hi, O1lo, Whi, Wlo, b1, nullptr, nullptr,
                                      H1hi, H1lo, DFF, DMODEL, DMODEL, 1, 1);

    // FFN2, split-K=2 -> partials S1, S3
    tsplit_kernel<<<gT_2, blk>>>(w2, Whi, Wlo, DFF, DMODEL);
    gemm_mma<<<gProjZ, blk, GEMM_SMEM>>>(H1hi, H1lo, Whi, Wlo, b2, S1, S3,
                                         nullptr, nullptr, DMODEL, DFF, DFF / 2, 0, 0);

    // out = LN(out1 + p0 + p1)
    add_ln_kernel<<<M_TOK, blk>>>(S2, S1, S3, ga, be, out, nullptr, nullptr, 0);
}

// round 7
// speedup vs baseline: 2.7685x; 1.0660x over previous
#include <cuda_runtime.h>
#include <cuda_bf16.h>
#include <cstdint>

// ---------------------------------------------------------------------------
// EncoderLayer R6: R5 + attention with plain-bf16 K/V (Q still split) +
// single batched weight-split kernel with dedicated weight buffers.
// ---------------------------------------------------------------------------

#define M_TOK   8192
#define DMODEL  1024
#define DFF     4096
#define NHEAD   16
#define DHEAD   64
#define SEQ     2048
#define QKVS    3072

// fp32 scratch
__device__ float g_S1 [M_TOK * DMODEL];
__device__ float g_S2 [M_TOK * DMODEL];
__device__ float g_S3 [M_TOK * DMODEL];
__device__ float g_b3 [QKVS];
// bf16 split operands
__device__ __nv_bfloat16 g_Xhi [M_TOK * DMODEL];
__device__ __nv_bfloat16 g_Xlo [M_TOK * DMODEL];
__device__ __nv_bfloat16 g_QKVhi[M_TOK * QKVS];
__device__ __nv_bfloat16 g_QKVlo[M_TOK * QKVS];
__device__ __nv_bfloat16 g_Chi [M_TOK * DMODEL];
__device__ __nv_bfloat16 g_Clo [M_TOK * DMODEL];
__device__ __nv_bfloat16 g_O1hi[M_TOK * DMODEL];
__device__ __nv_bfloat16 g_O1lo[M_TOK * DMODEL];
__device__ __nv_bfloat16 g_H1hi[M_TOK * DFF];
__device__ __nv_bfloat16 g_H1lo[M_TOK * DFF];
// dedicated transposed split weights
__device__ __nv_bfloat16 g_WQKVh[QKVS * DMODEL];
__device__ __nv_bfloat16 g_WQKVl[QKVS * DMODEL];
__device__ __nv_bfloat16 g_WOh [DMODEL * DMODEL];
__device__ __nv_bfloat16 g_WOl [DMODEL * DMODEL];
__device__ __nv_bfloat16 g_W1h [DFF * DMODEL];
__device__ __nv_bfloat16 g_W1l [DFF * DMODEL];
__device__ __nv_bfloat16 g_W2h [DMODEL * DFF];
__device__ __nv_bfloat16 g_W2l [DMODEL * DFF];

__device__ __forceinline__ uint32_t smem_u32(const void* p) {
    uint32_t a;
    asm("{ .reg .u64 t; cvta.to.shared.u64 t, %1; cvt.u32.u64 %0, t; }" : "=r"(a) : "l"(p));
    return a;
}
__device__ __forceinline__ void ldmat_x4(uint32_t* r, uint32_t addr) {
    asm volatile("ldmatrix.sync.aligned.m8n8.x4.shared.b16 {%0,%1,%2,%3}, [%4];"
                 : "=r"(r[0]), "=r"(r[1]), "=r"(r[2]), "=r"(r[3]) : "r"(addr));
}
__device__ __forceinline__ void ldmat_x4t(uint32_t* r, uint32_t addr) {
    asm volatile("ldmatrix.sync.aligned.m8n8.x4.trans.shared.b16 {%0,%1,%2,%3}, [%4];"
                 : "=r"(r[0]), "=r"(r[1]), "=r"(r[2]), "=r"(r[3]) : "r"(addr));
}
__device__ __forceinline__ void mma_bf16(float* d, const uint32_t* a, const uint32_t* b) {
    asm volatile("mma.sync.aligned.m16n8k16.row.col.f32.bf16.bf16.f32 "
                 "{%0,%1,%2,%3}, {%4,%5,%6,%7}, {%8,%9}, {%0,%1,%2,%3};"
                 : "+f"(d[0]), "+f"(d[1]), "+f"(d[2]), "+f"(d[3])
                 : "r"(a[0]), "r"(a[1]), "r"(a[2]), "r"(a[3]), "r"(b[0]), "r"(b[1]));
}
__device__ __forceinline__ uint32_t pack_bf2(float lo, float hi) {
    __nv_bfloat162 t = __floats2bfloat162_rn(lo, hi);
    return *reinterpret_cast<uint32_t*>(&t);
}
#define CP16(dst, src) asm volatile("cp.async.cg.shared.global [%0], [%1], 16;" :: "r"(dst), "l"(src))
#define CP_COMMIT()    asm volatile("cp.async.commit_group;" ::: "memory")
#define CP_WAIT1()     asm volatile("cp.async.wait_group 1;" ::: "memory")
#define CP_WAIT0()     asm volatile("cp.async.wait_group 0;" ::: "memory")

// ---------------------------------------------------------------------------
// Split-bf16 HMMA GEMM, cp.async double-buffered, optional split-K.
// ---------------------------------------------------------------------------
#define SMS 40
#define GST 40960
#define OF_AHI 0
#define OF_ALO 10240
#define OF_BHI 20480
#define OF_BLO 30720
#define GEMM_SMEM (2 * GST)

__global__ void __launch_bounds__(256, 2) gemm_mma(
    const __nv_bfloat16* __restrict__ Ahi, const __nv_bfloat16* __restrict__ Alo,
    const __nv_bfloat16* __restrict__ Bhi, const __nv_bfloat16* __restrict__ Blo,
    const float* __restrict__ bias, float* __restrict__ C0, float* __restrict__ C1,
    __nv_bfloat16* __restrict__ Chi, __nv_bfloat16* __restrict__ Clo,
    int N, int K, int Ksl, int relu, int mode)
{
    extern __shared__ char smraw[];
    const uint32_t sb = smem_u32(smraw);

    const int tid = threadIdx.x;
    const int wid = tid >> 5, lid = tid & 31;
    const int m0 = blockIdx.y * 128, n0 = blockIdx.x * 128;
    const int z  = blockIdx.z;
    const long kzb = (long)z * Ksl;
    float* __restrict__ C = z ? C1 : C0;
    const int wm = (wid >> 2) * 64;
    const int wn = (wid & 3) * 32;

    const int r   = tid >> 2;
    const int cg  = (tid & 3) * 8;
    const uint32_t soff = (uint32_t)(r * 80 + cg * 2);

    float acc[4][4][4];
#pragma unroll
    for (int mt = 0; mt < 4; mt++)
#pragma unroll
        for (int nt = 0; nt < 4; nt++)
#pragma unroll
            for (int f = 0; f < 4; f++) acc[mt][nt][f] = 0.f;

    const int lrow = lid & 15;
    const int lcol = (lid >> 4) * 8;
    const int NC = Ksl >> 5;

    auto issue = [&](int i) {
        const int s = i & 1;
        const uint32_t base = sb + s * GST;
        const long k0 = kzb + (long)(i << 5);
        const long ra = (long)(m0 + r) * K + k0 + cg;
        const long rb = (long)(n0 + r) * K + k0 + cg;
        CP16(base + OF_AHI + soff,            Ahi + ra);
        CP16(base + OF_AHI + soff + 64 * 80,  Ahi + ra + 64 * (long)K);
        CP16(base + OF_ALO + soff,            Alo + ra);
        CP16(base + OF_ALO + soff + 64 * 80,  Alo + ra + 64 * (long)K);
        CP16(base + OF_BHI + soff,            Bhi + rb);
        CP16(base + OF_BHI + soff + 64 * 80,  Bhi + rb + 64 * (long)K);
        CP16(base + OF_BLO + soff,            Blo + rb);
        CP16(base + OF_BLO + soff + 64 * 80,  Blo + rb + 64 * (long)K);
    };

    issue(0);
    CP_COMMIT();

    for (int i = 0; i < NC; i++) {
        if (i + 1 < NC) { issue(i + 1); CP_COMMIT(); CP_WAIT1(); }
        else            { CP_WAIT0(); }
        __syncthreads();

        const uint32_t base = sb + (i & 1) * GST;
        const uint32_t aH = base + OF_AHI, aL = base + OF_ALO;
        const uint32_t bH = base + OF_BHI, bL = base + OF_BLO;

#pragma unroll
        for (int k16 = 0; k16 < 2; k16++) {
            const uint32_t ao = ((wm + lrow) * SMS + k16 * 16 + lcol) * 2;
            const uint32_t bo = ((wn + lrow) * SMS + k16 * 16 + lcol) * 2;
            uint32_t afH[4][4], afL[4][4];
#pragma unroll
            for (int mt = 0; mt < 4; mt++) {
                ldmat_x4(afH[mt], aH + ao + mt * 16 * SMS * 2);
                ldmat_x4(afL[mt], aL + ao + mt * 16 * SMS * 2);
            }
            uint32_t bfH[2][4], bfL[2][4];
#pragma unroll
            for (int np = 0; np < 2; np++) {
                ldmat_x4(bfH[np], bH + bo + np * 16 * SMS * 2);
                ldmat_x4(bfL[np], bL + bo + np * 16 * SMS * 2);
            }
#pragma unroll
            for (int mt = 0; mt < 4; mt++) {
#pragma unroll
                for (int nt = 0; nt < 4; nt++) {
                    uint32_t bH2[2] = { bfH[nt >> 1][nt & 1], bfH[nt >> 1][(nt & 1) + 2] };
                    uint32_t bL2[2] = { bfL[nt >> 1][nt & 1], bfL[nt >> 1][(nt & 1) + 2] };
                    mma_bf16(acc[mt][nt], afH[mt], bH2);
                    mma_bf16(acc[mt][nt], afH[mt], bL2);
                    mma_bf16(acc[mt][nt], afL[mt], bH2);
                }
            }
        }
        __syncthreads();
    }

    const int g  = lid >> 2;
    const int tg = (lid & 3) * 2;
#pragma unroll
    for (int mt = 0; mt < 4; mt++) {
        const int row = m0 + wm + mt * 16 + g;
#pragma unroll
        for (int nt = 0; nt < 4; nt++) {
            const int col = n0 + wn + nt * 8 + tg;
            const float b0 = z ? 0.f : bias[col];
            const float b1 = z ? 0.f : bias[col + 1];
            float v0 = acc[mt][nt][0] + b0;
            float v1 = acc[mt][nt][1] + b1;
            float v2 = acc[mt][nt][2] + b0;
            float v3 = acc[mt][nt][3] + b1;
            if (relu) {
                v0 = fmaxf(v0, 0.f); v1 = fmaxf(v1, 0.f);
                v2 = fmaxf(v2, 0.f); v3 = fmaxf(v3, 0.f);
            }
            if (mode == 0) {
                C[(long)row * N + col]           = v0;
                C[(long)row * N + col + 1]       = v1;
                C[(long)(row + 8) * N + col]     = v2;
                C[(long)(row + 8) * N + col + 1] = v3;
            } else {
                float h0 = __bfloat162float(__float2bfloat16(v0));
                float h1 = __bfloat162float(__float2bfloat16(v1));
                float h2 = __bfloat162float(__float2bfloat16(v2));
                float h3 = __bfloat162float(__float2bfloat16(v3));
                *(uint32_t*)(Chi + (long)row * N + col)       = pack_bf2(h0, h1);
                *(uint32_t*)(Chi + (long)(row + 8) * N + col) = pack_bf2(h2, h3);
                *(uint32_t*)(Clo + (long)row * N + col)       = pack_bf2(v0 - h0, v1 - h1);
                *(uint32_t*)(Clo + (long)(row + 8) * N + col) = pack_bf2(v2 - h2, v3 - h3);
            }
        }
    }
}

// ---------------------------------------------------------------------------
// HMMA attention: Q split bf16 (hi+lo), K/V plain bf16 (hi only).
// smem: QH 18432 | QL 18432 | stage{KH,VH} 18432 x2 = 73728 bytes
// ---------------------------------------------------------------------------
#define ATS 72
#define AQ_H  0
#define AQ_L  18432
#define AKV0  36864
#define AKVST 18432
#define A_KH  0
#define A_VH  9216
#define ATTN_SMEM 73728

__global__ void __launch_bounds__(256, 2) attn_mma(
    const __nv_bfloat16* __restrict__ QKVhi, const __nv_bfloat16* __restrict__ QKVlo,
    __nv_bfloat16* __restrict__ Chi, __nv_bfloat16* __restrict__ Clo)
{
    extern __shared__ char smraw[];
    const uint32_t sb = smem_u32(smraw);

    const int tid = threadIdx.x;
    const int wid = tid >> 5, lid = tid & 31;
    const int bh = blockIdx.y;
    const int b = bh >> 4, h = bh & 15;
    const int q0 = blockIdx.x * 128;
    const long qbase = (long)(b * SEQ + q0) * QKVS + h * DHEAD;
    const long kbase = (long)(b * SEQ) * QKVS + DMODEL + h * DHEAD;
    const long vbase = kbase + DMODEL;

    for (int e = tid; e < 128 * 8; e += 256) {
        int row = e >> 3, cgp = (e & 7) * 8;
        const long gp = qbase + (long)row * QKVS + cgp;
        const uint32_t so = (uint32_t)(row * 144 + cgp * 2);
        *(uint4*)(smraw + AQ_H + so) = *(const uint4*)(QKVhi + gp);
        *(uint4*)(smraw + AQ_L + so) = *(const uint4*)(QKVlo + gp);
    }

    auto issueKV = [&](int kt, int s) {
        const uint32_t base = sb + AKV0 + s * AKVST;
#pragma unroll
        for (int e0 = 0; e0 < 2; e0++) {
            const int e = tid + e0 * 256;
            const int row = e >> 3, cgp = (e & 7) * 8;
            const long kR = kbase + (long)(kt * 64 + row) * QKVS + cgp;
            const long vR = vbase + (long)(kt * 64 + row) * QKVS + cgp;
            const uint32_t so = (uint32_t)(row * 144 + cgp * 2);
            CP16(base + A_KH + so, QKVhi + kR);
            CP16(base + A_VH + so, QKVhi + vR);
        }
    };

    const int mrow = wid * 16;
    const int lrow = lid & 15;
    const int lcol = (lid >> 4) * 8;
    const uint32_t qhB = sb + AQ_H, qlB = sb + AQ_L;

    float acc[8][4];
#pragma unroll
    for (int nt = 0; nt < 8; nt++)
#pragma unroll
        for (int f = 0; f < 4; f++) acc[nt][f] = 0.f;
    float den0 = 0.f, den1 = 0.f;

    issueKV(0, 0);
    CP_COMMIT();

    for (int kt = 0; kt < SEQ / 64; kt++) {
        if (kt + 1 < SEQ / 64) { issueKV(kt + 1, (kt + 1) & 1); CP_COMMIT(); CP_WAIT1(); }
        else                   { CP_WAIT0(); }
        __syncthreads();

        const uint32_t kvb = sb + AKV0 + (kt & 1) * AKVST;
        const uint32_t khB = kvb + A_KH, vhB = kvb + A_VH;

        // S = (Qhi + Qlo) K^T
        float S[8][4];
#pragma unroll
        for (int nt = 0; nt < 8; nt++)
#pragma unroll
            for (int f = 0; f < 4; f++) S[nt][f] = 0.f;

#pragma unroll
        for (int k16 = 0; k16 < 4; k16++) {
            uint32_t aH[4], aL[4];
            ldmat_x4(aH, qhB + ((mrow + lrow) * ATS + k16 * 16 + lcol) * 2);
            ldmat_x4(aL, qlB + ((mrow + lrow) * ATS + k16 * 16 + lcol) * 2);
#pragma unroll
            for (int np = 0; np < 4; np++) {
                uint32_t bH[4];
                ldmat_x4(bH, khB + ((np * 16 + lrow) * ATS + k16 * 16 + lcol) * 2);
                uint32_t f0H[2] = { bH[0], bH[2] }, f1H[2] = { bH[1], bH[3] };
                mma_bf16(S[2 * np],     aH, f0H);
                mma_bf16(S[2 * np],     aL, f0H);
                mma_bf16(S[2 * np + 1], aH, f1H);
                mma_bf16(S[2 * np + 1], aL, f1H);
            }
        }

        uint32_t P[4][4];
#pragma unroll
        for (int nt = 0; nt < 8; nt++) {
            float e0 = __expf(fminf(fmaxf(S[nt][0] * 0.125f, -10.f), 10.f) - 10.f);
            float e1 = __expf(fminf(fmaxf(S[nt][1] * 0.125f, -10.f), 10.f) - 10.f);
            float e2 = __expf(fminf(fmaxf(S[nt][2] * 0.125f, -10.f), 10.f) - 10.f);
            float e3 = __expf(fminf(fmaxf(S[nt][3] * 0.125f, -10.f), 10.f) - 10.f);
            den0 += e0 + e1;
            den1 += e2 + e3;
            const int j = nt >> 1;
            if ((nt & 1) == 0) { P[j][0] = pack_bf2(e0, e1); P[j][1] = pack_bf2(e2, e3); }
            else               { P[j][2] = pack_bf2(e0, e1); P[j][3] = pack_bf2(e2, e3); }
        }

        // acc += P @ V
#pragma unroll
        for (int j = 0; j < 4; j++) {
#pragma unroll
            for (int np = 0; np < 4; np++) {
                uint32_t vH[4];
                ldmat_x4t(vH, vhB + ((j * 16 + lrow) * ATS + np * 16 + lcol) * 2);
                uint32_t fH0[2] = { vH[0], vH[1] }, fH1[2] = { vH[2], vH[3] };
                mma_bf16(acc[2 * np],     P[j], fH0);
                mma_bf16(acc[2 * np + 1], P[j], fH1);
            }
        }
        __syncthreads();
    }

    den0 += __shfl_xor_sync(~0u, den0, 1);
    den0 += __shfl_xor_sync(~0u, den0, 2);
    den1 += __shfl_xor_sync(~0u, den1, 1);
    den1 += __shfl_xor_sync(~0u, den1, 2);
    const float i0 = 1.f / den0, i1 = 1.f / den1;

    const int g  = lid >> 2;
    const int tg = (lid & 3) * 2;
    const long row0 = (long)(b * SEQ + q0 + mrow + g) * DMODEL + h * DHEAD;
    const long row1 = row0 + 8 * DMODEL;
#pragma unroll
    for (int nt = 0; nt < 8; nt++) {
        const int col = nt * 8 + tg;
        float v0 = acc[nt][0] * i0, v1 = acc[nt][1] * i0;
        float v2 = acc[nt][2] * i1, v3 = acc[nt][3] * i1;
        float h0 = __bfloat162float(__float2bfloat16(v0));
        float h1 = __bfloat162float(__float2bfloat16(v1));
        float h2 = __bfloat162float(__float2bfloat16(v2));
        float h3 = __bfloat162float(__float2bfloat16(v3));
        *(uint32_t*)(Chi + row0 + col) = pack_bf2(h0, h1);
        *(uint32_t*)(Chi + row1 + col) = pack_bf2(h2, h3);
        *(uint32_t*)(Clo + row0 + col) = pack_bf2(v0 - h0, v1 - h1);
        *(uint32_t*)(Clo + row1 + col) = pack_bf2(v2 - h2, v3 - h3);
    }
}

// ---------------------------------------------------------------------------
__global__ void __launch_bounds__(256) split_kernel(
    const float* __restrict__ A, __nv_bfloat16* __restrict__ hi,
    __nv_bfloat16* __restrict__ lo, long n4)
{
    long i = (long)blockIdx.x * blockDim.x + threadIdx.x;
    long stride = (long)gridDim.x * blockDim.x;
    for (; i < n4; i += stride) {
        float4 v = ((const float4*)A)[i];
        __nv_bfloat16 h0 = __float2bfloat16(v.x), h1 = __float2bfloat16(v.y);
        __nv_bfloat16 h2 = __float2bfloat16(v.z), h3 = __float2bfloat16(v.w);
        __nv_bfloat16 l0 = __float2bfloat16(v.x - __bfloat162float(h0));
        __nv_bfloat16 l1 = __float2bfloat16(v.y - __bfloat162float(h1));
        __nv_bfloat16 l2 = __float2bfloat16(v.z - __bfloat162float(h2));
        __nv_bfloat16 l3 = __float2bfloat16(v.w - __bfloat162float(h3));
        __nv_bfloat162 hp0(h0, h1), hp1(h2, h3), lp0(l0, l1), lp1(l2, l3);
        ((__nv_bfloat162*)hi)[i * 2]     = hp0;
        ((__nv_bfloat162*)hi)[i * 2 + 1] = hp1;
        ((__nv_bfloat162*)lo)[i * 2]     = lp0;
        ((__nv_bfloat162*)lo)[i * 2 + 1] = lp1;
    }
}

// ---------------------------------------------------------------------------
// All 6 weight matrices: transpose + split in one launch.
// blocks: [0,3072) wq/wk/wv | [3072,4096) wo | [4096,8192) w1 | [8192,12288) w2
// ---------------------------------------------------------------------------
__global__ void __launch_bounds__(256) tsplit_all(
    const float* __restrict__ wq, const float* __restrict__ wk,
    const float* __restrict__ wv, const float* __restrict__ wo,
    const float* __restrict__ w1, const float* __restrict__ w2,
    __nv_bfloat16* __restrict__ qkvh, __nv_bfloat16* __restrict__ qkvl,
    __nv_bfloat16* __restrict__ woh,  __nv_bfloat16* __restrict__ wol,
    __nv_bfloat16* __restrict__ w1h,  __nv_bfloat16* __restrict__ w1l,
    __nv_bfloat16* __restrict__ w2h,  __nv_bfloat16* __restrict__ w2l)
{
    const int bid = blockIdx.x;
    const float* W;
    __nv_bfloat16 *hi, *lo;
    int K, N, bn, bk;
    if (bid < 3072) {
        const int seg = bid >> 10, t = bid & 1023;
        W = seg == 0 ? wq : (seg == 1 ? wk : wv);
        hi = qkvh + (long)seg * DMODEL * DMODEL;
        lo = qkvl + (long)seg * DMODEL * DMODEL;
        K = DMODEL; N = DMODEL; bn = (t & 31) * 32; bk = (t >> 5) * 32;
    } else if (bid < 4096) {
        const int t = bid - 3072;
        W = wo; hi = woh; lo = wol;
        K = DMODEL; N = DMODEL; bn = (t & 31) * 32; bk = (t >> 5) * 32;
    } else if (bid < 8192) {
        const int t = bid - 4096;
        W = w1; hi = w1h; lo = w1l;
        K = DMODEL; N = DFF; bn = (t & 127) * 32; bk = (t >> 7) * 32;
    } else {
        const int t = bid - 8192;
        W = w2; hi = w2h; lo = w2l;
        K = DFF; N = DMODEL; bn = (t & 31) * 32; bk = (t >> 5) * 32;
    }

    __shared__ float tbuf[32][33];
    const int x = threadIdx.x & 31, y = threadIdx.x >> 5;
#pragma unroll
    for (int r = 0; r < 32; r += 8)
        tbuf[y + r][x] = W[(long)(bk + y + r) * N + bn + x];
    __syncthreads();
#pragma unroll
    for (int r = 0; r < 32; r += 8) {
        float v = tbuf[x][y + r];
        __nv_bfloat16 hh = __float2bfloat16(v);
        float rem = v - __bfloat162float(hh);
        long o = (long)(bn + y + r) * K + bk + x;
        hi[o] = hh;
        lo[o] = __float2bfloat16(rem);
    }
}

__global__ void __launch_bounds__(256) concat_bias_kernel(
    const float* __restrict__ bq, const float* __restrict__ bk,
    const float* __restrict__ bv, float* __restrict__ o)
{
    int i = blockIdx.x * 256 + threadIdx.x;
    if (i < DMODEL)           o[i] = bq[i];
    else if (i < 2 * DMODEL)  o[i] = bk[i - DMODEL];
    else if (i < 3 * DMODEL)  o[i] = bv[i - 2 * DMODEL];
}

// ---------------------------------------------------------------------------
// out = LayerNorm(A + B [+ B2]) * gamma + beta ; optional split bf16 output
// ---------------------------------------------------------------------------
__global__ __launch_bounds__(256) void add_ln_kernel(
    const float* __restrict__ A, const float* __restrict__ B,
    const float* __restrict__ B2,
    const float* __restrict__ gamma, const float* __restrict__ beta,
    float* __restrict__ out,
    __nv_bfloat16* __restrict__ ohi, __nv_bfloat16* __restrict__ olo,
    int do_split)
{
    __shared__ float red[2];
    const int row = blockIdx.x;
    const int tid = threadIdx.x;

    float4 a = ((const float4*)(A + (long)row * DMODEL))[tid];
    float4 b = ((const float4*)(B + (long)row * DMODEL))[tid];
    float4 v = {a.x + b.x, a.y + b.y, a.z + b.z, a.w + b.w};
    if (B2) {
        float4 c = ((const float4*)(B2 + (long)row * DMODEL))[tid];
        v.x += c.x; v.y += c.y; v.z += c.z; v.w += c.w;
    }

    float s  = v.x + v.y + v.z + v.w;
    float sq = v.x * v.x + v.y * v.y + v.z * v.z + v.w * v.w;
#pragma unroll
    for (int o = 16; o; o >>= 1) {
        s  += __shfl_xor_sync(~0u, s,  o);
        sq += __shfl_xor_sync(~0u, sq, o);
    }
    const int w = tid >> 5, l = tid & 31;
    __shared__ float ws[8], wq2[8];
    if (l == 0) { ws[w] = s; wq2[w] = sq; }
    __syncthreads();
    if (tid < 32) {
        float s2 = (tid < 8) ? ws[tid] : 0.f;
        float q2 = (tid < 8) ? wq2[tid] : 0.f;
#pragma unroll
        for (int o = 4; o; o >>= 1) {
            s2 += __shfl_xor_sync(~0u, s2, o);
            q2 += __shfl_xor_sync(~0u, q2, o);
        }
        if (tid == 0) { red[0] = s2; red[1] = q2; }
    }
    __syncthreads();
    float mean = red[0] * (1.f / DMODEL);
    float var  = red[1] * (1.f / DMODEL) - mean * mean;
    float rs   = rsqrtf(var + 1e-8f);

    float4 g  = ((const float4*)gamma)[tid];
    float4 be = ((const float4*)beta)[tid];
    float4 o4;
    o4.x = (v.x - mean) * rs * g.x + be.x;
    o4.y = (v.y - mean) * rs * g.y + be.y;
    o4.z = (v.z - mean) * rs * g.z + be.z;
    o4.w = (v.w - mean) * rs * g.w + be.w;
    ((float4*)(out + (long)row * DMODEL))[tid] = o4;

    if (do_split) {
        float h0 = __bfloat162float(__float2bfloat16(o4.x));
        float h1 = __bfloat162float(__float2bfloat16(o4.y));
        float h2 = __bfloat162float(__float2bfloat16(o4.z));
        float h3 = __bfloat162float(__float2bfloat16(o4.w));
        uint2 hv = { pack_bf2(h0, h1), pack_bf2(h2, h3) };
        uint2 lv = { pack_bf2(o4.x - h0, o4.y - h1), pack_bf2(o4.z - h2, o4.w - h3) };
        ((uint2*)(ohi + (long)row * DMODEL))[tid] = hv;
        ((uint2*)(olo + (long)row * DMODEL))[tid] = lv;
    }
}

// ---------------------------------------------------------------------------
extern "C" void kernel_launch(void* const* d_in, const int* in_sizes, int n_in,
                              void* d_out, int out_size)
{
    const float* x  = (const float*)d_in[0];
    const float* wq = (const float*)d_in[1];
    const float* bq = (const float*)d_in[2];
    const float* wk = (const float*)d_in[3];
    const float* bk = (const float*)d_in[4];
    const float* wv = (const float*)d_in[5];
    const float* bv = (const float*)d_in[6];
    const float* wo = (const float*)d_in[7];
    const float* bo = (const float*)d_in[8];
    const float* w1 = (const float*)d_in[9];
    const float* b1 = (const float*)d_in[10];
    const float* w2 = (const float*)d_in[11];
    const float* b2 = (const float*)d_in[12];
    const float* ga = (const float*)d_in[13];
    const float* be = (const float*)d_in[14];
    float* out = (float*)d_out;

    float *S1, *S2, *S3, *b3;
    __nv_bfloat16 *Xhi, *Xlo, *QKVhi, *QKVlo;
    __nv_bfloat16 *Chi, *Clo, *O1hi, *O1lo, *H1hi, *H1lo;
    __nv_bfloat16 *WQKVh, *WQKVl, *WOh, *WOl, *W1h, *W1l, *W2h, *W2l;
    cudaGetSymbolAddress((void**)&S1,    g_S1);
    cudaGetSymbolAddress((void**)&S2,    g_S2);
    cudaGetSymbolAddress((void**)&S3,    g_S3);
    cudaGetSymbolAddress((void**)&b3,    g_b3);
    cudaGetSymbolAddress((void**)&Xhi,   g_Xhi);
    cudaGetSymbolAddress((void**)&Xlo,   g_Xlo);
    cudaGetSymbolAddress((void**)&QKVhi, g_QKVhi);
    cudaGetSymbolAddress((void**)&QKVlo, g_QKVlo);
    cudaGetSymbolAddress((void**)&Chi,   g_Chi);
    cudaGetSymbolAddress((void**)&Clo,   g_Clo);
    cudaGetSymbolAddress((void**)&O1hi,  g_O1hi);
    cudaGetSymbolAddress((void**)&O1lo,  g_O1lo);
    cudaGetSymbolAddress((void**)&H1hi,  g_H1hi);
    cudaGetSymbolAddress((void**)&H1lo,  g_H1lo);
    cudaGetSymbolAddress((void**)&WQKVh, g_WQKVh);
    cudaGetSymbolAddress((void**)&WQKVl, g_WQKVl);
    cudaGetSymbolAddress((void**)&WOh,   g_WOh);
    cudaGetSymbolAddress((void**)&WOl,   g_WOl);
    cudaGetSymbolAddress((void**)&W1h,   g_W1h);
    cudaGetSymbolAddress((void**)&W1l,   g_W1l);
    cudaGetSymbolAddress((void**)&W2h,   g_W2h);
    cudaGetSymbolAddress((void**)&W2l,   g_W2l);

    cudaFuncSetAttribute(gemm_mma, cudaFuncAttributeMaxDynamicSharedMemorySize, GEMM_SMEM);
    cudaFuncSetAttribute(attn_mma, cudaFuncAttributeMaxDynamicSharedMemorySize, ATTN_SMEM);

    dim3 blk(256);
    dim3 gQKV(QKVS / 128, M_TOK / 128, 1);
    dim3 gProjZ(DMODEL / 128, M_TOK / 128, 2);
    dim3 gF1(DFF / 128, M_TOK / 128, 1);

    // prep: input split + ALL weight transpose-splits in one launch
    split_kernel<<<512, blk>>>(x, Xhi, Xlo, (long)M_TOK * DMODEL / 4);
    tsplit_all<<<12288, blk>>>(wq, wk, wv, wo, w1, w2,
                               WQKVh, WQKVl, WOh, WOl, W1h, W1l, W2h, W2l);
    concat_bias_kernel<<<(QKVS + 255) / 256, blk>>>(bq, bk, bv, b3);

    // fused QKV projection
    gemm_mma<<<gQKV, blk, GEMM_SMEM>>>(Xhi, Xlo, WQKVh, WQKVl, b3, nullptr, nullptr,
                                       QKVhi, QKVlo, QKVS, DMODEL, DMODEL, 0, 1);

    // attention
    dim3 gAttn(SEQ / 128, 4 * NHEAD);
    attn_mma<<<gAttn, blk, ATTN_SMEM>>>(QKVhi, QKVlo, Chi, Clo);

    // O projection, split-K=2
    gemm_mma<<<gProjZ, blk, GEMM_SMEM>>>(Chi, Clo, WOh, WOl, bo, S1, S3,
                                         nullptr, nullptr, DMODEL, DMODEL, DMODEL / 2, 0, 0);

    // out1 = LN(x + p0 + p1)
    add_ln_kernel<<<M_TOK, blk>>>(x, S1, S3, ga, be, S2, O1hi, O1lo, 1);

    // FFN1
    gemm_mma<<<gF1, blk, GEMM_SMEM>>>(O1hi, O1lo, W1h, W1l, b1, nullptr, nullptr,
                                      H1hi, H1lo, DFF, DMODEL, DMODEL, 1, 1);

    // FFN2, split-K=2
    gemm_mma<<<gProjZ, blk, GEMM_SMEM>>>(H1hi, H1lo, W2h, W2l, b2, S1, S3,
                                         nullptr, nullptr, DMODEL, DFF, DFF / 2, 0, 0);

    // out = LN(out1 + p0 + p1)
    add_ln_kernel<<<M_TOK, blk>>>(S2, S1, S3, ga, be, out, nullptr, nullptr, 0);
}

// round 8
// speedup vs baseline: 3.1104x; 1.1235x over previous
#include <cuda_runtime.h>
#include <cuda_bf16.h>
#include <cstdint>

// ---------------------------------------------------------------------------
// EncoderLayer R7: 3-stage cp.async pipelines (1 sync/iter) + XOR-swizzled
// GEMM smem (no padding). Otherwise R6 structure.
// ---------------------------------------------------------------------------

#define M_TOK   8192
#define DMODEL  1024
#define DFF     4096
#define NHEAD   16
#define DHEAD   64
#define SEQ     2048
#define QKVS    3072

// fp32 scratch
__device__ float g_S1 [M_TOK * DMODEL];
__device__ float g_S2 [M_TOK * DMODEL];
__device__ float g_S3 [M_TOK * DMODEL];
__device__ float g_b3 [QKVS];
// bf16 split operands
__device__ __nv_bfloat16 g_Xhi [M_TOK * DMODEL];
__device__ __nv_bfloat16 g_Xlo [M_TOK * DMODEL];
__device__ __nv_bfloat16 g_QKVhi[M_TOK * QKVS];
__device__ __nv_bfloat16 g_QKVlo[M_TOK * QKVS];
__device__ __nv_bfloat16 g_Chi [M_TOK * DMODEL];
__device__ __nv_bfloat16 g_Clo [M_TOK * DMODEL];
__device__ __nv_bfloat16 g_O1hi[M_TOK * DMODEL];
__device__ __nv_bfloat16 g_O1lo[M_TOK * DMODEL];
__device__ __nv_bfloat16 g_H1hi[M_TOK * DFF];
__device__ __nv_bfloat16 g_H1lo[M_TOK * DFF];
// dedicated transposed split weights
__device__ __nv_bfloat16 g_WQKVh[QKVS * DMODEL];
__device__ __nv_bfloat16 g_WQKVl[QKVS * DMODEL];
__device__ __nv_bfloat16 g_WOh [DMODEL * DMODEL];
__device__ __nv_bfloat16 g_WOl [DMODEL * DMODEL];
__device__ __nv_bfloat16 g_W1h [DFF * DMODEL];
__device__ __nv_bfloat16 g_W1l [DFF * DMODEL];
__device__ __nv_bfloat16 g_W2h [DMODEL * DFF];
__device__ __nv_bfloat16 g_W2l [DMODEL * DFF];

__device__ __forceinline__ uint32_t smem_u32(const void* p) {
    uint32_t a;
    asm("{ .reg .u64 t; cvta.to.shared.u64 t, %1; cvt.u32.u64 %0, t; }" : "=r"(a) : "l"(p));
    return a;
}
__device__ __forceinline__ void ldmat_x4(uint32_t* r, uint32_t addr) {
    asm volatile("ldmatrix.sync.aligned.m8n8.x4.shared.b16 {%0,%1,%2,%3}, [%4];"
                 : "=r"(r[0]), "=r"(r[1]), "=r"(r[2]), "=r"(r[3]) : "r"(addr));
}
__device__ __forceinline__ void ldmat_x4t(uint32_t* r, uint32_t addr) {
    asm volatile("ldmatrix.sync.aligned.m8n8.x4.trans.shared.b16 {%0,%1,%2,%3}, [%4];"
                 : "=r"(r[0]), "=r"(r[1]), "=r"(r[2]), "=r"(r[3]) : "r"(addr));
}
__device__ __forceinline__ void mma_bf16(float* d, const uint32_t* a, const uint32_t* b) {
    asm volatile("mma.sync.aligned.m16n8k16.row.col.f32.bf16.bf16.f32 "
                 "{%0,%1,%2,%3}, {%4,%5,%6,%7}, {%8,%9}, {%0,%1,%2,%3};"
                 : "+f"(d[0]), "+f"(d[1]), "+f"(d[2]), "+f"(d[3])
                 : "r"(a[0]), "r"(a[1]), "r"(a[2]), "r"(a[3]), "r"(b[0]), "r"(b[1]));
}
__device__ __forceinline__ uint32_t pack_bf2(float lo, float hi) {
    __nv_bfloat162 t = __floats2bfloat162_rn(lo, hi);
    return *reinterpret_cast<uint32_t*>(&t);
}
#define CP16(dst, src) asm volatile("cp.async.cg.shared.global [%0], [%1], 16;" :: "r"(dst), "l"(src))
#define CP_COMMIT()    asm volatile("cp.async.commit_group;" ::: "memory")
#define CP_WAIT1()     asm volatile("cp.async.wait_group 1;" ::: "memory")
#define CP_WAIT0()     asm volatile("cp.async.wait_group 0;" ::: "memory")

// 64B-row XOR swizzle: chunk col (16B units) XOR row bits [1:2]
#define SWZ(row, bc) ((uint32_t)((row) * 64 + ((bc) ^ (((row) & 6) << 3))))

// ---------------------------------------------------------------------------
// Split-bf16 HMMA GEMM, 3-stage cp.async pipeline, swizzled smem.
// BM=BN=128, BK=32. 256 threads = 2x4 warps, 64x32 per warp.
// stage: AHI 8K | ALO 8K | BHI 8K | BLO 8K = 32768 B; 3 stages = 98304 B.
// ---------------------------------------------------------------------------
#define GST 32768
#define OF_AHI 0
#define OF_ALO 8192
#define OF_BHI 16384
#define OF_BLO 24576
#define GEMM_SMEM (3 * GST)

__global__ void __launch_bounds__(256, 2) gemm_mma(
    const __nv_bfloat16* __restrict__ Ahi, const __nv_bfloat16* __restrict__ Alo,
    const __nv_bfloat16* __restrict__ Bhi, const __nv_bfloat16* __restrict__ Blo,
    const float* __restrict__ bias, float* __restrict__ C0, float* __restrict__ C1,
    __nv_bfloat16* __restrict__ Chi, __nv_bfloat16* __restrict__ Clo,
    int N, int K, int Ksl, int relu, int mode)
{
    extern __shared__ char smraw[];
    const uint32_t sb = smem_u32(smraw);

    const int tid = threadIdx.x;
    const int wid = tid >> 5, lid = tid & 31;
    const int m0 = blockIdx.y * 128, n0 = blockIdx.x * 128;
    const int z  = blockIdx.z;
    const long kzb = (long)z * Ksl;
    float* __restrict__ C = z ? C1 : C0;
    const int wm = (wid >> 2) * 64;
    const int wn = (wid & 3) * 32;

    const int r  = tid >> 2;          // 0..63
    const int cg = (tid & 3) * 8;     // element col
    const int cb = (tid & 3) * 16;    // byte chunk col
    const uint32_t sw0 = SWZ(r, cb);
    const uint32_t sw1 = SWZ(r + 64, cb);

    float acc[4][4][4];
#pragma unroll
    for (int mt = 0; mt < 4; mt++)
#pragma unroll
        for (int nt = 0; nt < 4; nt++)
#pragma unroll
            for (int f = 0; f < 4; f++) acc[mt][nt][f] = 0.f;

    const int lrow = lid & 15;
    const int lcb  = (lid >> 4) * 16;   // byte col within k16 block
    const int NC = Ksl >> 5;

    auto issue = [&](int i) {
        const uint32_t base = sb + (i % 3) * GST;
        const long k0 = kzb + (long)(i << 5);
        const long ra = (long)(m0 + r) * K + k0 + cg;
        const long rb = (long)(n0 + r) * K + k0 + cg;
        CP16(base + OF_AHI + sw0, Ahi + ra);
        CP16(base + OF_AHI + sw1, Ahi + ra + 64 * (long)K);
        CP16(base + OF_ALO + sw0, Alo + ra);
        CP16(base + OF_ALO + sw1, Alo + ra + 64 * (long)K);
        CP16(base + OF_BHI + sw0, Bhi + rb);
        CP16(base + OF_BHI + sw1, Bhi + rb + 64 * (long)K);
        CP16(base + OF_BLO + sw0, Blo + rb);
        CP16(base + OF_BLO + sw1, Blo + rb + 64 * (long)K);
    };

    issue(0); CP_COMMIT();
    if (NC > 1) { issue(1); CP_COMMIT(); }

    for (int i = 0; i < NC; i++) {
        if (i + 1 < NC) CP_WAIT1(); else CP_WAIT0();
        __syncthreads();
        if (i + 2 < NC) { issue(i + 2); CP_COMMIT(); }

        const uint32_t base = sb + (i % 3) * GST;
        const uint32_t aH = base + OF_AHI, aL = base + OF_ALO;
        const uint32_t bH = base + OF_BHI, bL = base + OF_BLO;

#pragma unroll
        for (int k16 = 0; k16 < 2; k16++) {
            const int bc = k16 * 32 + lcb;
            uint32_t afH[4][4], afL[4][4];
#pragma unroll
            for (int mt = 0; mt < 4; mt++) {
                const int arow = wm + mt * 16 + lrow;
                ldmat_x4(afH[mt], aH + SWZ(arow, bc));
                ldmat_x4(afL[mt], aL + SWZ(arow, bc));
            }
            uint32_t bfH[2][4], bfL[2][4];
#pragma unroll
            for (int np = 0; np < 2; np++) {
                const int brow = wn + np * 16 + lrow;
                ldmat_x4(bfH[np], bH + SWZ(brow, bc));
                ldmat_x4(bfL[np], bL + SWZ(brow, bc));
            }
#pragma unroll
            for (int mt = 0; mt < 4; mt++) {
#pragma unroll
                for (int nt = 0; nt < 4; nt++) {
                    uint32_t bH2[2] = { bfH[nt >> 1][nt & 1], bfH[nt >> 1][(nt & 1) + 2] };
                    uint32_t bL2[2] = { bfL[nt >> 1][nt & 1], bfL[nt >> 1][(nt & 1) + 2] };
                    mma_bf16(acc[mt][nt], afH[mt], bH2);
                    mma_bf16(acc[mt][nt], afH[mt], bL2);
                    mma_bf16(acc[mt][nt], afL[mt], bH2);
                }
            }
        }
    }

    const int g  = lid >> 2;
    const int tg = (lid & 3) * 2;
#pragma unroll
    for (int mt = 0; mt < 4; mt++) {
        const int row = m0 + wm + mt * 16 + g;
#pragma unroll
        for (int nt = 0; nt < 4; nt++) {
            const int col = n0 + wn + nt * 8 + tg;
            const float b0 = z ? 0.f : bias[col];
            const float b1 = z ? 0.f : bias[col + 1];
            float v0 = acc[mt][nt][0] + b0;
            float v1 = acc[mt][nt][1] + b1;
            float v2 = acc[mt][nt][2] + b0;
            float v3 = acc[mt][nt][3] + b1;
            if (relu) {
                v0 = fmaxf(v0, 0.f); v1 = fmaxf(v1, 0.f);
                v2 = fmaxf(v2, 0.f); v3 = fmaxf(v3, 0.f);
            }
            if (mode == 0) {
                C[(long)row * N + col]           = v0;
                C[(long)row * N + col + 1]       = v1;
                C[(long)(row + 8) * N + col]     = v2;
                C[(long)(row + 8) * N + col + 1] = v3;
            } else {
                float h0 = __bfloat162float(__float2bfloat16(v0));
                float h1 = __bfloat162float(__float2bfloat16(v1));
                float h2 = __bfloat162float(__float2bfloat16(v2));
                float h3 = __bfloat162float(__float2bfloat16(v3));
                *(uint32_t*)(Chi + (long)row * N + col)       = pack_bf2(h0, h1);
                *(uint32_t*)(Chi + (long)(row + 8) * N + col) = pack_bf2(h2, h3);
                *(uint32_t*)(Clo + (long)row * N + col)       = pack_bf2(v0 - h0, v1 - h1);
                *(uint32_t*)(Clo + (long)(row + 8) * N + col) = pack_bf2(v2 - h2, v3 - h3);
            }
        }
    }
}

// ---------------------------------------------------------------------------
// HMMA attention: Q split bf16, K/V plain bf16, 3-stage K/V pipeline.
// smem: QH 18432 | QL 18432 | 3 x stage{KH 9216, VH 9216} = 92160 bytes
// ---------------------------------------------------------------------------
#define ATS 72
#define AQ_H  0
#define AQ_L  18432
#define AKV0  36864
#define AKVST 18432
#define A_KH  0
#define A_VH  9216
#define ATTN_SMEM 92160

__global__ void __launch_bounds__(256, 2) attn_mma(
    const __nv_bfloat16* __restrict__ QKVhi, const __nv_bfloat16* __restrict__ QKVlo,
    __nv_bfloat16* __restrict__ Chi, __nv_bfloat16* __restrict__ Clo)
{
    extern __shared__ char smraw[];
    const uint32_t sb = smem_u32(smraw);

    const int tid = threadIdx.x;
    const int wid = tid >> 5, lid = tid & 31;
    const int bh = blockIdx.y;
    const int b = bh >> 4, h = bh & 15;
    const int q0 = blockIdx.x * 128;
    const long qbase = (long)(b * SEQ + q0) * QKVS + h * DHEAD;
    const long kbase = (long)(b * SEQ) * QKVS + DMODEL + h * DHEAD;
    const long vbase = kbase + DMODEL;

    for (int e = tid; e < 128 * 8; e += 256) {
        int row = e >> 3, cgp = (e & 7) * 8;
        const long gp = qbase + (long)row * QKVS + cgp;
        const uint32_t so = (uint32_t)(row * 144 + cgp * 2);
        *(uint4*)(smraw + AQ_H + so) = *(const uint4*)(QKVhi + gp);
        *(uint4*)(smraw + AQ_L + so) = *(const uint4*)(QKVlo + gp);
    }

    auto issueKV = [&](int kt) {
        const uint32_t base = sb + AKV0 + (kt % 3) * AKVST;
#pragma unroll
        for (int e0 = 0; e0 < 2; e0++) {
            const int e = tid + e0 * 256;
            const int row = e >> 3, cgp = (e & 7) * 8;
            const long kR = kbase + (long)(kt * 64 + row) * QKVS + cgp;
            const long vR = vbase + (long)(kt * 64 + row) * QKVS + cgp;
            const uint32_t so = (uint32_t)(row * 144 + cgp * 2);
            CP16(base + A_KH + so, QKVhi + kR);
            CP16(base + A_VH + so, QKVhi + vR);
        }
    };

    const int mrow = wid * 16;
    const int lrow = lid & 15;
    const int lcol = (lid >> 4) * 8;
    const uint32_t qhB = sb + AQ_H, qlB = sb + AQ_L;

    float acc[8][4];
#pragma unroll
    for (int nt = 0; nt < 8; nt++)
#pragma unroll
        for (int f = 0; f < 4; f++) acc[nt][f] = 0.f;
    float den0 = 0.f, den1 = 0.f;

    const int NKT = SEQ / 64;
    issueKV(0); CP_COMMIT();
    issueKV(1); CP_COMMIT();

    for (int kt = 0; kt < NKT; kt++) {
        if (kt + 1 < NKT) CP_WAIT1(); else CP_WAIT0();
        __syncthreads();
        if (kt + 2 < NKT) { issueKV(kt + 2); CP_COMMIT(); }

        const uint32_t kvb = sb + AKV0 + (kt % 3) * AKVST;
        const uint32_t khB = kvb + A_KH, vhB = kvb + A_VH;

        // S = (Qhi + Qlo) K^T
        float S[8][4];
#pragma unroll
        for (int nt = 0; nt < 8; nt++)
#pragma unroll
            for (int f = 0; f < 4; f++) S[nt][f] = 0.f;

#pragma unroll
        for (int k16 = 0; k16 < 4; k16++) {
            uint32_t aH[4], aL[4];
            ldmat_x4(aH, qhB + ((mrow + lrow) * ATS + k16 * 16 + lcol) * 2);
            ldmat_x4(aL, qlB + ((mrow + lrow) * ATS + k16 * 16 + lcol) * 2);
#pragma unroll
            for (int np = 0; np < 4; np++) {
                uint32_t bH[4];
                ldmat_x4(bH, khB + ((np * 16 + lrow) * ATS + k16 * 16 + lcol) * 2);
                uint32_t f0H[2] = { bH[0], bH[2] }, f1H[2] = { bH[1], bH[3] };
                mma_bf16(S[2 * np],     aH, f0H);
                mma_bf16(S[2 * np],     aL, f0H);
                mma_bf16(S[2 * np + 1], aH, f1H);
                mma_bf16(S[2 * np + 1], aL, f1H);
            }
        }

        uint32_t P[4][4];
#pragma unroll
        for (int nt = 0; nt < 8; nt++) {
            float e0 = __expf(fminf(fmaxf(S[nt][0] * 0.125f, -10.f), 10.f) - 10.f);
            float e1 = __expf(fminf(fmaxf(S[nt][1] * 0.125f, -10.f), 10.f) - 10.f);
            float e2 = __expf(fminf(fmaxf(S[nt][2] * 0.125f, -10.f), 10.f) - 10.f);
            float e3 = __expf(fminf(fmaxf(S[nt][3] * 0.125f, -10.f), 10.f) - 10.f);
            den0 += e0 + e1;
            den1 += e2 + e3;
            const int j = nt >> 1;
            if ((nt & 1) == 0) { P[j][0] = pack_bf2(e0, e1); P[j][1] = pack_bf2(e2, e3); }
            else               { P[j][2] = pack_bf2(e0, e1); P[j][3] = pack_bf2(e2, e3); }
        }

        // acc += P @ V
#pragma unroll
        for (int j = 0; j < 4; j++) {
#pragma unroll
            for (int np = 0; np < 4; np++) {
                uint32_t vH[4];
                ldmat_x4t(vH, vhB + ((j * 16 + lrow) * ATS + np * 16 + lcol) * 2);
                uint32_t fH0[2] = { vH[0], vH[1] }, fH1[2] = { vH[2], vH[3] };
                mma_bf16(acc[2 * np],     P[j], fH0);
                mma_bf16(acc[2 * np + 1], P[j], fH1);
            }
        }
    }

    den0 += __shfl_xor_sync(~0u, den0, 1);
    den0 += __shfl_xor_sync(~0u, den0, 2);
    den1 += __shfl_xor_sync(~0u, den1, 1);
    den1 += __shfl_xor_sync(~0u, den1, 2);
    const float i0 = 1.f / den0, i1 = 1.f / den1;

    const int g  = lid >> 2;
    const int tg = (lid & 3) * 2;
    const long row0 = (long)(b * SEQ + q0 + mrow + g) * DMODEL + h * DHEAD;
    const long row1 = row0 + 8 * DMODEL;
#pragma unroll
    for (int nt = 0; nt < 8; nt++) {
        const int col = nt * 8 + tg;
        float v0 = acc[nt][0] * i0, v1 = acc[nt][1] * i0;
        float v2 = acc[nt][2] * i1, v3 = acc[nt][3] * i1;
        float h0 = __bfloat162float(__float2bfloat16(v0));
        float h1 = __bfloat162float(__float2bfloat16(v1));
        float h2 = __bfloat162float(__float2bfloat16(v2));
        float h3 = __bfloat162float(__float2bfloat16(v3));
        *(uint32_t*)(Chi + row0 + col) = pack_bf2(h0, h1);
        *(uint32_t*)(Chi + row1 + col) = pack_bf2(h2, h3);
        *(uint32_t*)(Clo + row0 + col) = pack_bf2(v0 - h0, v1 - h1);
        *(uint32_t*)(Clo + row1 + col) = pack_bf2(v2 - h2, v3 - h3);
    }
}

// ---------------------------------------------------------------------------
__global__ void __launch_bounds__(256) split_kernel(
    const float* __restrict__ A, __nv_bfloat16* __restrict__ hi,
    __nv_bfloat16* __restrict__ lo, long n4)
{
    long i = (long)blockIdx.x * blockDim.x + threadIdx.x;
    long stride = (long)gridDim.x * blockDim.x;
    for (; i < n4; i += stride) {
        float4 v = ((const float4*)A)[i];
        __nv_bfloat16 h0 = __float2bfloat16(v.x), h1 = __float2bfloat16(v.y);
        __nv_bfloat16 h2 = __float2bfloat16(v.z), h3 = __float2bfloat16(v.w);
        __nv_bfloat16 l0 = __float2bfloat16(v.x - __bfloat162float(h0));
        __nv_bfloat16 l1 = __float2bfloat16(v.y - __bfloat162float(h1));
        __nv_bfloat16 l2 = __float2bfloat16(v.z - __bfloat162float(h2));
        __nv_bfloat16 l3 = __float2bfloat16(v.w - __bfloat162float(h3));
        __nv_bfloat162 hp0(h0, h1), hp1(h2, h3), lp0(l0, l1), lp1(l2, l3);
        ((__nv_bfloat162*)hi)[i * 2]     = hp0;
        ((__nv_bfloat162*)hi)[i * 2 + 1] = hp1;
        ((__nv_bfloat162*)lo)[i * 2]     = lp0;
        ((__nv_bfloat162*)lo)[i * 2 + 1] = lp1;
    }
}

// ---------------------------------------------------------------------------
__global__ void __launch_bounds__(256) tsplit_all(
    const float* __restrict__ wq, const float* __restrict__ wk,
    const float* __restrict__ wv, const float* __restrict__ wo,
    const float* __restrict__ w1, const float* __restrict__ w2,
    __nv_bfloat16* __restrict__ qkvh, __nv_bfloat16* __restrict__ qkvl,
    __nv_bfloat16* __restrict__ woh,  __nv_bfloat16* __restrict__ wol,
    __nv_bfloat16* __restrict__ w1h,  __nv_bfloat16* __restrict__ w1l,
    __nv_bfloat16* __restrict__ w2h,  __nv_bfloat16* __restrict__ w2l)
{
    const int bid = blockIdx.x;
    const float* W;
    __nv_bfloat16 *hi, *lo;
    int K, N, bn, bk;
    if (bid < 3072) {
        const int seg = bid >> 10, t = bid & 1023;
        W = seg == 0 ? wq : (seg == 1 ? wk : wv);
        hi = qkvh + (long)seg * DMODEL * DMODEL;
        lo = qkvl + (long)seg * DMODEL * DMODEL;
        K = DMODEL; N = DMODEL; bn = (t & 31) * 32; bk = (t >> 5) * 32;
    } else if (bid < 4096) {
        const int t = bid - 3072;
        W = wo; hi = woh; lo = wol;
        K = DMODEL; N = DMODEL; bn = (t & 31) * 32; bk = (t >> 5) * 32;
    } else if (bid < 8192) {
        const int t = bid - 4096;
        W = w1; hi = w1h; lo = w1l;
        K = DMODEL; N = DFF; bn = (t & 127) * 32; bk = (t >> 7) * 32;
    } else {
        const int t = bid - 8192;
        W = w2; hi = w2h; lo = w2l;
        K = DFF; N = DMODEL; bn = (t & 31) * 32; bk = (t >> 5) * 32;
    }

    __shared__ float tbuf[32][33];
    const int x = threadIdx.x & 31, y = threadIdx.x >> 5;
#pragma unroll
    for (int r = 0; r < 32; r += 8)
        tbuf[y + r][x] = W[(long)(bk + y + r) * N + bn + x];
    __syncthreads();
#pragma unroll
    for (int r = 0; r < 32; r += 8) {
        float v = tbuf[x][y + r];
        __nv_bfloat16 hh = __float2bfloat16(v);
        float rem = v - __bfloat162float(hh);
        long o = (long)(bn + y + r) * K + bk + x;
        hi[o] = hh;
        lo[o] = __float2bfloat16(rem);
    }
}

__global__ void __launch_bounds__(256) concat_bias_kernel(
    const float* __restrict__ bq, const float* __restrict__ bk,
    const float* __restrict__ bv, float* __restrict__ o)
{
    int i = blockIdx.x * 256 + threadIdx.x;
    if (i < DMODEL)           o[i] = bq[i];
    else if (i < 2 * DMODEL)  o[i] = bk[i - DMODEL];
    else if (i < 3 * DMODEL)  o[i] = bv[i - 2 * DMODEL];
}

// ---------------------------------------------------------------------------
__global__ __launch_bounds__(256) void add_ln_kernel(
    const float* __restrict__ A, const float* __restrict__ B,
    const float* __restrict__ B2,
    const float* __restrict__ gamma, const float* __restrict__ beta,
    float* __restrict__ out,
    __nv_bfloat16* __restrict__ ohi, __nv_bfloat16* __restrict__ olo,
    int do_split)
{
    __shared__ float red[2];
    const int row = blockIdx.x;
    const int tid = threadIdx.x;

    float4 a = ((const float4*)(A + (long)row * DMODEL))[tid];
    float4 b = ((const float4*)(B + (long)row * DMODEL))[tid];
    float4 v = {a.x + b.x, a.y + b.y, a.z + b.z, a.w + b.w};
    if (B2) {
        float4 c = ((const float4*)(B2 + (long)row * DMODEL))[tid];
        v.x += c.x; v.y += c.y; v.z += c.z; v.w += c.w;
    }

    float s  = v.x + v.y + v.z + v.w;
    float sq = v.x * v.x + v.y * v.y + v.z * v.z + v.w * v.w;
#pragma unroll
    for (int o = 16; o; o >>= 1) {
        s  += __shfl_xor_sync(~0u, s,  o);
        sq += __shfl_xor_sync(~0u, sq, o);
    }
    const int w = tid >> 5, l = tid & 31;
    __shared__ float ws[8], wq2[8];
    if (l == 0) { ws[w] = s; wq2[w] = sq; }
    __syncthreads();
    if (tid < 32) {
        float s2 = (tid < 8) ? ws[tid] : 0.f;
        float q2 = (tid < 8) ? wq2[tid] : 0.f;
#pragma unroll
        for (int o = 4; o; o >>= 1) {
            s2 += __shfl_xor_sync(~0u, s2, o);
            q2 += __shfl_xor_sync(~0u, q2, o);
        }
        if (tid == 0) { red[0] = s2; red[1] = q2; }
    }
    __syncthreads();
    float mean = red[0] * (1.f / DMODEL);
    float var  = red[1] * (1.f / DMODEL) - mean * mean;
    float rs   = rsqrtf(var + 1e-8f);

    float4 g  = ((const float4*)gamma)[tid];
    float4 be = ((const float4*)beta)[tid];
    float4 o4;
    o4.x = (v.x - mean) * rs * g.x + be.x;
    o4.y = (v.y - mean) * rs * g.y + be.y;
    o4.z = (v.z - mean) * rs * g.z + be.z;
    o4.w = (v.w - mean) * rs * g.w + be.w;
    ((float4*)(out + (long)row * DMODEL))[tid] = o4;

    if (do_split) {
        float h0 = __bfloat162float(__float2bfloat16(o4.x));
        float h1 = __bfloat162float(__float2bfloat16(o4.y));
        float h2 = __bfloat162float(__float2bfloat16(o4.z));
        float h3 = __bfloat162float(__float2bfloat16(o4.w));
        uint2 hv = { pack_bf2(h0, h1), pack_bf2(h2, h3) };
        uint2 lv = { pack_bf2(o4.x - h0, o4.y - h1), pack_bf2(o4.z - h2, o4.w - h3) };
        ((uint2*)(ohi + (long)row * DMODEL))[tid] = hv;
        ((uint2*)(olo + (long)row * DMODEL))[tid] = lv;
    }
}

// ---------------------------------------------------------------------------
extern "C" void kernel_launch(void* const* d_in, const int* in_sizes, int n_in,
                              void* d_out, int out_size)
{
    const float* x  = (const float*)d_in[0];
    const float* wq = (const float*)d_in[1];
    const float* bq = (const float*)d_in[2];
    const float* wk = (const float*)d_in[3];
    const float* bk = (const float*)d_in[4];
    const float* wv = (const float*)d_in[5];
    const float* bv = (const float*)d_in[6];
    const float* wo = (const float*)d_in[7];
    const float* bo = (const float*)d_in[8];
    const float* w1 = (const float*)d_in[9];
    const float* b1 = (const float*)d_in[10];
    const float* w2 = (const float*)d_in[11];
    const float* b2 = (const float*)d_in[12];
    const float* ga = (const float*)d_in[13];
    const float* be = (const float*)d_in[14];
    float* out = (float*)d_out;

    float *S1, *S2, *S3, *b3;
    __nv_bfloat16 *Xhi, *Xlo, *QKVhi, *QKVlo;
    __nv_bfloat16 *Chi, *Clo, *O1hi, *O1lo, *H1hi, *H1lo;
    __nv_bfloat16 *WQKVh, *WQKVl, *WOh, *WOl, *W1h, *W1l, *W2h, *W2l;
    cudaGetSymbolAddress((void**)&S1,    g_S1);
    cudaGetSymbolAddress((void**)&S2,    g_S2);
    cudaGetSymbolAddress((void**)&S3,    g_S3);
    cudaGetSymbolAddress((void**)&b3,    g_b3);
    cudaGetSymbolAddress((void**)&Xhi,   g_Xhi);
    cudaGetSymbolAddress((void**)&Xlo,   g_Xlo);
    cudaGetSymbolAddress((void**)&QKVhi, g_QKVhi);
    cudaGetSymbolAddress((void**)&QKVlo, g_QKVlo);
    cudaGetSymbolAddress((void**)&Chi,   g_Chi);
    cudaGetSymbolAddress((void**)&Clo,   g_Clo);
    cudaGetSymbolAddress((void**)&O1hi,  g_O1hi);
    cudaGetSymbolAddress((void**)&O1lo,  g_O1lo);
    cudaGetSymbolAddress((void**)&H1hi,  g_H1hi);
    cudaGetSymbolAddress((void**)&H1lo,  g_H1lo);
    cudaGetSymbolAddress((void**)&WQKVh, g_WQKVh);
    cudaGetSymbolAddress((void**)&WQKVl, g_WQKVl);
    cudaGetSymbolAddress((void**)&WOh,   g_WOh);
    cudaGetSymbolAddress((void**)&WOl,   g_WOl);
    cudaGetSymbolAddress((void**)&W1h,   g_W1h);
    cudaGetSymbolAddress((void**)&W1l,   g_W1l);
    cudaGetSymbolAddress((void**)&W2h,   g_W2h);
    cudaGetSymbolAddress((void**)&W2l,   g_W2l);

    cudaFuncSetAttribute(gemm_mma, cudaFuncAttributeMaxDynamicSharedMemorySize, GEMM_SMEM);
    cudaFuncSetAttribute(attn_mma, cudaFuncAttributeMaxDynamicSharedMemorySize, ATTN_SMEM);

    dim3 blk(256);
    dim3 gQKV(QKVS / 128, M_TOK / 128, 1);
    dim3 gProjZ(DMODEL / 128, M_TOK / 128, 2);
    dim3 gF1(DFF / 128, M_TOK / 128, 1);

    split_kernel<<<512, blk>>>(x, Xhi, Xlo, (long)M_TOK * DMODEL / 4);
    tsplit_all<<<12288, blk>>>(wq, wk, wv, wo, w1, w2,
                               WQKVh, WQKVl, WOh, WOl, W1h, W1l, W2h, W2l);
    concat_bias_kernel<<<(QKVS + 255) / 256, blk>>>(bq, bk, bv, b3);

    gemm_mma<<<gQKV, blk, GEMM_SMEM>>>(Xhi, Xlo, WQKVh, WQKVl, b3, nullptr, nullptr,
                                       QKVhi, QKVlo, QKVS, DMODEL, DMODEL, 0, 1);

    dim3 gAttn(SEQ / 128, 4 * NHEAD);
    attn_mma<<<gAttn, blk, ATTN_SMEM>>>(QKVhi, QKVlo, Chi, Clo);

    gemm_mma<<<gProjZ, blk, GEMM_SMEM>>>(Chi, Clo, WOh, WOl, bo, S1, S3,
                                         nullptr, nullptr, DMODEL, DMODEL, DMODEL / 2, 0, 0);

    add_ln_kernel<<<M_TOK, blk>>>(x, S1, S3, ga, be, S2, O1hi, O1lo, 1);

    gemm_mma<<<gF1, blk, GEMM_SMEM>>>(O1hi, O1lo, W1h, W1l, b1, nullptr, nullptr,
                                      H1hi, H1lo, DFF, DMODEL, DMODEL, 1, 1);

    gemm_mma<<<gProjZ, blk, GEMM_SMEM>>>(H1hi, H1lo, W2h, W2l, b2, S1, S3,
                                         nullptr, nullptr, DMODEL, DFF, DFF / 2, 0, 0);

    add_ln_kernel<<<M_TOK, blk>>>(S2, S1, S3, ga, be, out, nullptr, nullptr, 0);
}

// round 9
// speedup vs baseline: 4.5833x; 1.4735x over previous
#include <cuda_runtime.h>
#include <cuda_fp16.h>
#include <cstdint>

// ---------------------------------------------------------------------------
// EncoderLayer R8: fp16 2-term GEMMs (A single fp16, W = fp16 hi+lo) +
// pure-fp16 attention (single-pass QK, single-pass PV). 3-stage cp.async.
// ---------------------------------------------------------------------------

#define M_TOK   8192
#define DMODEL  1024
#define DFF     4096
#define NHEAD   16
#define DHEAD   64
#define SEQ     2048
#define QKVS    3072

// fp32 scratch
__device__ float g_S1 [M_TOK * DMODEL];
__device__ float g_S2 [M_TOK * DMODEL];
__device__ float g_S3 [M_TOK * DMODEL];
__device__ float g_b3 [QKVS];
// fp16 activations
__device__ __half g_Xf  [M_TOK * DMODEL];
__device__ __half g_QKVf[M_TOK * QKVS];
__device__ __half g_Cf  [M_TOK * DMODEL];   // ctx
__device__ __half g_O1f [M_TOK * DMODEL];   // out1
__device__ __half g_H1f [M_TOK * DFF];      // relu(ffn1)
// fp16 split weights (transposed, [N,K])
__device__ __half g_WQKVh[QKVS * DMODEL];
__device__ __half g_WQKVl[QKVS * DMODEL];
__device__ __half g_WOh [DMODEL * DMODEL];
__device__ __half g_WOl [DMODEL * DMODEL];
__device__ __half g_W1h [DFF * DMODEL];
__device__ __half g_W1l [DFF * DMODEL];
__device__ __half g_W2h [DMODEL * DFF];
__device__ __half g_W2l [DMODEL * DFF];

__device__ __forceinline__ uint32_t smem_u32(const void* p) {
    uint32_t a;
    asm("{ .reg .u64 t; cvta.to.shared.u64 t, %1; cvt.u32.u64 %0, t; }" : "=r"(a) : "l"(p));
    return a;
}
__device__ __forceinline__ void ldmat_x4(uint32_t* r, uint32_t addr) {
    asm volatile("ldmatrix.sync.aligned.m8n8.x4.shared.b16 {%0,%1,%2,%3}, [%4];"
                 : "=r"(r[0]), "=r"(r[1]), "=r"(r[2]), "=r"(r[3]) : "r"(addr));
}
__device__ __forceinline__ void ldmat_x4t(uint32_t* r, uint32_t addr) {
    asm volatile("ldmatrix.sync.aligned.m8n8.x4.trans.shared.b16 {%0,%1,%2,%3}, [%4];"
                 : "=r"(r[0]), "=r"(r[1]), "=r"(r[2]), "=r"(r[3]) : "r"(addr));
}
__device__ __forceinline__ void mma_f16(float* d, const uint32_t* a, const uint32_t* b) {
    asm volatile("mma.sync.aligned.m16n8k16.row.col.f32.f16.f16.f32 "
                 "{%0,%1,%2,%3}, {%4,%5,%6,%7}, {%8,%9}, {%0,%1,%2,%3};"
                 : "+f"(d[0]), "+f"(d[1]), "+f"(d[2]), "+f"(d[3])
                 : "r"(a[0]), "r"(a[1]), "r"(a[2]), "r"(a[3]), "r"(b[0]), "r"(b[1]));
}
__device__ __forceinline__ uint32_t pack_h2(float lo, float hi) {
    __half2 t = __floats2half2_rn(lo, hi);
    return *reinterpret_cast<uint32_t*>(&t);
}
#define CP16(dst, src) asm volatile("cp.async.cg.shared.global [%0], [%1], 16;" :: "r"(dst), "l"(src))
#define CP_COMMIT()    asm volatile("cp.async.commit_group;" ::: "memory")
#define CP_WAIT1()     asm volatile("cp.async.wait_group 1;" ::: "memory")
#define CP_WAIT0()     asm volatile("cp.async.wait_group 0;" ::: "memory")

// 64B-row XOR swizzle
#define SWZ(row, bc) ((uint32_t)((row) * 64 + ((bc) ^ (((row) & 6) << 3))))

// ---------------------------------------------------------------------------
// fp16 2-term HMMA GEMM: C = A @ W + bias, A fp16, W = Whi + Wlo (fp16, [N,K]).
// BM=BN=128, BK=32. 256 threads = 2x4 warps, 64x32 per warp. 3-stage pipeline.
// stage: A 8K | BHI 8K | BLO 8K = 24576 B; 3 stages = 73728 B.
// ---------------------------------------------------------------------------
#define GST 24576
#define OF_A   0
#define OF_BHI 8192
#define OF_BLO 16384
#define GEMM_SMEM (3 * GST)

__global__ void __launch_bounds__(256, 2) gemm_mma(
    const __half* __restrict__ A,
    const __half* __restrict__ Bhi, const __half* __restrict__ Blo,
    const float* __restrict__ bias, float* __restrict__ C0, float* __restrict__ C1,
    __half* __restrict__ Cf,
    int N, int K, int Ksl, int relu, int mode)
{
    extern __shared__ char smraw[];
    const uint32_t sb = smem_u32(smraw);

    const int tid = threadIdx.x;
    const int wid = tid >> 5, lid = tid & 31;
    const int m0 = blockIdx.y * 128, n0 = blockIdx.x * 128;
    const int z  = blockIdx.z;
    const long kzb = (long)z * Ksl;
    float* __restrict__ C = z ? C1 : C0;
    const int wm = (wid >> 2) * 64;
    const int wn = (wid & 3) * 32;

    const int r  = tid >> 2;
    const int cg = (tid & 3) * 8;
    const int cb = (tid & 3) * 16;
    const uint32_t sw0 = SWZ(r, cb);
    const uint32_t sw1 = SWZ(r + 64, cb);

    float acc[4][4][4];
#pragma unroll
    for (int mt = 0; mt < 4; mt++)
#pragma unroll
        for (int nt = 0; nt < 4; nt++)
#pragma unroll
            for (int f = 0; f < 4; f++) acc[mt][nt][f] = 0.f;

    const int lrow = lid & 15;
    const int lcb  = (lid >> 4) * 16;
    const int NC = Ksl >> 5;

    auto issue = [&](int i) {
        const uint32_t base = sb + (i % 3) * GST;
        const long k0 = kzb + (long)(i << 5);
        const long ra = (long)(m0 + r) * K + k0 + cg;
        const long rb = (long)(n0 + r) * K + k0 + cg;
        CP16(base + OF_A   + sw0, A + ra);
        CP16(base + OF_A   + sw1, A + ra + 64 * (long)K);
        CP16(base + OF_BHI + sw0, Bhi + rb);
        CP16(base + OF_BHI + sw1, Bhi + rb + 64 * (long)K);
        CP16(base + OF_BLO + sw0, Blo + rb);
        CP16(base + OF_BLO + sw1, Blo + rb + 64 * (long)K);
    };

    issue(0); CP_COMMIT();
    if (NC > 1) { issue(1); CP_COMMIT(); }

    for (int i = 0; i < NC; i++) {
        if (i + 1 < NC) CP_WAIT1(); else CP_WAIT0();
        __syncthreads();
        if (i + 2 < NC) { issue(i + 2); CP_COMMIT(); }

        const uint32_t base = sb + (i % 3) * GST;
        const uint32_t aB = base + OF_A;
        const uint32_t bH = base + OF_BHI, bL = base + OF_BLO;

#pragma unroll
        for (int k16 = 0; k16 < 2; k16++) {
            const int bc = k16 * 32 + lcb;
            uint32_t af[4][4];
#pragma unroll
            for (int mt = 0; mt < 4; mt++)
                ldmat_x4(af[mt], aB + SWZ(wm + mt * 16 + lrow, bc));
            uint32_t bfH[2][4], bfL[2][4];
#pragma unroll
            for (int np = 0; np < 2; np++) {
                const int brow = wn + np * 16 + lrow;
                ldmat_x4(bfH[np], bH + SWZ(brow, bc));
                ldmat_x4(bfL[np], bL + SWZ(brow, bc));
            }
#pragma unroll
            for (int mt = 0; mt < 4; mt++) {
#pragma unroll
                for (int nt = 0; nt < 4; nt++) {
                    uint32_t bH2[2] = { bfH[nt >> 1][nt & 1], bfH[nt >> 1][(nt & 1) + 2] };
                    uint32_t bL2[2] = { bfL[nt >> 1][nt & 1], bfL[nt >> 1][(nt & 1) + 2] };
                    mma_f16(acc[mt][nt], af[mt], bH2);
                    mma_f16(acc[mt][nt], af[mt], bL2);
                }
            }
        }
    }

    const int g  = lid >> 2;
    const int tg = (lid & 3) * 2;
#pragma unroll
    for (int mt = 0; mt < 4; mt++) {
        const int row = m0 + wm + mt * 16 + g;
#pragma unroll
        for (int nt = 0; nt < 4; nt++) {
            const int col = n0 + wn + nt * 8 + tg;
            const float b0 = z ? 0.f : bias[col];
            const float b1 = z ? 0.f : bias[col + 1];
            float v0 = acc[mt][nt][0] + b0;
            float v1 = acc[mt][nt][1] + b1;
            float v2 = acc[mt][nt][2] + b0;
            float v3 = acc[mt][nt][3] + b1;
            if (relu) {
                v0 = fmaxf(v0, 0.f); v1 = fmaxf(v1, 0.f);
                v2 = fmaxf(v2, 0.f); v3 = fmaxf(v3, 0.f);
            }
            if (mode == 0) {
                C[(long)row * N + col]           = v0;
                C[(long)row * N + col + 1]       = v1;
                C[(long)(row + 8) * N + col]     = v2;
                C[(long)(row + 8) * N + col + 1] = v3;
            } else {
                *(uint32_t*)(Cf + (long)row * N + col)       = pack_h2(v0, v1);
                *(uint32_t*)(Cf + (long)(row + 8) * N + col) = pack_h2(v2, v3);
            }
        }
    }
}

// ---------------------------------------------------------------------------
// fp16 HMMA attention: single-pass QK, single-pass PV, 3-stage K/V pipeline.
// smem: Q 18432 | 3 x stage{K 9216, V 9216} = 73728 bytes
// ---------------------------------------------------------------------------
#define ATS 72
#define AQ    0
#define AKV0  18432
#define AKVST 18432
#define A_K   0
#define A_V   9216
#define ATTN_SMEM 73728

__global__ void __launch_bounds__(256, 2) attn_mma(
    const __half* __restrict__ QKVf, __half* __restrict__ Cf)
{
    extern __shared__ char smraw[];
    const uint32_t sb = smem_u32(smraw);

    const int tid = threadIdx.x;
    const int wid = tid >> 5, lid = tid & 31;
    const int bh = blockIdx.y;
    const int b = bh >> 4, h = bh & 15;
    const int q0 = blockIdx.x * 128;
    const long qbase = (long)(b * SEQ + q0) * QKVS + h * DHEAD;
    const long kbase = (long)(b * SEQ) * QKVS + DMODEL + h * DHEAD;
    const long vbase = kbase + DMODEL;

    for (int e = tid; e < 128 * 8; e += 256) {
        int row = e >> 3, cgp = (e & 7) * 8;
        const uint32_t so = (uint32_t)(row * 144 + cgp * 2);
        *(uint4*)(smraw + AQ + so) = *(const uint4*)(QKVf + qbase + (long)row * QKVS + cgp);
    }

    auto issueKV = [&](int kt) {
        const uint32_t base = sb + AKV0 + (kt % 3) * AKVST;
#pragma unroll
        for (int e0 = 0; e0 < 2; e0++) {
            const int e = tid + e0 * 256;
            const int row = e >> 3, cgp = (e & 7) * 8;
            const uint32_t so = (uint32_t)(row * 144 + cgp * 2);
            CP16(base + A_K + so, QKVf + kbase + (long)(kt * 64 + row) * QKVS + cgp);
            CP16(base + A_V + so, QKVf + vbase + (long)(kt * 64 + row) * QKVS + cgp);
        }
    };

    const int mrow = wid * 16;
    const int lrow = lid & 15;
    const int lcol = (lid >> 4) * 8;
    const uint32_t qB = sb + AQ;

    float acc[8][4];
#pragma unroll
    for (int nt = 0; nt < 8; nt++)
#pragma unroll
        for (int f = 0; f < 4; f++) acc[nt][f] = 0.f;
    float den0 = 0.f, den1 = 0.f;

    const int NKT = SEQ / 64;
    issueKV(0); CP_COMMIT();
    issueKV(1); CP_COMMIT();

    for (int kt = 0; kt < NKT; kt++) {
        if (kt + 1 < NKT) CP_WAIT1(); else CP_WAIT0();
        __syncthreads();
        if (kt + 2 < NKT) { issueKV(kt + 2); CP_COMMIT(); }

        const uint32_t kvb = sb + AKV0 + (kt % 3) * AKVST;
        const uint32_t kB = kvb + A_K, vB = kvb + A_V;

        // S = Q K^T (fp16 single pass)
        float S[8][4];
#pragma unroll
        for (int nt = 0; nt < 8; nt++)
#pragma unroll
            for (int f = 0; f < 4; f++) S[nt][f] = 0.f;

#pragma unroll
        for (int k16 = 0; k16 < 4; k16++) {
            uint32_t aF[4];
            ldmat_x4(aF, qB + ((mrow + lrow) * ATS + k16 * 16 + lcol) * 2);
#pragma unroll
            for (int np = 0; np < 4; np++) {
                uint32_t bF[4];
                ldmat_x4(bF, kB + ((np * 16 + lrow) * ATS + k16 * 16 + lcol) * 2);
                uint32_t f0[2] = { bF[0], bF[2] }, f1[2] = { bF[1], bF[3] };
                mma_f16(S[2 * np],     aF, f0);
                mma_f16(S[2 * np + 1], aF, f1);
            }
        }

        // p = exp(clip(S/8) - 10), pack fp16; den in fp32
        uint32_t P[4][4];
#pragma unroll
        for (int nt = 0; nt < 8; nt++) {
            float e0 = __expf(fminf(fmaxf(S[nt][0] * 0.125f, -10.f), 10.f) - 10.f);
            float e1 = __expf(fminf(fmaxf(S[nt][1] * 0.125f, -10.f), 10.f) - 10.f);
            float e2 = __expf(fminf(fmaxf(S[nt][2] * 0.125f, -10.f), 10.f) - 10.f);
            float e3 = __expf(fminf(fmaxf(S[nt][3] * 0.125f, -10.f), 10.f) - 10.f);
            den0 += e0 + e1;
            den1 += e2 + e3;
            const int j = nt >> 1;
            if ((nt & 1) == 0) { P[j][0] = pack_h2(e0, e1); P[j][1] = pack_h2(e2, e3); }
            else               { P[j][2] = pack_h2(e0, e1); P[j][3] = pack_h2(e2, e3); }
        }

        // acc += P @ V
#pragma unroll
        for (int j = 0; j < 4; j++) {
#pragma unroll
            for (int np = 0; np < 4; np++) {
                uint32_t vF[4];
                ldmat_x4t(vF, vB + ((j * 16 + lrow) * ATS + np * 16 + lcol) * 2);
                uint32_t f0[2] = { vF[0], vF[1] }, f1[2] = { vF[2], vF[3] };
                mma_f16(acc[2 * np],     P[j], f0);
                mma_f16(acc[2 * np + 1], P[j], f1);
            }
        }
    }

    den0 += __shfl_xor_sync(~0u, den0, 1);
    den0 += __shfl_xor_sync(~0u, den0, 2);
    den1 += __shfl_xor_sync(~0u, den1, 1);
    den1 += __shfl_xor_sync(~0u, den1, 2);
    const float i0 = 1.f / den0, i1 = 1.f / den1;

    const int g  = lid >> 2;
    const int tg = (lid & 3) * 2;
    const long row0 = (long)(b * SEQ + q0 + mrow + g) * DMODEL + h * DHEAD;
    const long row1 = row0 + 8 * DMODEL;
#pragma unroll
    for (int nt = 0; nt < 8; nt++) {
        const int col = nt * 8 + tg;
        *(uint32_t*)(Cf + row0 + col) = pack_h2(acc[nt][0] * i0, acc[nt][1] * i0);
        *(uint32_t*)(Cf + row1 + col) = pack_h2(acc[nt][2] * i1, acc[nt][3] * i1);
    }
}

// ---------------------------------------------------------------------------
// x fp32 -> fp16
// ---------------------------------------------------------------------------
__global__ void __launch_bounds__(256) cvt_kernel(
    const float* __restrict__ A, __half* __restrict__ o, long n4)
{
    long i = (long)blockIdx.x * blockDim.x + threadIdx.x;
    long stride = (long)gridDim.x * blockDim.x;
    for (; i < n4; i += stride) {
        float4 v = ((const float4*)A)[i];
        uint2 p = { pack_h2(v.x, v.y), pack_h2(v.z, v.w) };
        ((uint2*)o)[i] = p;
    }
}

// ---------------------------------------------------------------------------
// All 6 weight matrices: transpose + fp16 hi/lo split, one launch.
// ---------------------------------------------------------------------------
__global__ void __launch_bounds__(256) tsplit_all(
    const float* __restrict__ wq, const float* __restrict__ wk,
    const float* __restrict__ wv, const float* __restrict__ wo,
    const float* __restrict__ w1, const float* __restrict__ w2,
    __half* __restrict__ qkvh, __half* __restrict__ qkvl,
    __half* __restrict__ woh,  __half* __restrict__ wol,
    __half* __restrict__ w1h,  __half* __restrict__ w1l,
    __half* __restrict__ w2h,  __half* __restrict__ w2l)
{
    const int bid = blockIdx.x;
    const float* W;
    __half *hi, *lo;
    int K, N, bn, bk;
    if (bid < 3072) {
        const int seg = bid >> 10, t = bid & 1023;
        W = seg == 0 ? wq : (seg == 1 ? wk : wv);
        hi = qkvh + (long)seg * DMODEL * DMODEL;
        lo = qkvl + (long)seg * DMODEL * DMODEL;
        K = DMODEL; N = DMODEL; bn = (t & 31) * 32; bk = (t >> 5) * 32;
    } else if (bid < 4096) {
        const int t = bid - 3072;
        W = wo; hi = woh; lo = wol;
        K = DMODEL; N = DMODEL; bn = (t & 31) * 32; bk = (t >> 5) * 32;
    } else if (bid < 8192) {
        const int t = bid - 4096;
        W = w1; hi = w1h; lo = w1l;
        K = DMODEL; N = DFF; bn = (t & 127) * 32; bk = (t >> 7) * 32;
    } else {
        const int t = bid - 8192;
        W = w2; hi = w2h; lo = w2l;
        K = DFF; N = DMODEL; bn = (t & 31) * 32; bk = (t >> 5) * 32;
    }

    __shared__ float tbuf[32][33];
    const int x = threadIdx.x & 31, y = threadIdx.x >> 5;
#pragma unroll
    for (int r = 0; r < 32; r += 8)
        tbuf[y + r][x] = W[(long)(bk + y + r) * N + bn + x];
    __syncthreads();
#pragma unroll
    for (int r = 0; r < 32; r += 8) {
        float v = tbuf[x][y + r];
        __half hh = __float2half_rn(v);
        float rem = v - __half2float(hh);
        long o = (long)(bn + y + r) * K + bk + x;
        hi[o] = hh;
        lo[o] = __float2half_rn(rem);
    }
}

__global__ void __launch_bounds__(256) concat_bias_kernel(
    const float* __restrict__ bq, const float* __restrict__ bk,
    const float* __restrict__ bv, float* __restrict__ o)
{
    int i = blockIdx.x * 256 + threadIdx.x;
    if (i < DMODEL)           o[i] = bq[i];
    else if (i < 2 * DMODEL)  o[i] = bk[i - DMODEL];
    else if (i < 3 * DMODEL)  o[i] = bv[i - 2 * DMODEL];
}

// ---------------------------------------------------------------------------
// out = LayerNorm(A + B [+ B2]) * gamma + beta ; optional fp16 output
// ---------------------------------------------------------------------------
__global__ __launch_bounds__(256) void add_ln_kernel(
    const float* __restrict__ A, const float* __restrict__ B,
    const float* __restrict__ B2,
    const float* __restrict__ gamma, const float* __restrict__ beta,
    float* __restrict__ out, __half* __restrict__ ohf, int do_half)
{
    __shared__ float red[2];
    const int row = blockIdx.x;
    const int tid = threadIdx.x;

    float4 a = ((const float4*)(A + (long)row * DMODEL))[tid];
    float4 b = ((const float4*)(B + (long)row * DMODEL))[tid];
    float4 v = {a.x + b.x, a.y + b.y, a.z + b.z, a.w + b.w};
    if (B2) {
        float4 c = ((const float4*)(B2 + (long)row * DMODEL))[tid];
        v.x += c.x; v.y += c.y; v.z += c.z; v.w += c.w;
    }

    float s  = v.x + v.y + v.z + v.w;
    float sq = v.x * v.x + v.y * v.y + v.z * v.z + v.w * v.w;
#pragma unroll
    for (int o = 16; o; o >>= 1) {
        s  += __shfl_xor_sync(~0u, s,  o);
        sq += __shfl_xor_sync(~0u, sq, o);
    }
    const int w = tid >> 5, l = tid & 31;
    __shared__ float ws[8], wq2[8];
    if (l == 0) { ws[w] = s; wq2[w] = sq; }
    __syncthreads();
    if (tid < 32) {
        float s2 = (tid < 8) ? ws[tid] : 0.f;
        float q2 = (tid < 8) ? wq2[tid] : 0.f;
#pragma unroll
        for (int o = 4; o; o >>= 1) {
            s2 += __shfl_xor_sync(~0u, s2, o);
            q2 += __shfl_xor_sync(~0u, q2, o);
        }
        if (tid == 0) { red[0] = s2; red[1] = q2; }
    }
    __syncthreads();
    float mean = red[0] * (1.f / DMODEL);
    float var  = red[1] * (1.f / DMODEL) - mean * mean;
    float rs   = rsqrtf(var + 1e-8f);

    float4 g  = ((const float4*)gamma)[tid];
    float4 be = ((const float4*)beta)[tid];
    float4 o4;
    o4.x = (v.x - mean) * rs * g.x + be.x;
    o4.y = (v.y - mean) * rs * g.y + be.y;
    o4.z = (v.z - mean) * rs * g.z + be.z;
    o4.w = (v.w - mean) * rs * g.w + be.w;
    ((float4*)(out + (long)row * DMODEL))[tid] = o4;

    if (do_half) {
        uint2 hv = { pack_h2(o4.x, o4.y), pack_h2(o4.z, o4.w) };
        ((uint2*)(ohf + (long)row * DMODEL))[tid] = hv;
    }
}

// ---------------------------------------------------------------------------
extern "C" void kernel_launch(void* const* d_in, const int* in_sizes, int n_in,
                              void* d_out, int out_size)
{
    const float* x  = (const float*)d_in[0];
    const float* wq = (const float*)d_in[1];
    const float* bq = (const float*)d_in[2];
    const float* wk = (const float*)d_in[3];
    const float* bk = (const float*)d_in[4];
    const float* wv = (const float*)d_in[5];
    const float* bv = (const float*)d_in[6];
    const float* wo = (const float*)d_in[7];
    const float* bo = (const float*)d_in[8];
    const float* w1 = (const float*)d_in[9];
    const float* b1 = (const float*)d_in[10];
    const float* w2 = (const float*)d_in[11];
    const float* b2 = (const float*)d_in[12];
    const float* ga = (const float*)d_in[13];
    const float* be = (const float*)d_in[14];
    float* out = (float*)d_out;

    float *S1, *S2, *S3, *b3;
    __half *Xf, *QKVf, *Cf, *O1f, *H1f;
    __half *WQKVh, *WQKVl, *WOh, *WOl, *W1h, *W1l, *W2h, *W2l;
    cudaGetSymbolAddress((void**)&S1,    g_S1);
    cudaGetSymbolAddress((void**)&S2,    g_S2);
    cudaGetSymbolAddress((void**)&S3,    g_S3);
    cudaGetSymbolAddress((void**)&b3,    g_b3);
    cudaGetSymbolAddress((void**)&Xf,    g_Xf);
    cudaGetSymbolAddress((void**)&QKVf,  g_QKVf);
    cudaGetSymbolAddress((void**)&Cf,    g_Cf);
    cudaGetSymbolAddress((void**)&O1f,   g_O1f);
    cudaGetSymbolAddress((void**)&H1f,   g_H1f);
    cudaGetSymbolAddress((void**)&WQKVh, g_WQKVh);
    cudaGetSymbolAddress((void**)&WQKVl, g_WQKVl);
    cudaGetSymbolAddress((void**)&WOh,   g_WOh);
    cudaGetSymbolAddress((void**)&WOl,   g_WOl);
    cudaGetSymbolAddress((void**)&W1h,   g_W1h);
    cudaGetSymbolAddress((void**)&W1l,   g_W1l);
    cudaGetSymbolAddress((void**)&W2h,   g_W2h);
    cudaGetSymbolAddress((void**)&W2l,   g_W2l);

    cudaFuncSetAttribute(gemm_mma, cudaFuncAttributeMaxDynamicSharedMemorySize, GEMM_SMEM);
    cudaFuncSetAttribute(attn_mma, cudaFuncAttributeMaxDynamicSharedMemorySize, ATTN_SMEM);

    dim3 blk(256);
    dim3 gQKV(QKVS / 128, M_TOK / 128, 1);
    dim3 gProjZ(DMODEL / 128, M_TOK / 128, 2);
    dim3 gF1(DFF / 128, M_TOK / 128, 1);

    cvt_kernel<<<512, blk>>>(x, Xf, (long)M_TOK * DMODEL / 4);
    tsplit_all<<<12288, blk>>>(wq, wk, wv, wo, w1, w2,
                               WQKVh, WQKVl, WOh, WOl, W1h, W1l, W2h, W2l);
    concat_bias_kernel<<<(QKVS + 255) / 256, blk>>>(bq, bk, bv, b3);

    // fused QKV projection -> fp16
    gemm_mma<<<gQKV, blk, GEMM_SMEM>>>(Xf, WQKVh, WQKVl, b3, nullptr, nullptr,
                                       QKVf, QKVS, DMODEL, DMODEL, 0, 1);

    // attention -> fp16 ctx
    dim3 gAttn(SEQ / 128, 4 * NHEAD);
    attn_mma<<<gAttn, blk, ATTN_SMEM>>>(QKVf, Cf);

    // O projection, split-K=2 -> fp32 partials
    gemm_mma<<<gProjZ, blk, GEMM_SMEM>>>(Cf, WOh, WOl, bo, S1, S3,
                                         nullptr, DMODEL, DMODEL, DMODEL / 2, 0, 0);

    // out1 = LN(x + p0 + p1) -> fp32 + fp16
    add_ln_kernel<<<M_TOK, blk>>>(x, S1, S3, ga, be, S2, O1f, 1);

    // FFN1 -> relu -> fp16
    gemm_mma<<<gF1, blk, GEMM_SMEM>>>(O1f, W1h, W1l, b1, nullptr, nullptr,
                                      H1f, DFF, DMODEL, DMODEL, 1, 1);

    // FFN2, split-K=2 -> fp32 partials
    gemm_mma<<<gProjZ, blk, GEMM_SMEM>>>(H1f, W2h, W2l, b2, S1, S3,
                                         nullptr, DMODEL, DFF, DFF / 2, 0, 0);

    // out = LN(out1 + p0 + p1)
    add_ln_kernel<<<M_TOK, blk>>>(S2, S1, S3, ga, be, out, nullptr, 0);
}

// round 10
// speedup vs baseline: 6.8769x; 1.5004x over previous
#include <cuda_runtime.h>
#include <cuda_fp16.h>
#include <cstdint>

// ---------------------------------------------------------------------------
// EncoderLayer R9: pure-fp16 single-pass HMMA GEMMs (4-stage cp.async) +
// pure-fp16 attention. fp32 accumulate + fp32 residual/LN throughout.
// ---------------------------------------------------------------------------

#define M_TOK   8192
#define DMODEL  1024
#define DFF     4096
#define NHEAD   16
#define DHEAD   64
#define SEQ     2048
#define QKVS    3072

// fp32 scratch
__device__ float g_S1 [M_TOK * DMODEL];
__device__ float g_S2 [M_TOK * DMODEL];
__device__ float g_S3 [M_TOK * DMODEL];
__device__ float g_b3 [QKVS];
// fp16 activations
__device__ __half g_Xf  [M_TOK * DMODEL];
__device__ __half g_QKVf[M_TOK * QKVS];
__device__ __half g_Cf  [M_TOK * DMODEL];
__device__ __half g_O1f [M_TOK * DMODEL];
__device__ __half g_H1f [M_TOK * DFF];
// fp16 transposed weights [N,K]
__device__ __half g_WQKV[QKVS * DMODEL];
__device__ __half g_WO  [DMODEL * DMODEL];
__device__ __half g_W1  [DFF * DMODEL];
__device__ __half g_W2  [DMODEL * DFF];

__device__ __forceinline__ uint32_t smem_u32(const void* p) {
    uint32_t a;
    asm("{ .reg .u64 t; cvta.to.shared.u64 t, %1; cvt.u32.u64 %0, t; }" : "=r"(a) : "l"(p));
    return a;
}
__device__ __forceinline__ void ldmat_x4(uint32_t* r, uint32_t addr) {
    asm volatile("ldmatrix.sync.aligned.m8n8.x4.shared.b16 {%0,%1,%2,%3}, [%4];"
                 : "=r"(r[0]), "=r"(r[1]), "=r"(r[2]), "=r"(r[3]) : "r"(addr));
}
__device__ __forceinline__ void ldmat_x4t(uint32_t* r, uint32_t addr) {
    asm volatile("ldmatrix.sync.aligned.m8n8.x4.trans.shared.b16 {%0,%1,%2,%3}, [%4];"
                 : "=r"(r[0]), "=r"(r[1]), "=r"(r[2]), "=r"(r[3]) : "r"(addr));
}
__device__ __forceinline__ void mma_f16(float* d, const uint32_t* a, const uint32_t* b) {
    asm volatile("mma.sync.aligned.m16n8k16.row.col.f32.f16.f16.f32 "
                 "{%0,%1,%2,%3}, {%4,%5,%6,%7}, {%8,%9}, {%0,%1,%2,%3};"
                 : "+f"(d[0]), "+f"(d[1]), "+f"(d[2]), "+f"(d[3])
                 : "r"(a[0]), "r"(a[1]), "r"(a[2]), "r"(a[3]), "r"(b[0]), "r"(b[1]));
}
__device__ __forceinline__ uint32_t pack_h2(float lo, float hi) {
    __half2 t = __floats2half2_rn(lo, hi);
    return *reinterpret_cast<uint32_t*>(&t);
}
#define CP16(dst, src) asm volatile("cp.async.cg.shared.global [%0], [%1], 16;" :: "r"(dst), "l"(src))
#define CP_COMMIT()    asm volatile("cp.async.commit_group;" ::: "memory")
#define CP_WAIT2()     asm volatile("cp.async.wait_group 2;" ::: "memory")
#define CP_WAIT1()     asm volatile("cp.async.wait_group 1;" ::: "memory")
#define CP_WAIT0()     asm volatile("cp.async.wait_group 0;" ::: "memory")

// 64B-row XOR swizzle
#define SWZ(row, bc) ((uint32_t)((row) * 64 + ((bc) ^ (((row) & 6) << 3))))

// ---------------------------------------------------------------------------
// fp16 single-pass HMMA GEMM: C = A @ W + bias (W as Wt[N,K] fp16).
// BM=BN=128, BK=32. 256 threads = 2x4 warps, 64x32/warp. 4-stage pipeline.
// stage: A 8K | B 8K = 16384 B; 4 stages = 65536 B.
// ---------------------------------------------------------------------------
#define GST 16384
#define OF_A 0
#define OF_B 8192
#define GEMM_SMEM (4 * GST)

__global__ void __launch_bounds__(256, 2) gemm_mma(
    const __half* __restrict__ A, const __half* __restrict__ B,
    const float* __restrict__ bias, float* __restrict__ C0, float* __restrict__ C1,
    __half* __restrict__ Cf,
    int N, int K, int Ksl, int relu, int mode)
{
    extern __shared__ char smraw[];
    const uint32_t sb = smem_u32(smraw);

    const int tid = threadIdx.x;
    const int wid = tid >> 5, lid = tid & 31;
    const int m0 = blockIdx.y * 128, n0 = blockIdx.x * 128;
    const int z  = blockIdx.z;
    const long kzb = (long)z * Ksl;
    float* __restrict__ C = z ? C1 : C0;
    const int wm = (wid >> 2) * 64;
    const int wn = (wid & 3) * 32;

    const int r  = tid >> 2;
    const int cg = (tid & 3) * 8;
    const int cb = (tid & 3) * 16;
    const uint32_t sw0 = SWZ(r, cb);
    const uint32_t sw1 = SWZ(r + 64, cb);

    float acc[4][4][4];
#pragma unroll
    for (int mt = 0; mt < 4; mt++)
#pragma unroll
        for (int nt = 0; nt < 4; nt++)
#pragma unroll
            for (int f = 0; f < 4; f++) acc[mt][nt][f] = 0.f;

    const int lrow = lid & 15;
    const int lcb  = (lid >> 4) * 16;
    const int NC = Ksl >> 5;

    auto issue = [&](int i) {
        const uint32_t base = sb + (i & 3) * GST;
        const long k0 = kzb + (long)(i << 5);
        const long ra = (long)(m0 + r) * K + k0 + cg;
        const long rb = (long)(n0 + r) * K + k0 + cg;
        CP16(base + OF_A + sw0, A + ra);
        CP16(base + OF_A + sw1, A + ra + 64 * (long)K);
        CP16(base + OF_B + sw0, B + rb);
        CP16(base + OF_B + sw1, B + rb + 64 * (long)K);
    };

    issue(0); CP_COMMIT();
    if (NC > 1) { issue(1); CP_COMMIT(); }
    if (NC > 2) { issue(2); CP_COMMIT(); }

    for (int i = 0; i < NC; i++) {
        const int ahead = NC - 1 - i;           // chunks still pending after i
        if (ahead >= 3)      CP_WAIT2();
        else if (ahead == 2) CP_WAIT2();
        else if (ahead == 1) CP_WAIT1();
        else                 CP_WAIT0();
        __syncthreads();
        if (i + 3 < NC) { issue(i + 3); CP_COMMIT(); }

        const uint32_t base = sb + (i & 3) * GST;
        const uint32_t aB = base + OF_A, bB = base + OF_B;

#pragma unroll
        for (int k16 = 0; k16 < 2; k16++) {
            const int bc = k16 * 32 + lcb;
            uint32_t af[4][4];
#pragma unroll
            for (int mt = 0; mt < 4; mt++)
                ldmat_x4(af[mt], aB + SWZ(wm + mt * 16 + lrow, bc));
            uint32_t bf[2][4];
#pragma unroll
            for (int np = 0; np < 2; np++)
                ldmat_x4(bf[np], bB + SWZ(wn + np * 16 + lrow, bc));
#pragma unroll
            for (int mt = 0; mt < 4; mt++) {
#pragma unroll
                for (int nt = 0; nt < 4; nt++) {
                    uint32_t b2[2] = { bf[nt >> 1][nt & 1], bf[nt >> 1][(nt & 1) + 2] };
                    mma_f16(acc[mt][nt], af[mt], b2);
                }
            }
        }
    }

    const int g  = lid >> 2;
    const int tg = (lid & 3) * 2;
#pragma unroll
    for (int mt = 0; mt < 4; mt++) {
        const int row = m0 + wm + mt * 16 + g;
#pragma unroll
        for (int nt = 0; nt < 4; nt++) {
            const int col = n0 + wn + nt * 8 + tg;
            const float b0 = z ? 0.f : bias[col];
            const float b1 = z ? 0.f : bias[col + 1];
            float v0 = acc[mt][nt][0] + b0;
            float v1 = acc[mt][nt][1] + b1;
            float v2 = acc[mt][nt][2] + b0;
            float v3 = acc[mt][nt][3] + b1;
            if (relu) {
                v0 = fmaxf(v0, 0.f); v1 = fmaxf(v1, 0.f);
                v2 = fmaxf(v2, 0.f); v3 = fmaxf(v3, 0.f);
            }
            if (mode == 0) {
                C[(long)row * N + col]           = v0;
                C[(long)row * N + col + 1]       = v1;
                C[(long)(row + 8) * N + col]     = v2;
                C[(long)(row + 8) * N + col + 1] = v3;
            } else {
                *(uint32_t*)(Cf + (long)row * N + col)       = pack_h2(v0, v1);
                *(uint32_t*)(Cf + (long)(row + 8) * N + col) = pack_h2(v2, v3);
            }
        }
    }
}

// ---------------------------------------------------------------------------
// fp16 HMMA attention: single-pass QK/PV, 3-stage K/V pipeline.
// smem: Q 18432 | 3 x stage{K 9216, V 9216} = 73728 bytes
// ---------------------------------------------------------------------------
#define ATS 72
#define AQ    0
#define AKV0  18432
#define AKVST 18432
#define A_K   0
#define A_V   9216
#define ATTN_SMEM 73728

__global__ void __launch_bounds__(256, 2) attn_mma(
    const __half* __restrict__ QKVf, __half* __restrict__ Cf)
{
    extern __shared__ char smraw[];
    const uint32_t sb = smem_u32(smraw);

    const int tid = threadIdx.x;
    const int wid = tid >> 5, lid = tid & 31;
    const int bh = blockIdx.y;
    const int b = bh >> 4, h = bh & 15;
    const int q0 = blockIdx.x * 128;
    const long qbase = (long)(b * SEQ + q0) * QKVS + h * DHEAD;
    const long kbase = (long)(b * SEQ) * QKVS + DMODEL + h * DHEAD;
    const long vbase = kbase + DMODEL;

    for (int e = tid; e < 128 * 8; e += 256) {
        int row = e >> 3, cgp = (e & 7) * 8;
        const uint32_t so = (uint32_t)(row * 144 + cgp * 2);
        *(uint4*)(smraw + AQ + so) = *(const uint4*)(QKVf + qbase + (long)row * QKVS + cgp);
    }

    auto issueKV = [&](int kt) {
        const uint32_t base = sb + AKV0 + (kt % 3) * AKVST;
#pragma unroll
        for (int e0 = 0; e0 < 2; e0++) {
            const int e = tid + e0 * 256;
            const int row = e >> 3, cgp = (e & 7) * 8;
            const uint32_t so = (uint32_t)(row * 144 + cgp * 2);
            CP16(base + A_K + so, QKVf + kbase + (long)(kt * 64 + row) * QKVS + cgp);
            CP16(base + A_V + so, QKVf + vbase + (long)(kt * 64 + row) * QKVS + cgp);
        }
    };

    const int mrow = wid * 16;
    const int lrow = lid & 15;
    const int lcol = (lid >> 4) * 8;
    const uint32_t qB = sb + AQ;

    float acc[8][4];
#pragma unroll
    for (int nt = 0; nt < 8; nt++)
#pragma unroll
        for (int f = 0; f < 4; f++) acc[nt][f] = 0.f;
    float den0 = 0.f, den1 = 0.f;

    const int NKT = SEQ / 64;
    issueKV(0); CP_COMMIT();
    issueKV(1); CP_COMMIT();

    for (int kt = 0; kt < NKT; kt++) {
        if (kt + 1 < NKT) CP_WAIT1(); else CP_WAIT0();
        __syncthreads();
        if (kt + 2 < NKT) { issueKV(kt + 2); CP_COMMIT(); }

        const uint32_t kvb = sb + AKV0 + (kt % 3) * AKVST;
        const uint32_t kB = kvb + A_K, vB = kvb + A_V;

        float S[8][4];
#pragma unroll
        for (int nt = 0; nt < 8; nt++)
#pragma unroll
            for (int f = 0; f < 4; f++) S[nt][f] = 0.f;

#pragma unroll
        for (int k16 = 0; k16 < 4; k16++) {
            uint32_t aF[4];
            ldmat_x4(aF, qB + ((mrow + lrow) * ATS + k16 * 16 + lcol) * 2);
#pragma unroll
            for (int np = 0; np < 4; np++) {
                uint32_t bF[4];
                ldmat_x4(bF, kB + ((np * 16 + lrow) * ATS + k16 * 16 + lcol) * 2);
                uint32_t f0[2] = { bF[0], bF[2] }, f1[2] = { bF[1], bF[3] };
                mma_f16(S[2 * np],     aF, f0);
                mma_f16(S[2 * np + 1], aF, f1);
            }
        }

        uint32_t P[4][4];
#pragma unroll
        for (int nt = 0; nt < 8; nt++) {
            float e0 = __expf(fminf(fmaxf(S[nt][0] * 0.125f, -10.f), 10.f) - 10.f);
            float e1 = __expf(fminf(fmaxf(S[nt][1] * 0.125f, -10.f), 10.f) - 10.f);
            float e2 = __expf(fminf(fmaxf(S[nt][2] * 0.125f, -10.f), 10.f) - 10.f);
            float e3 = __expf(fminf(fmaxf(S[nt][3] * 0.125f, -10.f), 10.f) - 10.f);
            den0 += e0 + e1;
            den1 += e2 + e3;
            const int j = nt >> 1;
            if ((nt & 1) == 0) { P[j][0] = pack_h2(e0, e1); P[j][1] = pack_h2(e2, e3); }
            else               { P[j][2] = pack_h2(e0, e1); P[j][3] = pack_h2(e2, e3); }
        }

#pragma unroll
        for (int j = 0; j < 4; j++) {
#pragma unroll
            for (int np = 0; np < 4; np++) {
                uint32_t vF[4];
                ldmat_x4t(vF, vB + ((j * 16 + lrow) * ATS + np * 16 + lcol) * 2);
                uint32_t f0[2] = { vF[0], vF[1] }, f1[2] = { vF[2], vF[3] };
                mma_f16(acc[2 * np],     P[j], f0);
                mma_f16(acc[2 * np + 1], P[j], f1);
            }
        }
    }

    den0 += __shfl_xor_sync(~0u, den0, 1);
    den0 += __shfl_xor_sync(~0u, den0, 2);
    den1 += __shfl_xor_sync(~0u, den1, 1);
    den1 += __shfl_xor_sync(~0u, den1, 2);
    const float i0 = 1.f / den0, i1 = 1.f / den1;

    const int g  = lid >> 2;
    const int tg = (lid & 3) * 2;
    const long row0 = (long)(b * SEQ + q0 + mrow + g) * DMODEL + h * DHEAD;
    const long row1 = row0 + 8 * DMODEL;
#pragma unroll
    for (int nt = 0; nt < 8; nt++) {
        const int col = nt * 8 + tg;
        *(uint32_t*)(Cf + row0 + col) = pack_h2(acc[nt][0] * i0, acc[nt][1] * i0);
        *(uint32_t*)(Cf + row1 + col) = pack_h2(acc[nt][2] * i1, acc[nt][3] * i1);
    }
}

// ---------------------------------------------------------------------------
__global__ void __launch_bounds__(256) cvt_kernel(
    const float* __restrict__ A, __half* __restrict__ o, long n4)
{
    long i = (long)blockIdx.x * blockDim.x + threadIdx.x;
    long stride = (long)gridDim.x * blockDim.x;
    for (; i < n4; i += stride) {
        float4 v = ((const float4*)A)[i];
        uint2 p = { pack_h2(v.x, v.y), pack_h2(v.z, v.w) };
        ((uint2*)o)[i] = p;
    }
}

// ---------------------------------------------------------------------------
// All 6 weight matrices: transpose + fp16 convert, one launch.
// ---------------------------------------------------------------------------
__global__ void __launch_bounds__(256) tsplit_all(
    const float* __restrict__ wq, const float* __restrict__ wk,
    const float* __restrict__ wv, const float* __restrict__ wo,
    const float* __restrict__ w1, const float* __restrict__ w2,
    __half* __restrict__ qkvt, __half* __restrict__ wot,
    __half* __restrict__ w1t,  __half* __restrict__ w2t)
{
    const int bid = blockIdx.x;
    const float* W;
    __half* dst;
    int K, N, bn, bk;
    if (bid < 3072) {
        const int seg = bid >> 10, t = bid & 1023;
        W = seg == 0 ? wq : (seg == 1 ? wk : wv);
        dst = qkvt + (long)seg * DMODEL * DMODEL;
        K = DMODEL; N = DMODEL; bn = (t & 31) * 32; bk = (t >> 5) * 32;
    } else if (bid < 4096) {
        const int t = bid - 3072;
        W = wo; dst = wot;
        K = DMODEL; N = DMODEL; bn = (t & 31) * 32; bk = (t >> 5) * 32;
    } else if (bid < 8192) {
        const int t = bid - 4096;
        W = w1; dst = w1t;
        K = DMODEL; N = DFF; bn = (t & 127) * 32; bk = (t >> 7) * 32;
    } else {
        const int t = bid - 8192;
        W = w2; dst = w2t;
        K = DFF; N = DMODEL; bn = (t & 31) * 32; bk = (t >> 5) * 32;
    }

    __shared__ float tbuf[32][33];
    const int x = threadIdx.x & 31, y = threadIdx.x >> 5;
#pragma unroll
    for (int r = 0; r < 32; r += 8)
        tbuf[y + r][x] = W[(long)(bk + y + r) * N + bn + x];
    __syncthreads();
#pragma unroll
    for (int r = 0; r < 32; r += 8)
        dst[(long)(bn + y + r) * K + bk + x] = __float2half_rn(tbuf[x][y + r]);
}

__global__ void __launch_bounds__(256) concat_bias_kernel(
    const float* __restrict__ bq, const float* __restrict__ bk,
    const float* __restrict__ bv, float* __restrict__ o)
{
    int i = blockIdx.x * 256 + threadIdx.x;
    if (i < DMODEL)           o[i] = bq[i];
    else if (i < 2 * DMODEL)  o[i] = bk[i - DMODEL];
    else if (i < 3 * DMODEL)  o[i] = bv[i - 2 * DMODEL];
}

// ---------------------------------------------------------------------------
__global__ __launch_bounds__(256) void add_ln_kernel(
    const float* __restrict__ A, const float* __restrict__ B,
    const float* __restrict__ B2,
    const float* __restrict__ gamma, const float* __restrict__ beta,
    float* __restrict__ out, __half* __restrict__ ohf, int do_half)
{
    __shared__ float red[2];
    const int row = blockIdx.x;
    const int tid = threadIdx.x;

    float4 a = ((const float4*)(A + (long)row * DMODEL))[tid];
    float4 b = ((const float4*)(B + (long)row * DMODEL))[tid];
    float4 v = {a.x + b.x, a.y + b.y, a.z + b.z, a.w + b.w};
    if (B2) {
        float4 c = ((const float4*)(B2 + (long)row * DMODEL))[tid];
        v.x += c.x; v.y += c.y; v.z += c.z; v.w += c.w;
    }

    float s  = v.x + v.y + v.z + v.w;
    float sq = v.x * v.x + v.y * v.y + v.z * v.z + v.w * v.w;
#pragma unroll
    for (int o = 16; o; o >>= 1) {
        s  += __shfl_xor_sync(~0u, s,  o);
        sq += __shfl_xor_sync(~0u, sq, o);
    }
    const int w = tid >> 5, l = tid & 31;
    __shared__ float ws[8], wq2[8];
    if (l == 0) { ws[w] = s; wq2[w] = sq; }
    __syncthreads();
    if (tid < 32) {
        float s2 = (tid < 8) ? ws[tid] : 0.f;
        float q2 = (tid < 8) ? wq2[tid] : 0.f;
#pragma unroll
        for (int o = 4; o; o >>= 1) {
            s2 += __shfl_xor_sync(~0u, s2, o);
            q2 += __shfl_xor_sync(~0u, q2, o);
        }
        if (tid == 0) { red[0] = s2; red[1] = q2; }
    }
    __syncthreads();
    float mean = red[0] * (1.f / DMODEL);
    float var  = red[1] * (1.f / DMODEL) - mean * mean;
    float rs   = rsqrtf(var + 1e-8f);

    float4 g  = ((const float4*)gamma)[tid];
    float4 be = ((const float4*)beta)[tid];
    float4 o4;
    o4.x = (v.x - mean) * rs * g.x + be.x;
    o4.y = (v.y - mean) * rs * g.y + be.y;
    o4.z = (v.z - mean) * rs * g.z + be.z;
    o4.w = (v.w - mean) * rs * g.w + be.w;
    ((float4*)(out + (long)row * DMODEL))[tid] = o4;

    if (do_half) {
        uint2 hv = { pack_h2(o4.x, o4.y), pack_h2(o4.z, o4.w) };
        ((uint2*)(ohf + (long)row * DMODEL))[tid] = hv;
    }
}

// ---------------------------------------------------------------------------
extern "C" void kernel_launch(void* const* d_in, const int* in_sizes, int n_in,
                              void* d_out, int out_size)
{
    const float* x  = (const float*)d_in[0];
    const float* wq = (const float*)d_in[1];
    const float* bq = (const float*)d_in[2];
    const float* wk = (const float*)d_in[3];
    const float* bk = (const float*)d_in[4];
    const float* wv = (const float*)d_in[5];
    const float* bv = (const float*)d_in[6];
    const float* wo = (const float*)d_in[7];
    const float* bo = (const float*)d_in[8];
    const float* w1 = (const float*)d_in[9];
    const float* b1 = (const float*)d_in[10];
    const float* w2 = (const float*)d_in[11];
    const float* b2 = (const float*)d_in[12];
    const float* ga = (const float*)d_in[13];
    const float* be = (const float*)d_in[14];
    float* out = (float*)d_out;

    float *S1, *S2, *S3, *b3;
    __half *Xf, *QKVf, *Cf, *O1f, *H1f, *WQKV, *WO, *W1, *W2;
    cudaGetSymbolAddress((void**)&S1,   g_S1);
    cudaGetSymbolAddress((void**)&S2,   g_S2);
    cudaGetSymbolAddress((void**)&S3,   g_S3);
    cudaGetSymbolAddress((void**)&b3,   g_b3);
    cudaGetSymbolAddress((void**)&Xf,   g_Xf);
    cudaGetSymbolAddress((void**)&QKVf, g_QKVf);
    cudaGetSymbolAddress((void**)&Cf,   g_Cf);
    cudaGetSymbolAddress((void**)&O1f,  g_O1f);
    cudaGetSymbolAddress((void**)&H1f,  g_H1f);
    cudaGetSymbolAddress((void**)&WQKV, g_WQKV);
    cudaGetSymbolAddress((void**)&WO,   g_WO);
    cudaGetSymbolAddress((void**)&W1,   g_W1);
    cudaGetSymbolAddress((void**)&W2,   g_W2);

    cudaFuncSetAttribute(gemm_mma, cudaFuncAttributeMaxDynamicSharedMemorySize, GEMM_SMEM);
    cudaFuncSetAttribute(attn_mma, cudaFuncAttributeMaxDynamicSharedMemorySize, ATTN_SMEM);

    dim3 blk(256);
    dim3 gQKV(QKVS / 128, M_TOK / 128, 1);
    dim3 gProjZ(DMODEL / 128, M_TOK / 128, 2);
    dim3 gF1(DFF / 128, M_TOK / 128, 1);

    cvt_kernel<<<512, blk>>>(x, Xf, (long)M_TOK * DMODEL / 4);
    tsplit_all<<<12288, blk>>>(wq, wk, wv, wo, w1, w2, WQKV, WO, W1, W2);
    concat_bias_kernel<<<(QKVS + 255) / 256, blk>>>(bq, bk, bv, b3);

    // fused QKV projection -> fp16
    gemm_mma<<<gQKV, blk, GEMM_SMEM>>>(Xf, WQKV, b3, nullptr, nullptr,
                                       QKVf, QKVS, DMODEL, DMODEL, 0, 1);

    // attention -> fp16 ctx
    dim3 gAttn(SEQ / 128, 4 * NHEAD);
    attn_mma<<<gAttn, blk, ATTN_SMEM>>>(QKVf, Cf);

    // O projection, split-K=2 -> fp32 partials
    gemm_mma<<<gProjZ, blk, GEMM_SMEM>>>(Cf, WO, bo, S1, S3,
                                         nullptr, DMODEL, DMODEL, DMODEL / 2, 0, 0);

    // out1 = LN(x + p0 + p1) -> fp32 + fp16
    add_ln_kernel<<<M_TOK, blk>>>(x, S1, S3, ga, be, S2, O1f, 1);

    // FFN1 -> relu -> fp16
    gemm_mma<<<gF1, blk, GEMM_SMEM>>>(O1f, W1, b1, nullptr, nullptr,
                                      H1f, DFF, DMODEL, DMODEL, 1, 1);

    // FFN2, split-K=2 -> fp32 partials
    gemm_mma<<<gProjZ, blk, GEMM_SMEM>>>(H1f, W2, b2, S1, S3,
                                         nullptr, DMODEL, DFF, DFF / 2, 0, 0);

    // out = LN(out1 + p0 + p1)
    add_ln_kernel<<<M_TOK, blk>>>(S2, S1, S3, ga, be, out, nullptr, 0);
}